// round 8
// baseline (speedup 1.0000x reference)
#include <cuda_runtime.h>
#include <math.h>

#define S_   1000
#define B_   64
#define D_   440
#define H_   512
#define O_   1000
#define SB_  64000
#define H3_  1536

typedef unsigned long long ull;

// ---------------- f32x2 packed helpers ----------------
__device__ __forceinline__ ull pk2(float x, float y) {
    ull r; asm("mov.b64 %0, {%1,%2};" : "=l"(r) : "f"(x), "f"(y)); return r;
}
__device__ __forceinline__ void upk2(ull v, float& x, float& y) {
    asm("mov.b64 {%0,%1}, %2;" : "=f"(x), "=f"(y) : "l"(v));
}
__device__ __forceinline__ ull ffma2(ull a, ull b, ull c) {
    ull d; asm("fma.rn.f32x2 %0, %1, %2, %3;" : "=l"(d) : "l"(a), "l"(b), "l"(c)); return d;
}

// ---------------- scratch ----------------
__device__ __align__(16) float g_Y[(size_t)SB_ * H3_];
__device__ __align__(16) float g_YT[(size_t)S_ * H3_ * B_];  // [t][col][b], BN-folded
__device__ __align__(16) float g_Hst[(size_t)SB_ * H_];
__device__ __align__(16) float g_hT[2][H_ * B_];             // [buf][k*64 + b]
__device__ __align__(16) float g_rhT[H_ * B_];
__device__ __align__(16) float g_zT[H_ * B_];
__device__ float g_p1s[64 * H3_], g_p1q[64 * H3_];           // [col*64 + chunk]
__device__ float g_p2s[64 * O_], g_p2q[64 * O_];             // [col*64 + chunk]
__device__ float g_A2[O_], g_C2[O_];
__device__ unsigned g_flags[128];                             // flag-array barrier

// ---------------- fp32 SGEMM (generic): C[M,N] = A[M,K] * Bw[N,K]^T ----------------
#define GBM 128
#define GBN 64
#define GBK 8
__global__ __launch_bounds__(256) void sgemm_kernel(
    const float* __restrict__ A, const float* __restrict__ Bw, float* __restrict__ C,
    int M, int N, int K, int ldc) {
    __shared__ float As[2][GBK][GBM + 4];
    __shared__ float Bs[2][GBK][GBN + 4];
    const int bm = blockIdx.y * GBM;
    const int bn = blockIdx.x * GBN;
    const int t  = threadIdx.x;
    const int tx = t & 15;
    const int ty = t >> 4;
    const int lam = t >> 1, lak = (t & 1) * 4;
    const int lbn = (t & 127) >> 1, lbk = (t & 1) * 4;
    const bool bload = t < 128;

    ull acc2[4][4];
#pragma unroll
    for (int p = 0; p < 4; p++)
#pragma unroll
        for (int j = 0; j < 4; j++) acc2[p][j] = 0ull;

    const int nt = K / GBK;
    float4 va, vb;
    va = *(const float4*)(A + (size_t)(bm + lam) * K + lak);
    vb = make_float4(0.f, 0.f, 0.f, 0.f);
    if (bload && (bn + lbn) < N) vb = *(const float4*)(Bw + (size_t)(bn + lbn) * K + lbk);
    As[0][lak + 0][lam] = va.x; As[0][lak + 1][lam] = va.y;
    As[0][lak + 2][lam] = va.z; As[0][lak + 3][lam] = va.w;
    if (bload) {
        Bs[0][lbk + 0][lbn] = vb.x; Bs[0][lbk + 1][lbn] = vb.y;
        Bs[0][lbk + 2][lbn] = vb.z; Bs[0][lbk + 3][lbn] = vb.w;
    }
    __syncthreads();

    for (int kt = 0; kt < nt; kt++) {
        const int cur = kt & 1;
        const bool has = (kt + 1) < nt;
        if (has) {
            const int k0 = (kt + 1) * GBK;
            va = *(const float4*)(A + (size_t)(bm + lam) * K + k0 + lak);
            vb = make_float4(0.f, 0.f, 0.f, 0.f);
            if (bload && (bn + lbn) < N)
                vb = *(const float4*)(Bw + (size_t)(bn + lbn) * K + k0 + lbk);
        }
#pragma unroll
        for (int k = 0; k < GBK; k++) {
            ull a2[4], bb[4];
#pragma unroll
            for (int p = 0; p < 4; p++)
                a2[p] = *(const ull*)&As[cur][k][ty * 8 + 2 * p];
#pragma unroll
            for (int j = 0; j < 4; j++) {
                const float bs = Bs[cur][k][tx * 4 + j];
                bb[j] = pk2(bs, bs);
            }
#pragma unroll
            for (int p = 0; p < 4; p++)
#pragma unroll
                for (int j = 0; j < 4; j++)
                    acc2[p][j] = ffma2(a2[p], bb[j], acc2[p][j]);
        }
        if (has) {
            const int nb = cur ^ 1;
            As[nb][lak + 0][lam] = va.x; As[nb][lak + 1][lam] = va.y;
            As[nb][lak + 2][lam] = va.z; As[nb][lak + 3][lam] = va.w;
            if (bload) {
                Bs[nb][lbk + 0][lbn] = vb.x; Bs[nb][lbk + 1][lbn] = vb.y;
                Bs[nb][lbk + 2][lbn] = vb.z; Bs[nb][lbk + 3][lbn] = vb.w;
            }
        }
        __syncthreads();
    }

#pragma unroll
    for (int p = 0; p < 4; p++) {
        const size_t m0 = (size_t)(bm + ty * 8 + 2 * p);
#pragma unroll
        for (int j = 0; j < 4; j++) {
            const int n = bn + tx * 4 + j;
            if (n < N) {
                float lo, hi;
                upk2(acc2[p][j], lo, hi);
                C[m0 * ldc + n] = lo;
                C[(m0 + 1) * ldc + n] = hi;
            }
        }
    }
}

// ---------------- gate SGEMM: B rows come from Wh/Wz/Wr directly (N=1536, K=440) ----------------
__global__ __launch_bounds__(256) void sgemm_gate(
    const float* __restrict__ A, const float* __restrict__ Wh,
    const float* __restrict__ Wz, const float* __restrict__ Wr,
    float* __restrict__ C) {
    const int M = SB_, N = H3_, K = D_, ldc = H3_;
    __shared__ float As[2][GBK][GBM + 4];
    __shared__ float Bs[2][GBK][GBN + 4];
    const int bm = blockIdx.y * GBM;
    const int bn = blockIdx.x * GBN;
    const int t  = threadIdx.x;
    const int tx = t & 15;
    const int ty = t >> 4;
    const int lam = t >> 1, lak = (t & 1) * 4;
    const int lbn = (t & 127) >> 1, lbk = (t & 1) * 4;
    const bool bload = t < 128;

    // resolve this thread's B row pointer once
    const float* brow = 0;
    if (bload) {
        const int r = bn + lbn;
        brow = (r < 512) ? (Wh + (size_t)r * K)
             : (r < 1024) ? (Wz + (size_t)(r - 512) * K)
                          : (Wr + (size_t)(r - 1024) * K);
    }

    ull acc2[4][4];
#pragma unroll
    for (int p = 0; p < 4; p++)
#pragma unroll
        for (int j = 0; j < 4; j++) acc2[p][j] = 0ull;

    const int nt = K / GBK;
    float4 va, vb;
    va = *(const float4*)(A + (size_t)(bm + lam) * K + lak);
    vb = make_float4(0.f, 0.f, 0.f, 0.f);
    if (bload) vb = *(const float4*)(brow + lbk);
    As[0][lak + 0][lam] = va.x; As[0][lak + 1][lam] = va.y;
    As[0][lak + 2][lam] = va.z; As[0][lak + 3][lam] = va.w;
    if (bload) {
        Bs[0][lbk + 0][lbn] = vb.x; Bs[0][lbk + 1][lbn] = vb.y;
        Bs[0][lbk + 2][lbn] = vb.z; Bs[0][lbk + 3][lbn] = vb.w;
    }
    __syncthreads();

    for (int kt = 0; kt < nt; kt++) {
        const int cur = kt & 1;
        const bool has = (kt + 1) < nt;
        if (has) {
            const int k0 = (kt + 1) * GBK;
            va = *(const float4*)(A + (size_t)(bm + lam) * K + k0 + lak);
            if (bload) vb = *(const float4*)(brow + k0 + lbk);
        }
#pragma unroll
        for (int k = 0; k < GBK; k++) {
            ull a2[4], bb[4];
#pragma unroll
            for (int p = 0; p < 4; p++)
                a2[p] = *(const ull*)&As[cur][k][ty * 8 + 2 * p];
#pragma unroll
            for (int j = 0; j < 4; j++) {
                const float bs = Bs[cur][k][tx * 4 + j];
                bb[j] = pk2(bs, bs);
            }
#pragma unroll
            for (int p = 0; p < 4; p++)
#pragma unroll
                for (int j = 0; j < 4; j++)
                    acc2[p][j] = ffma2(a2[p], bb[j], acc2[p][j]);
        }
        if (has) {
            const int nb = cur ^ 1;
            As[nb][lak + 0][lam] = va.x; As[nb][lak + 1][lam] = va.y;
            As[nb][lak + 2][lam] = va.z; As[nb][lak + 3][lam] = va.w;
            if (bload) {
                Bs[nb][lbk + 0][lbn] = vb.x; Bs[nb][lbk + 1][lbn] = vb.y;
                Bs[nb][lbk + 2][lbn] = vb.z; Bs[nb][lbk + 3][lbn] = vb.w;
            }
        }
        __syncthreads();
    }

#pragma unroll
    for (int p = 0; p < 4; p++) {
        const size_t m0 = (size_t)(bm + ty * 8 + 2 * p);
#pragma unroll
        for (int j = 0; j < 4; j++) {
            const int n = bn + tx * 4 + j;
            float lo, hi;
            upk2(acc2[p][j], lo, hi);
            C[m0 * ldc + n] = lo;
            C[(m0 + 1) * ldc + n] = hi;
        }
    }
}

// ---------------- deterministic column stats, partials laid out [col*64 + chunk] ----------------
__global__ void colstat_stage1(const float* __restrict__ X, int ncols,
                               float* __restrict__ ps, float* __restrict__ pq) {
    const int col = blockIdx.x * 256 + threadIdx.x;
    if (col >= ncols) return;
    const int chunk = blockIdx.y;
    const size_t base = (size_t)chunk * 1000 * ncols + col;
    float s = 0.f, q = 0.f;
    for (int r = 0; r < 1000; r++) {
        const float v = X[base + (size_t)r * ncols];
        s += v; q = fmaf(v, v, q);
    }
    ps[col * 64 + chunk] = s;
    pq[col * 64 + chunk] = q;
}

__global__ void colstat_stage2(const float* __restrict__ ps, const float* __restrict__ pq,
                               int ncols, const float* __restrict__ gamma,
                               const float* __restrict__ beta,
                               float* __restrict__ Aout, float* __restrict__ Cout) {
    const int col = blockIdx.x * 256 + threadIdx.x;
    if (col >= ncols) return;
    float s = 0.f, q = 0.f;
    for (int c = 0; c < 64; c++) { s += ps[col * 64 + c]; q += pq[col * 64 + c]; }
    const float m = s * (1.f / 64000.f);
    const float v = q * (1.f / 64000.f) - m * m;
    const float a = gamma[col] * rsqrtf(v + 1e-5f);
    Aout[col] = a;
    Cout[col] = beta[col] - m * a;
}

// ---------------- transpose + BN stats fold (computes A/C inline from partials) ----------------
__global__ __launch_bounds__(256) void transpose_fold2(
    const float* __restrict__ gh, const float* __restrict__ bhp,
    const float* __restrict__ gz, const float* __restrict__ bz,
    const float* __restrict__ gr, const float* __restrict__ br) {
    __shared__ float tile[32][65];
    __shared__ float sA[32], sC[32];
    const int t    = blockIdx.y;
    const int col0 = blockIdx.x * 32;
    const int tid  = threadIdx.x;

    if (tid < 32) {
        const int col = col0 + tid;
        float s = 0.f, q = 0.f;
        const float4* ps4 = (const float4*)(g_p1s + col * 64);
        const float4* pq4 = (const float4*)(g_p1q + col * 64);
#pragma unroll
        for (int c = 0; c < 16; c++) {
            const float4 a = ps4[c], b = pq4[c];
            s += a.x + a.y + a.z + a.w;
            q += b.x + b.y + b.z + b.w;
        }
        const float m = s * (1.f / 64000.f);
        const float v = q * (1.f / 64000.f) - m * m;
        float gamma, beta;
        if (col < 512)       { gamma = gh[col];        beta = bhp[col]; }
        else if (col < 1024) { gamma = gz[col - 512];  beta = bz[col - 512]; }
        else                 { gamma = gr[col - 1024]; beta = br[col - 1024]; }
        const float a = gamma * rsqrtf(v + 1e-5f);
        sA[tid] = a;
        sC[tid] = beta - m * a;
    }
    __syncthreads();

    const int rc = tid & 31;
    const int rb = tid >> 5;
    const float a = sA[rc];
    const float c = sC[rc];
#pragma unroll
    for (int bb = 0; bb < 8; bb++) {
        const int b = rb + bb * 8;
        const float v = g_Y[((size_t)t * B_ + b) * H3_ + col0 + rc];
        tile[rc][b] = fmaf(v, a, c);
    }
    __syncthreads();
    const int wb = tid & 63;
    const int wc = tid >> 6;
#pragma unroll
    for (int cc = 0; cc < 8; cc++) {
        const int cl = wc + cc * 4;
        g_YT[(size_t)t * (H3_ * B_) + (size_t)(col0 + cl) * B_ + wb] = tile[cl][wb];
    }
}

// ---------------- persistent scan v7: flag-array barrier + LDS.128 U loads ----------------
#define SMF_U1 0                    // [512k][16j]  = 8192
#define SMF_U2 8192                 // [512k][8j]   = 4096
#define SMF_P1 12288                // [16w][32b][18] = 9216
#define SMF_P2 21504                // [16w][32b][10] = 5120
#define SMF_T  26624                // [8j][32b] = 256
#define SMF_TOT 26880

__global__ __launch_bounds__(512, 1) void scan7_kernel(
    const float* __restrict__ Uh, const float* __restrict__ Uz,
    const float* __restrict__ Ur) {
    extern __shared__ float sm[];
    float* sU1 = sm + SMF_U1;
    float* sU2 = sm + SMF_U2;
    float* sP1 = sm + SMF_P1;
    float* sP2 = sm + SMF_P2;
    float* sT  = sm + SMF_T;
    __shared__ unsigned s_base;

    const int cta  = blockIdx.x;
    const int tid  = threadIdx.x;
    const int w    = tid >> 5;
    const int lane = tid & 31;
    const bool isR = cta >= 64;
    const int grp  = isR ? (cta - 64) : cta;
    const int jt1  = grp >> 1;
    const int bh   = cta & 1;
    const int jt2  = cta >> 1;
    const int bglob = bh * 32 + lane;

    unsigned* fl;
    asm("cvta.global.u64 %0, %1;" : "=l"(fl) : "l"(g_flags));

    // read monotonic barrier base (all flags equal at launch entry)
    if (tid == 0) {
        unsigned b;
        asm volatile("ld.relaxed.gpu.global.u32 %0, [%1];" : "=r"(b) : "l"(fl + cta));
        s_base = b;
    }

    {
        const float* U1 = isR ? Ur : Uz;
        for (int i = tid; i < 8192; i += 512) {
            const int k = i >> 4, jj = i & 15;
            sU1[i] = U1[(jt1 * 16 + jj) * H_ + k];
        }
        for (int i = tid; i < 4096; i += 512) {
            const int k = i >> 3, jj = i & 7;
            sU2[i] = Uh[(jt2 * 8 + jj) * H_ + k];
        }
    }
    if (tid < 256) g_hT[0][cta * 256 + tid] = 0.f;
    __syncthreads();
    const unsigned base = s_base;

    // flag-array barrier: arrival = own-flag store; wait = 128 threads poll one flag each
    auto gwait = [&](unsigned k) {
        __syncthreads();
        if (tid == 0)
            asm volatile("st.release.gpu.global.u32 [%0], %1;"
                         :: "l"(fl + cta), "r"(base + k) : "memory");
        if (tid < 128) {
            unsigned v;
            do {
                asm volatile("ld.acquire.gpu.global.u32 %0, [%1];"
                             : "=r"(v) : "l"(fl + tid) : "memory");
            } while ((v - base) < k);
        }
        __syncthreads();
    };

    gwait(1u);

    const int rj1 = tid >> 5;
    const int jglob1 = jt1 * 16 + rj1;
    const size_t yoff1 = (size_t)((isR ? 1024 : 512) + jglob1) * B_ + bglob;
    const int rj2 = (tid >> 5) & 7;
    const int jglob2 = jt2 * 8 + rj2;
    const size_t yoff2 = (size_t)jglob2 * B_ + bglob;
    const int kw = w * 32;

    for (int t = 0; t < S_; t++) {
        const float* hbuf = g_hT[t & 1];
        float* hnext = g_hT[(t + 1) & 1];
        const float* YTt = g_YT + (size_t)t * (H3_ * B_);

        const float yg = __ldcg(YTt + yoff1);
        const float hpre1 = isR ? __ldcg(hbuf + jglob1 * 64 + bglob) : 0.f;

        // ---- phase1 gemm: 32 front-batched LDG, LDS.128 U, FFMA2 sweep ----
        {
            float hr[32];
#pragma unroll
            for (int kk = 0; kk < 32; kk++)
                hr[kk] = __ldcg(hbuf + (kw + kk) * 64 + bglob);
            ull acc2[8];
#pragma unroll
            for (int p = 0; p < 8; p++) acc2[p] = 0ull;
#pragma unroll
            for (int kk = 0; kk < 32; kk++) {
                const ull hh = pk2(hr[kk], hr[kk]);
                const float* urow = &sU1[(kw + kk) * 16];
                const ulonglong2 u01 = *(const ulonglong2*)(urow);
                const ulonglong2 u23 = *(const ulonglong2*)(urow + 4);
                const ulonglong2 u45 = *(const ulonglong2*)(urow + 8);
                const ulonglong2 u67 = *(const ulonglong2*)(urow + 12);
                acc2[0] = ffma2(hh, u01.x, acc2[0]);
                acc2[1] = ffma2(hh, u01.y, acc2[1]);
                acc2[2] = ffma2(hh, u23.x, acc2[2]);
                acc2[3] = ffma2(hh, u23.y, acc2[3]);
                acc2[4] = ffma2(hh, u45.x, acc2[4]);
                acc2[5] = ffma2(hh, u45.y, acc2[5]);
                acc2[6] = ffma2(hh, u67.x, acc2[6]);
                acc2[7] = ffma2(hh, u67.y, acc2[7]);
            }
            ull* dst = (ull*)&sP1[w * 576 + lane * 18];
#pragma unroll
            for (int p = 0; p < 8; p++) dst[p] = acc2[p];
        }
        __syncthreads();

        // ---- phase1 reduce + activation -> z or rh ----
        {
            float pre = 0.f;
#pragma unroll
            for (int q = 0; q < 16; q++) pre += sP1[q * 576 + (tid & 31) * 18 + rj1];
            const float gate = 1.f / (1.f + __expf(-(yg + pre)));
            if (isR) g_rhT[jglob1 * 64 + bglob] = gate * hpre1;
            else     g_zT[jglob1 * 64 + bglob] = gate;
        }
        gwait(2u + 2u * (unsigned)t);

        float yh = 0.f, zv = 0.f, hp2 = 0.f;
        if (tid < 256) {
            yh  = __ldcg(YTt + yoff2);
            zv  = __ldcg(g_zT + jglob2 * 64 + bglob);
            hp2 = __ldcg(hbuf + jglob2 * 64 + bglob);
        }

        // ---- phase2 gemm ----
        {
            float rr[32];
#pragma unroll
            for (int kk = 0; kk < 32; kk++)
                rr[kk] = __ldcg(g_rhT + (kw + kk) * 64 + bglob);
            ull acc2[4];
#pragma unroll
            for (int p = 0; p < 4; p++) acc2[p] = 0ull;
#pragma unroll
            for (int kk = 0; kk < 32; kk++) {
                const ull rv = pk2(rr[kk], rr[kk]);
                const float* urow = &sU2[(kw + kk) * 8];
                const ulonglong2 u01 = *(const ulonglong2*)(urow);
                const ulonglong2 u23 = *(const ulonglong2*)(urow + 4);
                acc2[0] = ffma2(rv, u01.x, acc2[0]);
                acc2[1] = ffma2(rv, u01.y, acc2[1]);
                acc2[2] = ffma2(rv, u23.x, acc2[2]);
                acc2[3] = ffma2(rv, u23.y, acc2[3]);
            }
            ull* dst = (ull*)&sP2[w * 320 + lane * 10];
#pragma unroll
            for (int p = 0; p < 4; p++) dst[p] = acc2[p];
        }
        __syncthreads();

        // ---- phase2 reduce + h update ----
        if (tid < 256) {
            float pre = 0.f;
#pragma unroll
            for (int q = 0; q < 16; q++) pre += sP2[q * 320 + (tid & 31) * 10 + rj2];
            const float hc = tanhf(yh + pre);
            const float hn = fmaf(zv, hp2 - hc, hc);
            hnext[jglob2 * 64 + bglob] = hn;
            sT[rj2 * 32 + (tid & 31)] = hn;
        }
        __syncthreads();
        if (tid < 32) {
            const size_t row = (size_t)t * B_ + bh * 32 + tid;
            const float4 v0 = make_float4(sT[0 * 32 + tid], sT[1 * 32 + tid],
                                          sT[2 * 32 + tid], sT[3 * 32 + tid]);
            const float4 v1 = make_float4(sT[4 * 32 + tid], sT[5 * 32 + tid],
                                          sT[6 * 32 + tid], sT[7 * 32 + tid]);
            *(float4*)(g_Hst + row * H_ + jt2 * 8)     = v0;
            *(float4*)(g_Hst + row * H_ + jt2 * 8 + 4) = v1;
        }
        gwait(3u + 2u * (unsigned)t);
    }
}

// ---------------- row log_softmax with folded BN, in place ----------------
__global__ __launch_bounds__(256) void logsoftmax_kernel(float* __restrict__ C) {
    const int row = blockIdx.x;
    float* p = C + (size_t)row * O_;
    __shared__ float red[256];
    const int t = threadIdx.x;
    float mx = -3.4e38f;
    for (int j = t; j < O_; j += 256) {
        const float v = p[j] * g_A2[j] + g_C2[j];
        mx = fmaxf(mx, v);
    }
    red[t] = mx; __syncthreads();
    for (int s = 128; s > 0; s >>= 1) { if (t < s) red[t] = fmaxf(red[t], red[t + s]); __syncthreads(); }
    mx = red[0]; __syncthreads();
    float sum = 0.f;
    for (int j = t; j < O_; j += 256) {
        const float v = p[j] * g_A2[j] + g_C2[j];
        sum += expf(v - mx);
    }
    red[t] = sum; __syncthreads();
    for (int s = 128; s > 0; s >>= 1) { if (t < s) red[t] += red[t + s]; __syncthreads(); }
    const float lse = mx + logf(red[0]);
    __syncthreads();
    for (int j = t; j < O_; j += 256) {
        const float v = p[j] * g_A2[j] + g_C2[j];
        p[j] = v - lse;
    }
}

// ---------------- launch ----------------
extern "C" void kernel_launch(void* const* d_in, const int* in_sizes, int n_in,
                              void* d_out, int out_size) {
    const float* x  = (const float*)d_in[0];
    const float* Wh = (const float*)d_in[1];
    const float* Wz = (const float*)d_in[2];
    const float* Wr = (const float*)d_in[3];
    const float* Uh = (const float*)d_in[4];
    const float* Uz = (const float*)d_in[5];
    const float* Ur = (const float*)d_in[6];
    const float* gh = (const float*)d_in[7];
    const float* bh = (const float*)d_in[8];
    const float* gz = (const float*)d_in[9];
    const float* bz = (const float*)d_in[10];
    const float* gr = (const float*)d_in[11];
    const float* br = (const float*)d_in[12];
    const float* Wf = (const float*)d_in[13];
    const float* gf = (const float*)d_in[14];
    const float* bf = (const float*)d_in[15];
    float* out = (float*)d_out;

    float *pY, *pH, *p1s, *p1q, *p2s, *p2q, *pA2, *pC2;
    cudaGetSymbolAddress((void**)&pY,  g_Y);
    cudaGetSymbolAddress((void**)&pH,  g_Hst);
    cudaGetSymbolAddress((void**)&p1s, g_p1s);
    cudaGetSymbolAddress((void**)&p1q, g_p1q);
    cudaGetSymbolAddress((void**)&p2s, g_p2s);
    cudaGetSymbolAddress((void**)&p2q, g_p2q);
    cudaGetSymbolAddress((void**)&pA2, g_A2);
    cudaGetSymbolAddress((void**)&pC2, g_C2);

    cudaFuncSetAttribute(scan7_kernel, cudaFuncAttributeMaxDynamicSharedMemorySize,
                         SMF_TOT * (int)sizeof(float));

    // 0) gate projections straight from Wh/Wz/Wr: Y = x @ [Wh;Wz;Wr]^T
    sgemm_gate<<<dim3(H3_ / GBN, SB_ / GBM), 256>>>(x, Wh, Wz, Wr, pY);

    // 1) BN partial stats
    colstat_stage1<<<dim3(6, 64), 256>>>(pY, H3_, p1s, p1q);

    // 2) stats finalize + BN fold + transpose -> YT
    transpose_fold2<<<dim3(48, 1000), 256>>>(gh, bh, gz, bz, gr, br);

    // 3) persistent recurrent scan  (launch index 3 -> gets profiled by ncu)
    scan7_kernel<<<128, 512, SMF_TOT * sizeof(float)>>>(Uh, Uz, Ur);

    // 4) final projection into d_out
    sgemm_kernel<<<dim3((O_ + GBN - 1) / GBN, SB_ / GBM), 256>>>(pH, Wf, out, SB_, O_, H_, O_);

    // 5-6) output BN stats
    colstat_stage1<<<dim3(4, 64), 256>>>(out, O_, p2s, p2q);
    colstat_stage2<<<4, 256>>>(p2s, p2q, O_, gf, bf, pA2, pC2);

    // 7) BN-apply + log_softmax in place
    logsoftmax_kernel<<<SB_, 256>>>(out);
}

// round 9
// speedup vs baseline: 1.6550x; 1.6550x over previous
#include <cuda_runtime.h>
#include <math.h>

#define S_   1000
#define B_   64
#define D_   440
#define H_   512
#define O_   1000
#define SB_  64000
#define H3_  1536

typedef unsigned long long ull;

// ---------------- f32x2 packed helpers ----------------
__device__ __forceinline__ ull pk2(float x, float y) {
    ull r; asm("mov.b64 %0, {%1,%2};" : "=l"(r) : "f"(x), "f"(y)); return r;
}
__device__ __forceinline__ void upk2(ull v, float& x, float& y) {
    asm("mov.b64 {%0,%1}, %2;" : "=f"(x), "=f"(y) : "l"(v));
}
__device__ __forceinline__ ull ffma2(ull a, ull b, ull c) {
    ull d; asm("fma.rn.f32x2 %0, %1, %2, %3;" : "=l"(d) : "l"(a), "l"(b), "l"(c)); return d;
}

// ---------------- scratch ----------------
__device__ __align__(16) float g_Y[(size_t)SB_ * H3_];
__device__ __align__(16) float g_YT[(size_t)S_ * H3_ * B_];  // [t][col][b], BN-folded
__device__ __align__(16) float g_Hst[(size_t)SB_ * H_];
__device__ __align__(16) float g_hT[2][H_ * B_];             // [buf][k*64 + b]
__device__ __align__(16) float g_rhT[H_ * B_];
__device__ __align__(16) float g_zT[H_ * B_];
__device__ float g_p1s[64 * H3_], g_p1q[64 * H3_];           // [col*64 + chunk]
__device__ float g_p2s[64 * O_], g_p2q[64 * O_];             // [col*64 + chunk]
__device__ float g_A2[O_], g_C2[O_];
__device__ unsigned g_cnt;                                    // monotonic barrier counter

// ---------------- fp32 SGEMM (generic): C[M,N] = A[M,K] * Bw[N,K]^T ----------------
#define GBM 128
#define GBN 64
#define GBK 8
__global__ __launch_bounds__(256) void sgemm_kernel(
    const float* __restrict__ A, const float* __restrict__ Bw, float* __restrict__ C,
    int M, int N, int K, int ldc) {
    __shared__ float As[2][GBK][GBM + 4];
    __shared__ float Bs[2][GBK][GBN + 4];
    const int bm = blockIdx.y * GBM;
    const int bn = blockIdx.x * GBN;
    const int t  = threadIdx.x;
    const int tx = t & 15;
    const int ty = t >> 4;
    const int lam = t >> 1, lak = (t & 1) * 4;
    const int lbn = (t & 127) >> 1, lbk = (t & 1) * 4;
    const bool bload = t < 128;

    ull acc2[4][4];
#pragma unroll
    for (int p = 0; p < 4; p++)
#pragma unroll
        for (int j = 0; j < 4; j++) acc2[p][j] = 0ull;

    const int nt = K / GBK;
    float4 va, vb;
    va = *(const float4*)(A + (size_t)(bm + lam) * K + lak);
    vb = make_float4(0.f, 0.f, 0.f, 0.f);
    if (bload && (bn + lbn) < N) vb = *(const float4*)(Bw + (size_t)(bn + lbn) * K + lbk);
    As[0][lak + 0][lam] = va.x; As[0][lak + 1][lam] = va.y;
    As[0][lak + 2][lam] = va.z; As[0][lak + 3][lam] = va.w;
    if (bload) {
        Bs[0][lbk + 0][lbn] = vb.x; Bs[0][lbk + 1][lbn] = vb.y;
        Bs[0][lbk + 2][lbn] = vb.z; Bs[0][lbk + 3][lbn] = vb.w;
    }
    __syncthreads();

    for (int kt = 0; kt < nt; kt++) {
        const int cur = kt & 1;
        const bool has = (kt + 1) < nt;
        if (has) {
            const int k0 = (kt + 1) * GBK;
            va = *(const float4*)(A + (size_t)(bm + lam) * K + k0 + lak);
            vb = make_float4(0.f, 0.f, 0.f, 0.f);
            if (bload && (bn + lbn) < N)
                vb = *(const float4*)(Bw + (size_t)(bn + lbn) * K + k0 + lbk);
        }
#pragma unroll
        for (int k = 0; k < GBK; k++) {
            ull a2[4], bb[4];
#pragma unroll
            for (int p = 0; p < 4; p++)
                a2[p] = *(const ull*)&As[cur][k][ty * 8 + 2 * p];
#pragma unroll
            for (int j = 0; j < 4; j++) {
                const float bs = Bs[cur][k][tx * 4 + j];
                bb[j] = pk2(bs, bs);
            }
#pragma unroll
            for (int p = 0; p < 4; p++)
#pragma unroll
                for (int j = 0; j < 4; j++)
                    acc2[p][j] = ffma2(a2[p], bb[j], acc2[p][j]);
        }
        if (has) {
            const int nb = cur ^ 1;
            As[nb][lak + 0][lam] = va.x; As[nb][lak + 1][lam] = va.y;
            As[nb][lak + 2][lam] = va.z; As[nb][lak + 3][lam] = va.w;
            if (bload) {
                Bs[nb][lbk + 0][lbn] = vb.x; Bs[nb][lbk + 1][lbn] = vb.y;
                Bs[nb][lbk + 2][lbn] = vb.z; Bs[nb][lbk + 3][lbn] = vb.w;
            }
        }
        __syncthreads();
    }

#pragma unroll
    for (int p = 0; p < 4; p++) {
        const size_t m0 = (size_t)(bm + ty * 8 + 2 * p);
#pragma unroll
        for (int j = 0; j < 4; j++) {
            const int n = bn + tx * 4 + j;
            if (n < N) {
                float lo, hi;
                upk2(acc2[p][j], lo, hi);
                C[m0 * ldc + n] = lo;
                C[(m0 + 1) * ldc + n] = hi;
            }
        }
    }
}

// ---------------- gate SGEMM: B rows from Wh/Wz/Wr directly (N=1536, K=440) ----------------
__global__ __launch_bounds__(256) void sgemm_gate(
    const float* __restrict__ A, const float* __restrict__ Wh,
    const float* __restrict__ Wz, const float* __restrict__ Wr,
    float* __restrict__ C) {
    const int K = D_, ldc = H3_;
    __shared__ float As[2][GBK][GBM + 4];
    __shared__ float Bs[2][GBK][GBN + 4];
    const int bm = blockIdx.y * GBM;
    const int bn = blockIdx.x * GBN;
    const int t  = threadIdx.x;
    const int tx = t & 15;
    const int ty = t >> 4;
    const int lam = t >> 1, lak = (t & 1) * 4;
    const int lbn = (t & 127) >> 1, lbk = (t & 1) * 4;
    const bool bload = t < 128;

    const float* brow = 0;
    if (bload) {
        const int r = bn + lbn;
        brow = (r < 512) ? (Wh + (size_t)r * K)
             : (r < 1024) ? (Wz + (size_t)(r - 512) * K)
                          : (Wr + (size_t)(r - 1024) * K);
    }

    ull acc2[4][4];
#pragma unroll
    for (int p = 0; p < 4; p++)
#pragma unroll
        for (int j = 0; j < 4; j++) acc2[p][j] = 0ull;

    const int nt = K / GBK;
    float4 va, vb;
    va = *(const float4*)(A + (size_t)(bm + lam) * K + lak);
    vb = make_float4(0.f, 0.f, 0.f, 0.f);
    if (bload) vb = *(const float4*)(brow + lbk);
    As[0][lak + 0][lam] = va.x; As[0][lak + 1][lam] = va.y;
    As[0][lak + 2][lam] = va.z; As[0][lak + 3][lam] = va.w;
    if (bload) {
        Bs[0][lbk + 0][lbn] = vb.x; Bs[0][lbk + 1][lbn] = vb.y;
        Bs[0][lbk + 2][lbn] = vb.z; Bs[0][lbk + 3][lbn] = vb.w;
    }
    __syncthreads();

    for (int kt = 0; kt < nt; kt++) {
        const int cur = kt & 1;
        const bool has = (kt + 1) < nt;
        if (has) {
            const int k0 = (kt + 1) * GBK;
            va = *(const float4*)(A + (size_t)(bm + lam) * K + k0 + lak);
            if (bload) vb = *(const float4*)(brow + k0 + lbk);
        }
#pragma unroll
        for (int k = 0; k < GBK; k++) {
            ull a2[4], bb[4];
#pragma unroll
            for (int p = 0; p < 4; p++)
                a2[p] = *(const ull*)&As[cur][k][ty * 8 + 2 * p];
#pragma unroll
            for (int j = 0; j < 4; j++) {
                const float bs = Bs[cur][k][tx * 4 + j];
                bb[j] = pk2(bs, bs);
            }
#pragma unroll
            for (int p = 0; p < 4; p++)
#pragma unroll
                for (int j = 0; j < 4; j++)
                    acc2[p][j] = ffma2(a2[p], bb[j], acc2[p][j]);
        }
        if (has) {
            const int nb = cur ^ 1;
            As[nb][lak + 0][lam] = va.x; As[nb][lak + 1][lam] = va.y;
            As[nb][lak + 2][lam] = va.z; As[nb][lak + 3][lam] = va.w;
            if (bload) {
                Bs[nb][lbk + 0][lbn] = vb.x; Bs[nb][lbk + 1][lbn] = vb.y;
                Bs[nb][lbk + 2][lbn] = vb.z; Bs[nb][lbk + 3][lbn] = vb.w;
            }
        }
        __syncthreads();
    }

#pragma unroll
    for (int p = 0; p < 4; p++) {
        const size_t m0 = (size_t)(bm + ty * 8 + 2 * p);
#pragma unroll
        for (int j = 0; j < 4; j++) {
            const int n = bn + tx * 4 + j;
            float lo, hi;
            upk2(acc2[p][j], lo, hi);
            C[m0 * ldc + n] = lo;
            C[(m0 + 1) * ldc + n] = hi;
        }
    }
}

// ---------------- deterministic column stats, partials [col*64 + chunk] ----------------
__global__ void colstat_stage1(const float* __restrict__ X, int ncols,
                               float* __restrict__ ps, float* __restrict__ pq) {
    const int col = blockIdx.x * 256 + threadIdx.x;
    if (col >= ncols) return;
    const int chunk = blockIdx.y;
    const size_t base = (size_t)chunk * 1000 * ncols + col;
    float s = 0.f, q = 0.f;
    for (int r = 0; r < 1000; r++) {
        const float v = X[base + (size_t)r * ncols];
        s += v; q = fmaf(v, v, q);
    }
    ps[col * 64 + chunk] = s;
    pq[col * 64 + chunk] = q;
}

__global__ void colstat_stage2(const float* __restrict__ ps, const float* __restrict__ pq,
                               int ncols, const float* __restrict__ gamma,
                               const float* __restrict__ beta,
                               float* __restrict__ Aout, float* __restrict__ Cout) {
    const int col = blockIdx.x * 256 + threadIdx.x;
    if (col >= ncols) return;
    float s = 0.f, q = 0.f;
    for (int c = 0; c < 64; c++) { s += ps[col * 64 + c]; q += pq[col * 64 + c]; }
    const float m = s * (1.f / 64000.f);
    const float v = q * (1.f / 64000.f) - m * m;
    const float a = gamma[col] * rsqrtf(v + 1e-5f);
    Aout[col] = a;
    Cout[col] = beta[col] - m * a;
}

// ---------------- transpose + BN stats fold ----------------
__global__ __launch_bounds__(256) void transpose_fold2(
    const float* __restrict__ gh, const float* __restrict__ bhp,
    const float* __restrict__ gz, const float* __restrict__ bz,
    const float* __restrict__ gr, const float* __restrict__ br) {
    __shared__ float tile[32][65];
    __shared__ float sA[32], sC[32];
    const int t    = blockIdx.y;
    const int col0 = blockIdx.x * 32;
    const int tid  = threadIdx.x;

    if (tid < 32) {
        const int col = col0 + tid;
        float s = 0.f, q = 0.f;
        const float4* ps4 = (const float4*)(g_p1s + col * 64);
        const float4* pq4 = (const float4*)(g_p1q + col * 64);
#pragma unroll
        for (int c = 0; c < 16; c++) {
            const float4 a = ps4[c], b = pq4[c];
            s += a.x + a.y + a.z + a.w;
            q += b.x + b.y + b.z + b.w;
        }
        const float m = s * (1.f / 64000.f);
        const float v = q * (1.f / 64000.f) - m * m;
        float gamma, beta;
        if (col < 512)       { gamma = gh[col];        beta = bhp[col]; }
        else if (col < 1024) { gamma = gz[col - 512];  beta = bz[col - 512]; }
        else                 { gamma = gr[col - 1024]; beta = br[col - 1024]; }
        const float a = gamma * rsqrtf(v + 1e-5f);
        sA[tid] = a;
        sC[tid] = beta - m * a;
    }
    __syncthreads();

    const int rc = tid & 31;
    const int rb = tid >> 5;
    const float a = sA[rc];
    const float c = sC[rc];
#pragma unroll
    for (int bb = 0; bb < 8; bb++) {
        const int b = rb + bb * 8;
        const float v = g_Y[((size_t)t * B_ + b) * H3_ + col0 + rc];
        tile[rc][b] = fmaf(v, a, c);
    }
    __syncthreads();
    const int wb = tid & 63;
    const int wc = tid >> 6;
#pragma unroll
    for (int cc = 0; cc < 8; cc++) {
        const int cl = wc + cc * 4;
        g_YT[(size_t)t * (H3_ * B_) + (size_t)(col0 + cl) * B_ + wb] = tile[cl][wb];
    }
}

// ---------------- persistent scan v8: monotonic single-counter barrier ----------------
#define SMF_U1 0                    // [512k][16j]  = 8192
#define SMF_U2 8192                 // [512k][8j]   = 4096
#define SMF_P1 12288                // [16w][32b][18] = 9216
#define SMF_P2 21504                // [16w][32b][10] = 5120
#define SMF_T  26624                // [8j][32b] = 256
#define SMF_TOT 26880

__global__ __launch_bounds__(512, 1) void scan8_kernel(
    const float* __restrict__ Uh, const float* __restrict__ Uz,
    const float* __restrict__ Ur) {
    extern __shared__ float sm[];
    float* sU1 = sm + SMF_U1;
    float* sU2 = sm + SMF_U2;
    float* sP1 = sm + SMF_P1;
    float* sP2 = sm + SMF_P2;
    float* sT  = sm + SMF_T;
    __shared__ unsigned s_base;

    const int cta  = blockIdx.x;
    const int tid  = threadIdx.x;
    const int w    = tid >> 5;
    const int lane = tid & 31;
    const bool isR = cta >= 64;
    const int grp  = isR ? (cta - 64) : cta;
    const int jt1  = grp >> 1;
    const int bh   = cta & 1;
    const int jt2  = cta >> 1;
    const int bglob = bh * 32 + lane;

    unsigned* pc;
    asm("cvta.global.u64 %0, %1;" : "=l"(pc) : "l"(&g_cnt));

    // monotonic barrier base (all CTAs see identical value before any arrive)
    if (tid == 0) {
        unsigned b;
        asm volatile("ld.relaxed.gpu.global.u32 %0, [%1];" : "=r"(b) : "l"(pc));
        s_base = b;
    }

    {
        const float* U1 = isR ? Ur : Uz;
        for (int i = tid; i < 8192; i += 512) {
            const int k = i >> 4, jj = i & 15;
            sU1[i] = U1[(jt1 * 16 + jj) * H_ + k];
        }
        for (int i = tid; i < 4096; i += 512) {
            const int k = i >> 3, jj = i & 7;
            sU2[i] = Uh[(jt2 * 8 + jj) * H_ + k];
        }
    }
    if (tid < 256) g_hT[0][cta * 256 + tid] = 0.f;
    __syncthreads();
    const unsigned base = s_base;

    // barrier k (1-based): arrive = release-add; wait = tid0 polls until count-base >= 128k
    auto gwait = [&](unsigned k) {
        __syncthreads();
        if (tid == 0) {
            asm volatile("red.release.gpu.global.add.u32 [%0], 1;" :: "l"(pc) : "memory");
            const unsigned tgt = 128u * k;
            unsigned v;
            do {
                asm volatile("ld.acquire.gpu.global.u32 %0, [%1];"
                             : "=r"(v) : "l"(pc) : "memory");
            } while ((v - base) < tgt);
        }
        __syncthreads();
    };

    gwait(1u);

    const int rj1 = tid >> 5;
    const int jglob1 = jt1 * 16 + rj1;
    const size_t yoff1 = (size_t)((isR ? 1024 : 512) + jglob1) * B_ + bglob;
    const int rj2 = (tid >> 5) & 7;
    const int jglob2 = jt2 * 8 + rj2;
    const size_t yoff2 = (size_t)jglob2 * B_ + bglob;
    const int kw = w * 32;

    for (int t = 0; t < S_; t++) {
        const float* hbuf = g_hT[t & 1];
        float* hnext = g_hT[(t + 1) & 1];
        const float* YTt = g_YT + (size_t)t * (H3_ * B_);

        const float yg = __ldcg(YTt + yoff1);
        const float hpre1 = isR ? __ldcg(hbuf + jglob1 * 64 + bglob) : 0.f;

        // ---- phase1 gemm: 32 front-batched LDG, LDS.128 U, FFMA2 sweep ----
        {
            float hr[32];
#pragma unroll
            for (int kk = 0; kk < 32; kk++)
                hr[kk] = __ldcg(hbuf + (kw + kk) * 64 + bglob);
            ull acc2[8];
#pragma unroll
            for (int p = 0; p < 8; p++) acc2[p] = 0ull;
#pragma unroll
            for (int kk = 0; kk < 32; kk++) {
                const ull hh = pk2(hr[kk], hr[kk]);
                const float* urow = &sU1[(kw + kk) * 16];
                const ulonglong2 u01 = *(const ulonglong2*)(urow);
                const ulonglong2 u23 = *(const ulonglong2*)(urow + 4);
                const ulonglong2 u45 = *(const ulonglong2*)(urow + 8);
                const ulonglong2 u67 = *(const ulonglong2*)(urow + 12);
                acc2[0] = ffma2(hh, u01.x, acc2[0]);
                acc2[1] = ffma2(hh, u01.y, acc2[1]);
                acc2[2] = ffma2(hh, u23.x, acc2[2]);
                acc2[3] = ffma2(hh, u23.y, acc2[3]);
                acc2[4] = ffma2(hh, u45.x, acc2[4]);
                acc2[5] = ffma2(hh, u45.y, acc2[5]);
                acc2[6] = ffma2(hh, u67.x, acc2[6]);
                acc2[7] = ffma2(hh, u67.y, acc2[7]);
            }
            ull* dst = (ull*)&sP1[w * 576 + lane * 18];
#pragma unroll
            for (int p = 0; p < 8; p++) dst[p] = acc2[p];
        }
        __syncthreads();

        // ---- phase1 reduce + activation -> z or rh ----
        {
            float pre = 0.f;
#pragma unroll
            for (int q = 0; q < 16; q++) pre += sP1[q * 576 + (tid & 31) * 18 + rj1];
            const float gate = 1.f / (1.f + __expf(-(yg + pre)));
            if (isR) g_rhT[jglob1 * 64 + bglob] = gate * hpre1;
            else     g_zT[jglob1 * 64 + bglob] = gate;
        }
        gwait(2u + 2u * (unsigned)t);

        float yh = 0.f, zv = 0.f, hp2 = 0.f;
        if (tid < 256) {
            yh  = __ldcg(YTt + yoff2);
            zv  = __ldcg(g_zT + jglob2 * 64 + bglob);
            hp2 = __ldcg(hbuf + jglob2 * 64 + bglob);
        }

        // ---- phase2 gemm ----
        {
            float rr[32];
#pragma unroll
            for (int kk = 0; kk < 32; kk++)
                rr[kk] = __ldcg(g_rhT + (kw + kk) * 64 + bglob);
            ull acc2[4];
#pragma unroll
            for (int p = 0; p < 4; p++) acc2[p] = 0ull;
#pragma unroll
            for (int kk = 0; kk < 32; kk++) {
                const ull rv = pk2(rr[kk], rr[kk]);
                const float* urow = &sU2[(kw + kk) * 8];
                const ulonglong2 u01 = *(const ulonglong2*)(urow);
                const ulonglong2 u23 = *(const ulonglong2*)(urow + 4);
                acc2[0] = ffma2(rv, u01.x, acc2[0]);
                acc2[1] = ffma2(rv, u01.y, acc2[1]);
                acc2[2] = ffma2(rv, u23.x, acc2[2]);
                acc2[3] = ffma2(rv, u23.y, acc2[3]);
            }
            ull* dst = (ull*)&sP2[w * 320 + lane * 10];
#pragma unroll
            for (int p = 0; p < 4; p++) dst[p] = acc2[p];
        }
        __syncthreads();

        // ---- phase2 reduce + h update ----
        if (tid < 256) {
            float pre = 0.f;
#pragma unroll
            for (int q = 0; q < 16; q++) pre += sP2[q * 320 + (tid & 31) * 10 + rj2];
            const float hc = tanhf(yh + pre);
            const float hn = fmaf(zv, hp2 - hc, hc);
            hnext[jglob2 * 64 + bglob] = hn;
            sT[rj2 * 32 + (tid & 31)] = hn;
        }
        __syncthreads();
        if (tid < 32) {
            const size_t row = (size_t)t * B_ + bh * 32 + tid;
            const float4 v0 = make_float4(sT[0 * 32 + tid], sT[1 * 32 + tid],
                                          sT[2 * 32 + tid], sT[3 * 32 + tid]);
            const float4 v1 = make_float4(sT[4 * 32 + tid], sT[5 * 32 + tid],
                                          sT[6 * 32 + tid], sT[7 * 32 + tid]);
            *(float4*)(g_Hst + row * H_ + jt2 * 8)     = v0;
            *(float4*)(g_Hst + row * H_ + jt2 * 8 + 4) = v1;
        }
        gwait(3u + 2u * (unsigned)t);
    }
}

// ---------------- row log_softmax with folded BN, in place ----------------
__global__ __launch_bounds__(256) void logsoftmax_kernel(float* __restrict__ C) {
    const int row = blockIdx.x;
    float* p = C + (size_t)row * O_;
    __shared__ float red[256];
    const int t = threadIdx.x;
    float mx = -3.4e38f;
    for (int j = t; j < O_; j += 256) {
        const float v = p[j] * g_A2[j] + g_C2[j];
        mx = fmaxf(mx, v);
    }
    red[t] = mx; __syncthreads();
    for (int s = 128; s > 0; s >>= 1) { if (t < s) red[t] = fmaxf(red[t], red[t + s]); __syncthreads(); }
    mx = red[0]; __syncthreads();
    float sum = 0.f;
    for (int j = t; j < O_; j += 256) {
        const float v = p[j] * g_A2[j] + g_C2[j];
        sum += expf(v - mx);
    }
    red[t] = sum; __syncthreads();
    for (int s = 128; s > 0; s >>= 1) { if (t < s) red[t] += red[t + s]; __syncthreads(); }
    const float lse = mx + logf(red[0]);
    __syncthreads();
    for (int j = t; j < O_; j += 256) {
        const float v = p[j] * g_A2[j] + g_C2[j];
        p[j] = v - lse;
    }
}

// ---------------- launch ----------------
extern "C" void kernel_launch(void* const* d_in, const int* in_sizes, int n_in,
                              void* d_out, int out_size) {
    const float* x  = (const float*)d_in[0];
    const float* Wh = (const float*)d_in[1];
    const float* Wz = (const float*)d_in[2];
    const float* Wr = (const float*)d_in[3];
    const float* Uh = (const float*)d_in[4];
    const float* Uz = (const float*)d_in[5];
    const float* Ur = (const float*)d_in[6];
    const float* gh = (const float*)d_in[7];
    const float* bh = (const float*)d_in[8];
    const float* gz = (const float*)d_in[9];
    const float* bz = (const float*)d_in[10];
    const float* gr = (const float*)d_in[11];
    const float* br = (const float*)d_in[12];
    const float* Wf = (const float*)d_in[13];
    const float* gf = (const float*)d_in[14];
    const float* bf = (const float*)d_in[15];
    float* out = (float*)d_out;

    float *pY, *pH, *p1s, *p1q, *p2s, *p2q, *pA2, *pC2;
    cudaGetSymbolAddress((void**)&pY,  g_Y);
    cudaGetSymbolAddress((void**)&pH,  g_Hst);
    cudaGetSymbolAddress((void**)&p1s, g_p1s);
    cudaGetSymbolAddress((void**)&p1q, g_p1q);
    cudaGetSymbolAddress((void**)&p2s, g_p2s);
    cudaGetSymbolAddress((void**)&p2q, g_p2q);
    cudaGetSymbolAddress((void**)&pA2, g_A2);
    cudaGetSymbolAddress((void**)&pC2, g_C2);

    cudaFuncSetAttribute(scan8_kernel, cudaFuncAttributeMaxDynamicSharedMemorySize,
                         SMF_TOT * (int)sizeof(float));

    // 0) gate projections straight from Wh/Wz/Wr
    sgemm_gate<<<dim3(H3_ / GBN, SB_ / GBM), 256>>>(x, Wh, Wz, Wr, pY);

    // 1) BN partial stats
    colstat_stage1<<<dim3(6, 64), 256>>>(pY, H3_, p1s, p1q);

    // 2) stats finalize + BN fold + transpose -> YT
    transpose_fold2<<<dim3(48, 1000), 256>>>(gh, bh, gz, bz, gr, br);

    // 3) persistent recurrent scan
    scan8_kernel<<<128, 512, SMF_TOT * sizeof(float)>>>(Uh, Uz, Ur);

    // 4) final projection into d_out
    sgemm_kernel<<<dim3((O_ + GBN - 1) / GBN, SB_ / GBM), 256>>>(pH, Wf, out, SB_, O_, H_, O_);

    // 5-6) output BN stats
    colstat_stage1<<<dim3(4, 64), 256>>>(out, O_, p2s, p2q);
    colstat_stage2<<<4, 256>>>(p2s, p2q, O_, gf, bf, pA2, pC2);

    // 7) BN-apply + log_softmax in place
    logsoftmax_kernel<<<SB_, 256>>>(out);
}

// round 10
// speedup vs baseline: 1.7391x; 1.0508x over previous
#include <cuda_runtime.h>
#include <math.h>

#define S_   1000
#define B_   64
#define D_   440
#define H_   512
#define O_   1000
#define SB_  64000
#define H3_  1536

typedef unsigned long long ull;

// ---------------- f32x2 packed helpers ----------------
__device__ __forceinline__ ull pk2(float x, float y) {
    ull r; asm("mov.b64 %0, {%1,%2};" : "=l"(r) : "f"(x), "f"(y)); return r;
}
__device__ __forceinline__ void upk2(ull v, float& x, float& y) {
    asm("mov.b64 {%0,%1}, %2;" : "=f"(x), "=f"(y) : "l"(v));
}
__device__ __forceinline__ ull ffma2(ull a, ull b, ull c) {
    ull d; asm("fma.rn.f32x2 %0, %1, %2, %3;" : "=l"(d) : "l"(a), "l"(b), "l"(c)); return d;
}

// ---------------- scratch ----------------
__device__ __align__(16) float g_Y[(size_t)SB_ * H3_];
__device__ __align__(16) float g_YT[(size_t)S_ * H3_ * B_];  // [t][col][b], BN-folded
__device__ __align__(16) float g_Hst[(size_t)SB_ * H_];
__device__ __align__(16) float g_hT[2][H_ * B_];             // [buf][k*64 + b]
__device__ __align__(16) float g_rhT[H_ * B_];
__device__ __align__(16) float g_zT[H_ * B_];
__device__ float g_p1s[64 * H3_], g_p1q[64 * H3_];           // [col*64 + chunk]
__device__ float g_p2s[64 * O_], g_p2q[64 * O_];
__device__ float g_A2[O_], g_C2[O_];
__device__ __align__(128) unsigned g_cnt2[64];               // [0]=bh0, [32]=bh1 (128B apart)

// ---------------- fp32 SGEMM (generic): C[M,N] = A[M,K] * Bw[N,K]^T ----------------
#define GBM 128
#define GBN 64
#define GBK 8
__global__ __launch_bounds__(256) void sgemm_kernel(
    const float* __restrict__ A, const float* __restrict__ Bw, float* __restrict__ C,
    int M, int N, int K, int ldc) {
    __shared__ float As[2][GBK][GBM + 4];
    __shared__ float Bs[2][GBK][GBN + 4];
    const int bm = blockIdx.y * GBM;
    const int bn = blockIdx.x * GBN;
    const int t  = threadIdx.x;
    const int tx = t & 15;
    const int ty = t >> 4;
    const int lam = t >> 1, lak = (t & 1) * 4;
    const int lbn = (t & 127) >> 1, lbk = (t & 1) * 4;
    const bool bload = t < 128;

    ull acc2[4][4];
#pragma unroll
    for (int p = 0; p < 4; p++)
#pragma unroll
        for (int j = 0; j < 4; j++) acc2[p][j] = 0ull;

    const int nt = K / GBK;
    float4 va, vb;
    va = *(const float4*)(A + (size_t)(bm + lam) * K + lak);
    vb = make_float4(0.f, 0.f, 0.f, 0.f);
    if (bload && (bn + lbn) < N) vb = *(const float4*)(Bw + (size_t)(bn + lbn) * K + lbk);
    As[0][lak + 0][lam] = va.x; As[0][lak + 1][lam] = va.y;
    As[0][lak + 2][lam] = va.z; As[0][lak + 3][lam] = va.w;
    if (bload) {
        Bs[0][lbk + 0][lbn] = vb.x; Bs[0][lbk + 1][lbn] = vb.y;
        Bs[0][lbk + 2][lbn] = vb.z; Bs[0][lbk + 3][lbn] = vb.w;
    }
    __syncthreads();

    for (int kt = 0; kt < nt; kt++) {
        const int cur = kt & 1;
        const bool has = (kt + 1) < nt;
        if (has) {
            const int k0 = (kt + 1) * GBK;
            va = *(const float4*)(A + (size_t)(bm + lam) * K + k0 + lak);
            vb = make_float4(0.f, 0.f, 0.f, 0.f);
            if (bload && (bn + lbn) < N)
                vb = *(const float4*)(Bw + (size_t)(bn + lbn) * K + k0 + lbk);
        }
#pragma unroll
        for (int k = 0; k < GBK; k++) {
            ull a2[4], bb[4];
#pragma unroll
            for (int p = 0; p < 4; p++)
                a2[p] = *(const ull*)&As[cur][k][ty * 8 + 2 * p];
#pragma unroll
            for (int j = 0; j < 4; j++) {
                const float bs = Bs[cur][k][tx * 4 + j];
                bb[j] = pk2(bs, bs);
            }
#pragma unroll
            for (int p = 0; p < 4; p++)
#pragma unroll
                for (int j = 0; j < 4; j++)
                    acc2[p][j] = ffma2(a2[p], bb[j], acc2[p][j]);
        }
        if (has) {
            const int nb = cur ^ 1;
            As[nb][lak + 0][lam] = va.x; As[nb][lak + 1][lam] = va.y;
            As[nb][lak + 2][lam] = va.z; As[nb][lak + 3][lam] = va.w;
            if (bload) {
                Bs[nb][lbk + 0][lbn] = vb.x; Bs[nb][lbk + 1][lbn] = vb.y;
                Bs[nb][lbk + 2][lbn] = vb.z; Bs[nb][lbk + 3][lbn] = vb.w;
            }
        }
        __syncthreads();
    }

#pragma unroll
    for (int p = 0; p < 4; p++) {
        const size_t m0 = (size_t)(bm + ty * 8 + 2 * p);
#pragma unroll
        for (int j = 0; j < 4; j++) {
            const int n = bn + tx * 4 + j;
            if (n < N) {
                float lo, hi;
                upk2(acc2[p][j], lo, hi);
                C[m0 * ldc + n] = lo;
                C[(m0 + 1) * ldc + n] = hi;
            }
        }
    }
}

// ---------------- gate SGEMM: B rows from Wh/Wz/Wr directly (N=1536, K=440) ----------------
__global__ __launch_bounds__(256) void sgemm_gate(
    const float* __restrict__ A, const float* __restrict__ Wh,
    const float* __restrict__ Wz, const float* __restrict__ Wr,
    float* __restrict__ C) {
    const int K = D_, ldc = H3_;
    __shared__ float As[2][GBK][GBM + 4];
    __shared__ float Bs[2][GBK][GBN + 4];
    const int bm = blockIdx.y * GBM;
    const int bn = blockIdx.x * GBN;
    const int t  = threadIdx.x;
    const int tx = t & 15;
    const int ty = t >> 4;
    const int lam = t >> 1, lak = (t & 1) * 4;
    const int lbn = (t & 127) >> 1, lbk = (t & 1) * 4;
    const bool bload = t < 128;

    const float* brow = 0;
    if (bload) {
        const int r = bn + lbn;
        brow = (r < 512) ? (Wh + (size_t)r * K)
             : (r < 1024) ? (Wz + (size_t)(r - 512) * K)
                          : (Wr + (size_t)(r - 1024) * K);
    }

    ull acc2[4][4];
#pragma unroll
    for (int p = 0; p < 4; p++)
#pragma unroll
        for (int j = 0; j < 4; j++) acc2[p][j] = 0ull;

    const int nt = K / GBK;
    float4 va, vb;
    va = *(const float4*)(A + (size_t)(bm + lam) * K + lak);
    vb = make_float4(0.f, 0.f, 0.f, 0.f);
    if (bload) vb = *(const float4*)(brow + lbk);
    As[0][lak + 0][lam] = va.x; As[0][lak + 1][lam] = va.y;
    As[0][lak + 2][lam] = va.z; As[0][lak + 3][lam] = va.w;
    if (bload) {
        Bs[0][lbk + 0][lbn] = vb.x; Bs[0][lbk + 1][lbn] = vb.y;
        Bs[0][lbk + 2][lbn] = vb.z; Bs[0][lbk + 3][lbn] = vb.w;
    }
    __syncthreads();

    for (int kt = 0; kt < nt; kt++) {
        const int cur = kt & 1;
        const bool has = (kt + 1) < nt;
        if (has) {
            const int k0 = (kt + 1) * GBK;
            va = *(const float4*)(A + (size_t)(bm + lam) * K + k0 + lak);
            if (bload) vb = *(const float4*)(brow + k0 + lbk);
        }
#pragma unroll
        for (int k = 0; k < GBK; k++) {
            ull a2[4], bb[4];
#pragma unroll
            for (int p = 0; p < 4; p++)
                a2[p] = *(const ull*)&As[cur][k][ty * 8 + 2 * p];
#pragma unroll
            for (int j = 0; j < 4; j++) {
                const float bs = Bs[cur][k][tx * 4 + j];
                bb[j] = pk2(bs, bs);
            }
#pragma unroll
            for (int p = 0; p < 4; p++)
#pragma unroll
                for (int j = 0; j < 4; j++)
                    acc2[p][j] = ffma2(a2[p], bb[j], acc2[p][j]);
        }
        if (has) {
            const int nb = cur ^ 1;
            As[nb][lak + 0][lam] = va.x; As[nb][lak + 1][lam] = va.y;
            As[nb][lak + 2][lam] = va.z; As[nb][lak + 3][lam] = va.w;
            if (bload) {
                Bs[nb][lbk + 0][lbn] = vb.x; Bs[nb][lbk + 1][lbn] = vb.y;
                Bs[nb][lbk + 2][lbn] = vb.z; Bs[nb][lbk + 3][lbn] = vb.w;
            }
        }
        __syncthreads();
    }

#pragma unroll
    for (int p = 0; p < 4; p++) {
        const size_t m0 = (size_t)(bm + ty * 8 + 2 * p);
#pragma unroll
        for (int j = 0; j < 4; j++) {
            const int n = bn + tx * 4 + j;
            float lo, hi;
            upk2(acc2[p][j], lo, hi);
            C[m0 * ldc + n] = lo;
            C[(m0 + 1) * ldc + n] = hi;
        }
    }
}

// ---------------- deterministic column stats, partials [col*64 + chunk] ----------------
__global__ void colstat_stage1(const float* __restrict__ X, int ncols,
                               float* __restrict__ ps, float* __restrict__ pq) {
    const int col = blockIdx.x * 256 + threadIdx.x;
    if (col >= ncols) return;
    const int chunk = blockIdx.y;
    const size_t base = (size_t)chunk * 1000 * ncols + col;
    float s = 0.f, q = 0.f;
    for (int r = 0; r < 1000; r++) {
        const float v = X[base + (size_t)r * ncols];
        s += v; q = fmaf(v, v, q);
    }
    ps[col * 64 + chunk] = s;
    pq[col * 64 + chunk] = q;
}

__global__ void colstat_stage2(const float* __restrict__ ps, const float* __restrict__ pq,
                               int ncols, const float* __restrict__ gamma,
                               const float* __restrict__ beta,
                               float* __restrict__ Aout, float* __restrict__ Cout) {
    const int col = blockIdx.x * 256 + threadIdx.x;
    if (col >= ncols) return;
    float s = 0.f, q = 0.f;
    for (int c = 0; c < 64; c++) { s += ps[col * 64 + c]; q += pq[col * 64 + c]; }
    const float m = s * (1.f / 64000.f);
    const float v = q * (1.f / 64000.f) - m * m;
    const float a = gamma[col] * rsqrtf(v + 1e-5f);
    Aout[col] = a;
    Cout[col] = beta[col] - m * a;
}

// ---------------- transpose + BN stats fold ----------------
__global__ __launch_bounds__(256) void transpose_fold2(
    const float* __restrict__ gh, const float* __restrict__ bhp,
    const float* __restrict__ gz, const float* __restrict__ bz,
    const float* __restrict__ gr, const float* __restrict__ br) {
    __shared__ float tile[32][65];
    __shared__ float sA[32], sC[32];
    const int t    = blockIdx.y;
    const int col0 = blockIdx.x * 32;
    const int tid  = threadIdx.x;

    if (tid < 32) {
        const int col = col0 + tid;
        float s = 0.f, q = 0.f;
        const float4* ps4 = (const float4*)(g_p1s + col * 64);
        const float4* pq4 = (const float4*)(g_p1q + col * 64);
#pragma unroll
        for (int c = 0; c < 16; c++) {
            const float4 a = ps4[c], b = pq4[c];
            s += a.x + a.y + a.z + a.w;
            q += b.x + b.y + b.z + b.w;
        }
        const float m = s * (1.f / 64000.f);
        const float v = q * (1.f / 64000.f) - m * m;
        float gamma, beta;
        if (col < 512)       { gamma = gh[col];        beta = bhp[col]; }
        else if (col < 1024) { gamma = gz[col - 512];  beta = bz[col - 512]; }
        else                 { gamma = gr[col - 1024]; beta = br[col - 1024]; }
        const float a = gamma * rsqrtf(v + 1e-5f);
        sA[tid] = a;
        sC[tid] = beta - m * a;
    }
    __syncthreads();

    const int rc = tid & 31;
    const int rb = tid >> 5;
    const float a = sA[rc];
    const float c = sC[rc];
#pragma unroll
    for (int bb = 0; bb < 8; bb++) {
        const int b = rb + bb * 8;
        const float v = g_Y[((size_t)t * B_ + b) * H3_ + col0 + rc];
        tile[rc][b] = fmaf(v, a, c);
    }
    __syncthreads();
    const int wb = tid & 63;
    const int wc = tid >> 6;
#pragma unroll
    for (int cc = 0; cc < 8; cc++) {
        const int cl = wc + cc * 4;
        g_YT[(size_t)t * (H3_ * B_) + (size_t)(col0 + cl) * B_ + wb] = tile[cl][wb];
    }
}

// ---------------- persistent scan v9: per-bh barriers + arrive/wait overlap ----------------
#define SMF_U1 0                    // [512k][16j]  = 8192
#define SMF_U2 8192                 // [512k][8j]   = 4096
#define SMF_P1 12288                // [16w][32b][18] = 9216
#define SMF_P2 21504                // [16w][32b][10] = 5120
#define SMF_T  26624                // [8j][32b] = 256
#define SMF_TOT 26880

__global__ __launch_bounds__(512, 1) void scan9_kernel(
    const float* __restrict__ Uh, const float* __restrict__ Uz,
    const float* __restrict__ Ur) {
    extern __shared__ float sm[];
    float* sU1 = sm + SMF_U1;
    float* sU2 = sm + SMF_U2;
    float* sP1 = sm + SMF_P1;
    float* sP2 = sm + SMF_P2;
    float* sT  = sm + SMF_T;
    __shared__ unsigned s_base;

    const int cta  = blockIdx.x;
    const int tid  = threadIdx.x;
    const int w    = tid >> 5;
    const int lane = tid & 31;
    const bool isR = cta >= 64;
    const int grp  = isR ? (cta - 64) : cta;
    const int jt1  = grp >> 1;
    const int bh   = cta & 1;
    const int jt2  = cta >> 1;
    const int bglob = bh * 32 + lane;

    unsigned* pc;
    asm("cvta.global.u64 %0, %1;" : "=l"(pc) : "l"(&g_cnt2[0]));
    pc += bh * 32;                      // per-b-half counter, 128 B apart

    // read monotonic base FIRST (before any CTA of this launch can arrive)
    if (tid == 0) {
        unsigned b;
        asm volatile("ld.relaxed.gpu.global.u32 %0, [%1];" : "=r"(b) : "l"(pc));
        s_base = b;
    }

    {
        const float* U1 = isR ? Ur : Uz;
        for (int i = tid; i < 8192; i += 512) {
            const int k = i >> 4, jj = i & 15;
            sU1[i] = U1[(jt1 * 16 + jj) * H_ + k];
        }
        for (int i = tid; i < 4096; i += 512) {
            const int k = i >> 3, jj = i & 7;
            sU2[i] = Uh[(jt2 * 8 + jj) * H_ + k];
        }
    }
    if (tid < 256) g_hT[0][cta * 256 + tid] = 0.f;
    __syncthreads();
    const unsigned base = s_base;

    // split barrier: arrive = release-add (after syncthreads); wait = tid0 polls 64*k
    auto arrive = [&]() {
        __syncthreads();
        if (tid == 0)
            asm volatile("red.release.gpu.global.add.u32 [%0], 1;" :: "l"(pc) : "memory");
    };
    auto wait = [&](unsigned k) {
        if (tid == 0) {
            const unsigned tgt = 64u * k;
            unsigned v;
            do {
                asm volatile("ld.acquire.gpu.global.u32 %0, [%1];"
                             : "=r"(v) : "l"(pc) : "memory");
            } while ((v - base) < tgt);
        }
        __syncthreads();
    };

    const int rj1 = tid >> 5;
    const int jglob1 = jt1 * 16 + rj1;
    const size_t yoff1 = (size_t)((isR ? 1024 : 512) + jglob1) * B_ + bglob;
    const int rj2 = (tid >> 5) & 7;
    const int jglob2 = jt2 * 8 + rj2;
    const size_t yoff2 = (size_t)jglob2 * B_ + bglob;
    const int kw = w * 32;

    arrive(); wait(1u);

    // prefetch yg for t=0
    float yg = __ldcg(g_YT + yoff1);

    for (int t = 0; t < S_; t++) {
        const float* hbuf = g_hT[t & 1];
        float* hnext = g_hT[(t + 1) & 1];
        const float* YTt = g_YT + (size_t)t * (H3_ * B_);

        const float hpre1 = isR ? __ldcg(hbuf + jglob1 * 64 + bglob) : 0.f;

        // ---- phase1 gemm: 32 front-batched LDG, LDS.128 U, FFMA2 sweep ----
        {
            float hr[32];
#pragma unroll
            for (int kk = 0; kk < 32; kk++)
                hr[kk] = __ldcg(hbuf + (kw + kk) * 64 + bglob);
            ull acc2[8];
#pragma unroll
            for (int p = 0; p < 8; p++) acc2[p] = 0ull;
#pragma unroll
            for (int kk = 0; kk < 32; kk++) {
                const ull hh = pk2(hr[kk], hr[kk]);
                const float* urow = &sU1[(kw + kk) * 16];
                const ulonglong2 u01 = *(const ulonglong2*)(urow);
                const ulonglong2 u23 = *(const ulonglong2*)(urow + 4);
                const ulonglong2 u45 = *(const ulonglong2*)(urow + 8);
                const ulonglong2 u67 = *(const ulonglong2*)(urow + 12);
                acc2[0] = ffma2(hh, u01.x, acc2[0]);
                acc2[1] = ffma2(hh, u01.y, acc2[1]);
                acc2[2] = ffma2(hh, u23.x, acc2[2]);
                acc2[3] = ffma2(hh, u23.y, acc2[3]);
                acc2[4] = ffma2(hh, u45.x, acc2[4]);
                acc2[5] = ffma2(hh, u45.y, acc2[5]);
                acc2[6] = ffma2(hh, u67.x, acc2[6]);
                acc2[7] = ffma2(hh, u67.y, acc2[7]);
            }
            ull* dst = (ull*)&sP1[w * 576 + lane * 18];
#pragma unroll
            for (int p = 0; p < 8; p++) dst[p] = acc2[p];
        }
        __syncthreads();

        // ---- phase1 reduce + activation -> z or rh ----
        {
            float pre = 0.f;
#pragma unroll
            for (int q = 0; q < 16; q++) pre += sP1[q * 576 + (tid & 31) * 18 + rj1];
            const float gate = 1.f / (1.f + __expf(-(yg + pre)));
            if (isR) g_rhT[jglob1 * 64 + bglob] = gate * hpre1;
            else     g_zT[jglob1 * 64 + bglob] = gate;
        }
        arrive();                                   // B1: rh/z published

        // overlap with B1 wait: loads independent of this barrier
        float yh = 0.f, hp2 = 0.f;
        if (tid < 256) {
            yh  = __ldcg(YTt + yoff2);              // read-only YT
            hp2 = __ldcg(hbuf + jglob2 * 64 + bglob); // prev-step h (already visible)
        }
        wait(2u + 2u * (unsigned)t);

        float zv = 0.f;
        if (tid < 256) zv = __ldcg(g_zT + jglob2 * 64 + bglob);

        // ---- phase2 gemm ----
        {
            float rr[32];
#pragma unroll
            for (int kk = 0; kk < 32; kk++)
                rr[kk] = __ldcg(g_rhT + (kw + kk) * 64 + bglob);
            ull acc2[4];
#pragma unroll
            for (int p = 0; p < 4; p++) acc2[p] = 0ull;
#pragma unroll
            for (int kk = 0; kk < 32; kk++) {
                const ull rv = pk2(rr[kk], rr[kk]);
                const float* urow = &sU2[(kw + kk) * 8];
                const ulonglong2 u01 = *(const ulonglong2*)(urow);
                const ulonglong2 u23 = *(const ulonglong2*)(urow + 4);
                acc2[0] = ffma2(rv, u01.x, acc2[0]);
                acc2[1] = ffma2(rv, u01.y, acc2[1]);
                acc2[2] = ffma2(rv, u23.x, acc2[2]);
                acc2[3] = ffma2(rv, u23.y, acc2[3]);
            }
            ull* dst = (ull*)&sP2[w * 320 + lane * 10];
#pragma unroll
            for (int p = 0; p < 4; p++) dst[p] = acc2[p];
        }
        __syncthreads();

        // ---- phase2 reduce + h update ----
        if (tid < 256) {
            float pre = 0.f;
#pragma unroll
            for (int q = 0; q < 16; q++) pre += sP2[q * 320 + (tid & 31) * 10 + rj2];
            const float hc = tanhf(yh + pre);
            const float hn = fmaf(zv, hp2 - hc, hc);
            hnext[jglob2 * 64 + bglob] = hn;
            sT[rj2 * 32 + (tid & 31)] = hn;
        }
        arrive();                                   // B2: hnext published

        // overlap with B2 wait: archive h_t + prefetch next yg (read-only)
        if (tid < 32) {
            const size_t row = (size_t)t * B_ + bh * 32 + tid;
            const float4 v0 = make_float4(sT[0 * 32 + tid], sT[1 * 32 + tid],
                                          sT[2 * 32 + tid], sT[3 * 32 + tid]);
            const float4 v1 = make_float4(sT[4 * 32 + tid], sT[5 * 32 + tid],
                                          sT[6 * 32 + tid], sT[7 * 32 + tid]);
            *(float4*)(g_Hst + row * H_ + jt2 * 8)     = v0;
            *(float4*)(g_Hst + row * H_ + jt2 * 8 + 4) = v1;
        }
        {
            const int tn = (t + 1 < S_) ? (t + 1) : t;
            yg = __ldcg(g_YT + (size_t)tn * (H3_ * B_) + yoff1);
        }
        wait(3u + 2u * (unsigned)t);
    }
}

// ---------------- row log_softmax, single global read, folded BN ----------------
__global__ __launch_bounds__(256) void logsoftmax_kernel(float* __restrict__ C) {
    const int row = blockIdx.x;
    float* p = C + (size_t)row * O_;
    __shared__ float red[256];
    const int t = threadIdx.x;
    float v[4];
    float mx = -3.4e38f;
#pragma unroll
    for (int i = 0; i < 4; i++) {
        const int j = t + i * 256;
        if (j < O_) {
            v[i] = p[j] * g_A2[j] + g_C2[j];
            mx = fmaxf(mx, v[i]);
        } else v[i] = -3.4e38f;
    }
    red[t] = mx; __syncthreads();
    for (int s = 128; s > 0; s >>= 1) { if (t < s) red[t] = fmaxf(red[t], red[t + s]); __syncthreads(); }
    mx = red[0]; __syncthreads();
    float sum = 0.f;
#pragma unroll
    for (int i = 0; i < 4; i++) {
        const int j = t + i * 256;
        if (j < O_) sum += expf(v[i] - mx);
    }
    red[t] = sum; __syncthreads();
    for (int s = 128; s > 0; s >>= 1) { if (t < s) red[t] += red[t + s]; __syncthreads(); }
    const float lse = mx + logf(red[0]);
#pragma unroll
    for (int i = 0; i < 4; i++) {
        const int j = t + i * 256;
        if (j < O_) p[j] = v[i] - lse;
    }
}

// ---------------- launch ----------------
extern "C" void kernel_launch(void* const* d_in, const int* in_sizes, int n_in,
                              void* d_out, int out_size) {
    const float* x  = (const float*)d_in[0];
    const float* Wh = (const float*)d_in[1];
    const float* Wz = (const float*)d_in[2];
    const float* Wr = (const float*)d_in[3];
    const float* Uh = (const float*)d_in[4];
    const float* Uz = (const float*)d_in[5];
    const float* Ur = (const float*)d_in[6];
    const float* gh = (const float*)d_in[7];
    const float* bh = (const float*)d_in[8];
    const float* gz = (const float*)d_in[9];
    const float* bz = (const float*)d_in[10];
    const float* gr = (const float*)d_in[11];
    const float* br = (const float*)d_in[12];
    const float* Wf = (const float*)d_in[13];
    const float* gf = (const float*)d_in[14];
    const float* bf = (const float*)d_in[15];
    float* out = (float*)d_out;

    float *pY, *pH, *p1s, *p1q, *p2s, *p2q, *pA2, *pC2;
    cudaGetSymbolAddress((void**)&pY,  g_Y);
    cudaGetSymbolAddress((void**)&pH,  g_Hst);
    cudaGetSymbolAddress((void**)&p1s, g_p1s);
    cudaGetSymbolAddress((void**)&p1q, g_p1q);
    cudaGetSymbolAddress((void**)&p2s, g_p2s);
    cudaGetSymbolAddress((void**)&p2q, g_p2q);
    cudaGetSymbolAddress((void**)&pA2, g_A2);
    cudaGetSymbolAddress((void**)&pC2, g_C2);

    cudaFuncSetAttribute(scan9_kernel, cudaFuncAttributeMaxDynamicSharedMemorySize,
                         SMF_TOT * (int)sizeof(float));

    // 0) gate projections straight from Wh/Wz/Wr
    sgemm_gate<<<dim3(H3_ / GBN, SB_ / GBM), 256>>>(x, Wh, Wz, Wr, pY);

    // 1) BN partial stats
    colstat_stage1<<<dim3(6, 64), 256>>>(pY, H3_, p1s, p1q);

    // 2) stats finalize + BN fold + transpose -> YT
    transpose_fold2<<<dim3(48, 1000), 256>>>(gh, bh, gz, bz, gr, br);

    // 3) persistent recurrent scan
    scan9_kernel<<<128, 512, SMF_TOT * sizeof(float)>>>(Uh, Uz, Ur);

    // 4) final projection into d_out
    sgemm_kernel<<<dim3((O_ + GBN - 1) / GBN, SB_ / GBM), 256>>>(pH, Wf, out, SB_, O_, H_, O_);

    // 5-6) output BN stats
    colstat_stage1<<<dim3(4, 64), 256>>>(out, O_, p2s, p2q);
    colstat_stage2<<<4, 256>>>(p2s, p2q, O_, gf, bf, pA2, pC2);

    // 7) BN-apply + log_softmax in place
    logsoftmax_kernel<<<SB_, 256>>>(out);
}

// round 12
// speedup vs baseline: 1.7599x; 1.0120x over previous
#include <cuda_runtime.h>
#include <math.h>

#define S_   1000
#define B_   64
#define D_   440
#define H_   512
#define O_   1000
#define SB_  64000
#define H3_  1536

typedef unsigned long long ull;

// ---------------- f32x2 packed helpers ----------------
__device__ __forceinline__ ull pk2(float x, float y) {
    ull r; asm("mov.b64 %0, {%1,%2};" : "=l"(r) : "f"(x), "f"(y)); return r;
}
__device__ __forceinline__ void upk2(ull v, float& x, float& y) {
    asm("mov.b64 {%0,%1}, %2;" : "=f"(x), "=f"(y) : "l"(v));
}
__device__ __forceinline__ ull ffma2(ull a, ull b, ull c) {
    ull d; asm("fma.rn.f32x2 %0, %1, %2, %3;" : "=l"(d) : "l"(a), "l"(b), "l"(c)); return d;
}

// ---------------- scratch ----------------
__device__ __align__(16) float g_YT[(size_t)S_ * H3_ * B_];  // [t][col][b], RAW (fold in scan)
__device__ __align__(16) float g_Hst[(size_t)SB_ * H_];
__device__ __align__(16) float g_hT[2][H_ * B_];             // [buf][k*64 + b]
__device__ __align__(16) float g_rhT[H_ * B_];
__device__ __align__(16) float g_zT[H_ * B_];
__device__ float g_p1s[H3_ * 50], g_p1q[H3_ * 50];           // [col*50 + chunk]
__device__ float g_A1[H3_], g_C1[H3_];
__device__ float g_p2s[64 * O_], g_p2q[64 * O_];             // [col*64 + chunk]
__device__ float g_A2[O_], g_C2[O_];
__device__ __align__(128) unsigned g_cnt2[64];               // [0]=bh0, [32]=bh1

// ---------------- fp32 SGEMM (generic): C[M,N] = A[M,K] * Bw[N,K]^T ----------------
#define GBM 128
#define GBN 64
#define GBK 8
__global__ __launch_bounds__(256) void sgemm_kernel(
    const float* __restrict__ A, const float* __restrict__ Bw, float* __restrict__ C,
    int M, int N, int K, int ldc) {
    __shared__ float As[2][GBK][GBM + 4];
    __shared__ float Bs[2][GBK][GBN + 4];
    const int bm = blockIdx.y * GBM;
    const int bn = blockIdx.x * GBN;
    const int t  = threadIdx.x;
    const int tx = t & 15;
    const int ty = t >> 4;
    const int lam = t >> 1, lak = (t & 1) * 4;
    const int lbn = (t & 127) >> 1, lbk = (t & 1) * 4;
    const bool bload = t < 128;

    ull acc2[4][4];
#pragma unroll
    for (int p = 0; p < 4; p++)
#pragma unroll
        for (int j = 0; j < 4; j++) acc2[p][j] = 0ull;

    const int nt = K / GBK;
    float4 va, vb;
    va = *(const float4*)(A + (size_t)(bm + lam) * K + lak);
    vb = make_float4(0.f, 0.f, 0.f, 0.f);
    if (bload && (bn + lbn) < N) vb = *(const float4*)(Bw + (size_t)(bn + lbn) * K + lbk);
    As[0][lak + 0][lam] = va.x; As[0][lak + 1][lam] = va.y;
    As[0][lak + 2][lam] = va.z; As[0][lak + 3][lam] = va.w;
    if (bload) {
        Bs[0][lbk + 0][lbn] = vb.x; Bs[0][lbk + 1][lbn] = vb.y;
        Bs[0][lbk + 2][lbn] = vb.z; Bs[0][lbk + 3][lbn] = vb.w;
    }
    __syncthreads();

    for (int kt = 0; kt < nt; kt++) {
        const int cur = kt & 1;
        const bool has = (kt + 1) < nt;
        if (has) {
            const int k0 = (kt + 1) * GBK;
            va = *(const float4*)(A + (size_t)(bm + lam) * K + k0 + lak);
            vb = make_float4(0.f, 0.f, 0.f, 0.f);
            if (bload && (bn + lbn) < N)
                vb = *(const float4*)(Bw + (size_t)(bn + lbn) * K + k0 + lbk);
        }
#pragma unroll
        for (int k = 0; k < GBK; k++) {
            ull a2[4], bb[4];
#pragma unroll
            for (int p = 0; p < 4; p++)
                a2[p] = *(const ull*)&As[cur][k][ty * 8 + 2 * p];
#pragma unroll
            for (int j = 0; j < 4; j++) {
                const float bs = Bs[cur][k][tx * 4 + j];
                bb[j] = pk2(bs, bs);
            }
#pragma unroll
            for (int p = 0; p < 4; p++)
#pragma unroll
                for (int j = 0; j < 4; j++)
                    acc2[p][j] = ffma2(a2[p], bb[j], acc2[p][j]);
        }
        if (has) {
            const int nb = cur ^ 1;
            As[nb][lak + 0][lam] = va.x; As[nb][lak + 1][lam] = va.y;
            As[nb][lak + 2][lam] = va.z; As[nb][lak + 3][lam] = va.w;
            if (bload) {
                Bs[nb][lbk + 0][lbn] = vb.x; Bs[nb][lbk + 1][lbn] = vb.y;
                Bs[nb][lbk + 2][lbn] = vb.z; Bs[nb][lbk + 3][lbn] = vb.w;
            }
        }
        __syncthreads();
    }

#pragma unroll
    for (int p = 0; p < 4; p++) {
        const size_t m0 = (size_t)(bm + ty * 8 + 2 * p);
#pragma unroll
        for (int j = 0; j < 4; j++) {
            const int n = bn + tx * 4 + j;
            if (n < N) {
                float lo, hi;
                upk2(acc2[p][j], lo, hi);
                C[m0 * ldc + n] = lo;
                C[(m0 + 1) * ldc + n] = hi;
            }
        }
    }
}

// ---------------- gate SGEMM -> writes YT[t][col][b] directly (raw, unfolded) ----------------
__global__ __launch_bounds__(256) void sgemm_gateT(
    const float* __restrict__ A, const float* __restrict__ Wh,
    const float* __restrict__ Wz, const float* __restrict__ Wr) {
    const int K = D_;
    __shared__ float As[2][GBK][GBM + 4];
    __shared__ float Bs[2][GBK][GBN + 4];
    const int bm = blockIdx.y * GBM;
    const int bn = blockIdx.x * GBN;
    const int t  = threadIdx.x;
    const int tx = t & 15;
    const int ty = t >> 4;
    const int lam = t >> 1, lak = (t & 1) * 4;
    const int lbn = (t & 127) >> 1, lbk = (t & 1) * 4;
    const bool bload = t < 128;

    const float* brow = 0;
    if (bload) {
        const int r = bn + lbn;
        brow = (r < 512) ? (Wh + (size_t)r * K)
             : (r < 1024) ? (Wz + (size_t)(r - 512) * K)
                          : (Wr + (size_t)(r - 1024) * K);
    }

    ull acc2[4][4];
#pragma unroll
    for (int p = 0; p < 4; p++)
#pragma unroll
        for (int j = 0; j < 4; j++) acc2[p][j] = 0ull;

    const int nt = K / GBK;
    float4 va, vb;
    va = *(const float4*)(A + (size_t)(bm + lam) * K + lak);
    vb = make_float4(0.f, 0.f, 0.f, 0.f);
    if (bload) vb = *(const float4*)(brow + lbk);
    As[0][lak + 0][lam] = va.x; As[0][lak + 1][lam] = va.y;
    As[0][lak + 2][lam] = va.z; As[0][lak + 3][lam] = va.w;
    if (bload) {
        Bs[0][lbk + 0][lbn] = vb.x; Bs[0][lbk + 1][lbn] = vb.y;
        Bs[0][lbk + 2][lbn] = vb.z; Bs[0][lbk + 3][lbn] = vb.w;
    }
    __syncthreads();

    for (int kt = 0; kt < nt; kt++) {
        const int cur = kt & 1;
        const bool has = (kt + 1) < nt;
        if (has) {
            const int k0 = (kt + 1) * GBK;
            va = *(const float4*)(A + (size_t)(bm + lam) * K + k0 + lak);
            if (bload) vb = *(const float4*)(brow + k0 + lbk);
        }
#pragma unroll
        for (int k = 0; k < GBK; k++) {
            ull a2[4], bb[4];
#pragma unroll
            for (int p = 0; p < 4; p++)
                a2[p] = *(const ull*)&As[cur][k][ty * 8 + 2 * p];
#pragma unroll
            for (int j = 0; j < 4; j++) {
                const float bs = Bs[cur][k][tx * 4 + j];
                bb[j] = pk2(bs, bs);
            }
#pragma unroll
            for (int p = 0; p < 4; p++)
#pragma unroll
                for (int j = 0; j < 4; j++)
                    acc2[p][j] = ffma2(a2[p], bb[j], acc2[p][j]);
        }
        if (has) {
            const int nb = cur ^ 1;
            As[nb][lak + 0][lam] = va.x; As[nb][lak + 1][lam] = va.y;
            As[nb][lak + 2][lam] = va.z; As[nb][lak + 3][lam] = va.w;
            if (bload) {
                Bs[nb][lbk + 0][lbn] = vb.x; Bs[nb][lbk + 1][lbn] = vb.y;
                Bs[nb][lbk + 2][lbn] = vb.z; Bs[nb][lbk + 3][lbn] = vb.w;
            }
        }
        __syncthreads();
    }

    // epilogue: rows m = t_step*64 + b  ->  YT[(t_step*H3 + col)*64 + b], float2 per m-pair
#pragma unroll
    for (int p = 0; p < 4; p++) {
        const int m0 = bm + ty * 8 + 2 * p;
        const int ts = m0 >> 6, b0 = m0 & 63;
#pragma unroll
        for (int j = 0; j < 4; j++) {
            const int col = bn + tx * 4 + j;
            float lo, hi;
            upk2(acc2[p][j], lo, hi);
            *(float2*)&g_YT[((size_t)ts * H3_ + col) * B_ + b0] = make_float2(lo, hi);
        }
    }
}

// ---------------- column stats over YT: sum over (t,b) per col; 50 t-chunks ----------------
__global__ void colstat_yt() {
    const int col = blockIdx.x * 256 + threadIdx.x;   // < 1536
    const int chunk = blockIdx.y;                      // 0..49, 20 t each
    float s = 0.f, q = 0.f;
    for (int t = chunk * 20; t < chunk * 20 + 20; t++) {
        const float4* p4 = (const float4*)&g_YT[((size_t)t * H3_ + col) * B_];
#pragma unroll
        for (int b = 0; b < 16; b++) {
            const float4 v = p4[b];
            s += v.x + v.y + v.z + v.w;
            q = fmaf(v.x, v.x, q); q = fmaf(v.y, v.y, q);
            q = fmaf(v.z, v.z, q); q = fmaf(v.w, v.w, q);
        }
    }
    g_p1s[col * 50 + chunk] = s;
    g_p1q[col * 50 + chunk] = q;
}

__global__ void fold1(const float* __restrict__ gh, const float* __restrict__ bhp,
                      const float* __restrict__ gz, const float* __restrict__ bz,
                      const float* __restrict__ gr, const float* __restrict__ br) {
    const int col = blockIdx.x * 256 + threadIdx.x;   // < 1536
    float s = 0.f, q = 0.f;
    for (int c = 0; c < 50; c++) { s += g_p1s[col * 50 + c]; q += g_p1q[col * 50 + c]; }
    const float m = s * (1.f / 64000.f);
    const float v = q * (1.f / 64000.f) - m * m;
    float gamma, beta;
    if (col < 512)       { gamma = gh[col];        beta = bhp[col]; }
    else if (col < 1024) { gamma = gz[col - 512];  beta = bz[col - 512]; }
    else                 { gamma = gr[col - 1024]; beta = br[col - 1024]; }
    const float a = gamma * rsqrtf(v + 1e-5f);
    g_A1[col] = a;
    g_C1[col] = beta - m * a;
}

// ---------------- deterministic column stats (row-major input, for output BN) ----------------
__global__ void colstat_stage1(const float* __restrict__ X, int ncols,
                               float* __restrict__ ps, float* __restrict__ pq) {
    const int col = blockIdx.x * 256 + threadIdx.x;
    if (col >= ncols) return;
    const int chunk = blockIdx.y;
    const size_t base = (size_t)chunk * 1000 * ncols + col;
    float s = 0.f, q = 0.f;
    for (int r = 0; r < 1000; r++) {
        const float v = X[base + (size_t)r * ncols];
        s += v; q = fmaf(v, v, q);
    }
    ps[col * 64 + chunk] = s;
    pq[col * 64 + chunk] = q;
}

__global__ void colstat_stage2(const float* __restrict__ ps, const float* __restrict__ pq,
                               int ncols, const float* __restrict__ gamma,
                               const float* __restrict__ beta,
                               float* __restrict__ Aout, float* __restrict__ Cout) {
    const int col = blockIdx.x * 256 + threadIdx.x;
    if (col >= ncols) return;
    float s = 0.f, q = 0.f;
    for (int c = 0; c < 64; c++) { s += ps[col * 64 + c]; q += pq[col * 64 + c]; }
    const float m = s * (1.f / 64000.f);
    const float v = q * (1.f / 64000.f) - m * m;
    const float a = gamma[col] * rsqrtf(v + 1e-5f);
    Aout[col] = a;
    Cout[col] = beta[col] - m * a;
}

// ---------------- persistent scan v9b: R10 scan + in-register BN fold ----------------
#define SMF_U1 0
#define SMF_U2 8192
#define SMF_P1 12288
#define SMF_P2 21504
#define SMF_T  26624
#define SMF_TOT 26880

__global__ __launch_bounds__(512, 1) void scan9b_kernel(
    const float* __restrict__ Uh, const float* __restrict__ Uz,
    const float* __restrict__ Ur) {
    extern __shared__ float sm[];
    float* sU1 = sm + SMF_U1;
    float* sU2 = sm + SMF_U2;
    float* sP1 = sm + SMF_P1;
    float* sP2 = sm + SMF_P2;
    float* sT  = sm + SMF_T;
    __shared__ unsigned s_base;

    const int cta  = blockIdx.x;
    const int tid  = threadIdx.x;
    const int w    = tid >> 5;
    const int lane = tid & 31;
    const bool isR = cta >= 64;
    const int grp  = isR ? (cta - 64) : cta;
    const int jt1  = grp >> 1;
    const int bh   = cta & 1;
    const int jt2  = cta >> 1;
    const int bglob = bh * 32 + lane;

    unsigned* pc;
    asm("cvta.global.u64 %0, %1;" : "=l"(pc) : "l"(&g_cnt2[0]));
    pc += bh * 32;

    if (tid == 0) {
        unsigned b;
        asm volatile("ld.relaxed.gpu.global.u32 %0, [%1];" : "=r"(b) : "l"(pc));
        s_base = b;
    }

    {
        const float* U1 = isR ? Ur : Uz;
        for (int i = tid; i < 8192; i += 512) {
            const int k = i >> 4, jj = i & 15;
            sU1[i] = U1[(jt1 * 16 + jj) * H_ + k];
        }
        for (int i = tid; i < 4096; i += 512) {
            const int k = i >> 3, jj = i & 7;
            sU2[i] = Uh[(jt2 * 8 + jj) * H_ + k];
        }
    }
    if (tid < 256) g_hT[0][cta * 256 + tid] = 0.f;
    __syncthreads();
    const unsigned base = s_base;

    auto arrive = [&]() {
        __syncthreads();
        if (tid == 0)
            asm volatile("red.release.gpu.global.add.u32 [%0], 1;" :: "l"(pc) : "memory");
    };
    auto wait = [&](unsigned k) {
        if (tid == 0) {
            const unsigned tgt = 64u * k;
            unsigned v;
            do {
                asm volatile("ld.acquire.gpu.global.u32 %0, [%1];"
                             : "=r"(v) : "l"(pc) : "memory");
            } while ((v - base) < tgt);
        }
        __syncthreads();
    };

    const int rj1 = tid >> 5;
    const int jglob1 = jt1 * 16 + rj1;
    const int colg = (isR ? 1024 : 512) + jglob1;
    const size_t yoff1 = (size_t)colg * B_ + bglob;
    const int rj2 = (tid >> 5) & 7;
    const int jglob2 = jt2 * 8 + rj2;
    const size_t yoff2 = (size_t)jglob2 * B_ + bglob;
    const int kw = w * 32;

    // per-thread BN fold coefficients (fixed columns)
    const float a1g = g_A1[colg], c1g = g_C1[colg];
    float a1h = 0.f, c1h = 0.f;
    if (tid < 256) { a1h = g_A1[jglob2]; c1h = g_C1[jglob2]; }

    arrive(); wait(1u);

    float yg = __ldcg(g_YT + yoff1);

    for (int t = 0; t < S_; t++) {
        const float* hbuf = g_hT[t & 1];
        float* hnext = g_hT[(t + 1) & 1];
        const float* YTt = g_YT + (size_t)t * (H3_ * B_);

        const float hpre1 = isR ? __ldcg(hbuf + jglob1 * 64 + bglob) : 0.f;

        // ---- phase1 gemm: 32 front-batched LDG, LDS.128 U, FFMA2 sweep ----
        {
            float hr[32];
#pragma unroll
            for (int kk = 0; kk < 32; kk++)
                hr[kk] = __ldcg(hbuf + (kw + kk) * 64 + bglob);
            ull acc2[8];
#pragma unroll
            for (int p = 0; p < 8; p++) acc2[p] = 0ull;
#pragma unroll
            for (int kk = 0; kk < 32; kk++) {
                const ull hh = pk2(hr[kk], hr[kk]);
                const float* urow = &sU1[(kw + kk) * 16];
                const ulonglong2 u01 = *(const ulonglong2*)(urow);
                const ulonglong2 u23 = *(const ulonglong2*)(urow + 4);
                const ulonglong2 u45 = *(const ulonglong2*)(urow + 8);
                const ulonglong2 u67 = *(const ulonglong2*)(urow + 12);
                acc2[0] = ffma2(hh, u01.x, acc2[0]);
                acc2[1] = ffma2(hh, u01.y, acc2[1]);
                acc2[2] = ffma2(hh, u23.x, acc2[2]);
                acc2[3] = ffma2(hh, u23.y, acc2[3]);
                acc2[4] = ffma2(hh, u45.x, acc2[4]);
                acc2[5] = ffma2(hh, u45.y, acc2[5]);
                acc2[6] = ffma2(hh, u67.x, acc2[6]);
                acc2[7] = ffma2(hh, u67.y, acc2[7]);
            }
            ull* dst = (ull*)&sP1[w * 576 + lane * 18];
#pragma unroll
            for (int p = 0; p < 8; p++) dst[p] = acc2[p];
        }
        __syncthreads();

        // ---- phase1 reduce + BN fold + activation -> z or rh ----
        {
            float pre = 0.f;
#pragma unroll
            for (int q = 0; q < 16; q++) pre += sP1[q * 576 + (tid & 31) * 18 + rj1];
            const float gate = 1.f / (1.f + __expf(-(fmaf(yg, a1g, c1g) + pre)));
            if (isR) g_rhT[jglob1 * 64 + bglob] = gate * hpre1;
            else     g_zT[jglob1 * 64 + bglob] = gate;
        }
        arrive();

        float yh = 0.f, hp2 = 0.f;
        if (tid < 256) {
            yh  = __ldcg(YTt + yoff2);
            hp2 = __ldcg(hbuf + jglob2 * 64 + bglob);
        }
        wait(2u + 2u * (unsigned)t);

        float zv = 0.f;
        if (tid < 256) zv = __ldcg(g_zT + jglob2 * 64 + bglob);

        // ---- phase2 gemm ----
        {
            float rr[32];
#pragma unroll
            for (int kk = 0; kk < 32; kk++)
                rr[kk] = __ldcg(g_rhT + (kw + kk) * 64 + bglob);
            ull acc2[4];
#pragma unroll
            for (int p = 0; p < 4; p++) acc2[p] = 0ull;
#pragma unroll
            for (int kk = 0; kk < 32; kk++) {
                const ull rv = pk2(rr[kk], rr[kk]);
                const float* urow = &sU2[(kw + kk) * 8];
                const ulonglong2 u01 = *(const ulonglong2*)(urow);
                const ulonglong2 u23 = *(const ulonglong2*)(urow + 4);
                acc2[0] = ffma2(rv, u01.x, acc2[0]);
                acc2[1] = ffma2(rv, u01.y, acc2[1]);
                acc2[2] = ffma2(rv, u23.x, acc2[2]);
                acc2[3] = ffma2(rv, u23.y, acc2[3]);
            }
            ull* dst = (ull*)&sP2[w * 320 + lane * 10];
#pragma unroll
            for (int p = 0; p < 4; p++) dst[p] = acc2[p];
        }
        __syncthreads();

        // ---- phase2 reduce + BN fold + h update ----
        if (tid < 256) {
            float pre = 0.f;
#pragma unroll
            for (int q = 0; q < 16; q++) pre += sP2[q * 320 + (tid & 31) * 10 + rj2];
            const float hc = tanhf(fmaf(yh, a1h, c1h) + pre);
            const float hn = fmaf(zv, hp2 - hc, hc);
            hnext[jglob2 * 64 + bglob] = hn;
            sT[rj2 * 32 + (tid & 31)] = hn;
        }
        arrive();

        if (tid < 32) {
            const size_t row = (size_t)t * B_ + bh * 32 + tid;
            const float4 v0 = make_float4(sT[0 * 32 + tid], sT[1 * 32 + tid],
                                          sT[2 * 32 + tid], sT[3 * 32 + tid]);
            const float4 v1 = make_float4(sT[4 * 32 + tid], sT[5 * 32 + tid],
                                          sT[6 * 32 + tid], sT[7 * 32 + tid]);
            *(float4*)(g_Hst + row * H_ + jt2 * 8)     = v0;
            *(float4*)(g_Hst + row * H_ + jt2 * 8 + 4) = v1;
        }
        {
            const int tn = (t + 1 < S_) ? (t + 1) : t;
            yg = __ldcg(g_YT + (size_t)tn * (H3_ * B_) + yoff1);
        }
        wait(3u + 2u * (unsigned)t);
    }
}

// ---------------- row log_softmax, single global read, folded BN ----------------
__global__ __launch_bounds__(256) void logsoftmax_kernel(float* __restrict__ C) {
    const int row = blockIdx.x;
    float* p = C + (size_t)row * O_;
    __shared__ float red[256];
    const int t = threadIdx.x;
    float v[4];
    float mx = -3.4e38f;
#pragma unroll
    for (int i = 0; i < 4; i++) {
        const int j = t + i * 256;
        if (j < O_) {
            v[i] = p[j] * g_A2[j] + g_C2[j];
            mx = fmaxf(mx, v[i]);
        } else v[i] = -3.4e38f;
    }
    red[t] = mx; __syncthreads();
    for (int s = 128; s > 0; s >>= 1) { if (t < s) red[t] = fmaxf(red[t], red[t + s]); __syncthreads(); }
    mx = red[0]; __syncthreads();
    float sum = 0.f;
#pragma unroll
    for (int i = 0; i < 4; i++) {
        const int j = t + i * 256;
        if (j < O_) sum += expf(v[i] - mx);
    }
    red[t] = sum; __syncthreads();
    for (int s = 128; s > 0; s >>= 1) { if (t < s) red[t] += red[t + s]; __syncthreads(); }
    const float lse = mx + logf(red[0]);
#pragma unroll
    for (int i = 0; i < 4; i++) {
        const int j = t + i * 256;
        if (j < O_) p[j] = v[i] - lse;
    }
}

// ---------------- launch ----------------
extern "C" void kernel_launch(void* const* d_in, const int* in_sizes, int n_in,
                              void* d_out, int out_size) {
    const float* x  = (const float*)d_in[0];
    const float* Wh = (const float*)d_in[1];
    const float* Wz = (const float*)d_in[2];
    const float* Wr = (const float*)d_in[3];
    const float* Uh = (const float*)d_in[4];
    const float* Uz = (const float*)d_in[5];
    const float* Ur = (const float*)d_in[6];
    const float* gh = (const float*)d_in[7];
    const float* bh = (const float*)d_in[8];
    const float* gz = (const float*)d_in[9];
    const float* bz = (const float*)d_in[10];
    const float* gr = (const float*)d_in[11];
    const float* br = (const float*)d_in[12];
    const float* Wf = (const float*)d_in[13];
    const float* gf = (const float*)d_in[14];
    const float* bf = (const float*)d_in[15];
    float* out = (float*)d_out;

    float *pH, *p2s, *p2q, *pA2, *pC2;
    cudaGetSymbolAddress((void**)&pH,  g_Hst);
    cudaGetSymbolAddress((void**)&p2s, g_p2s);
    cudaGetSymbolAddress((void**)&p2q, g_p2q);
    cudaGetSymbolAddress((void**)&pA2, g_A2);
    cudaGetSymbolAddress((void**)&pC2, g_C2);

    cudaFuncSetAttribute(scan9b_kernel, cudaFuncAttributeMaxDynamicSharedMemorySize,
                         SMF_TOT * (int)sizeof(float));

    // 0) gate projections -> YT[t][col][b] (raw)
    sgemm_gateT<<<dim3(H3_ / GBN, SB_ / GBM), 256>>>(x, Wh, Wz, Wr);

    // 1) BN stats over YT + fold coefficients
    colstat_yt<<<dim3(6, 50), 256>>>();
    fold1<<<6, 256>>>(gh, bh, gz, bz, gr, br);

    // 2) persistent recurrent scan (applies fold in registers)
    scan9b_kernel<<<128, 512, SMF_TOT * sizeof(float)>>>(Uh, Uz, Ur);

    // 3) final projection into d_out
    sgemm_kernel<<<dim3((O_ + GBN - 1) / GBN, SB_ / GBM), 256>>>(pH, Wf, out, SB_, O_, H_, O_);

    // 4) output BN stats
    colstat_stage1<<<dim3(4, 64), 256>>>(out, O_, p2s, p2q);
    colstat_stage2<<<4, 256>>>(p2s, p2q, O_, gf, bf, pA2, pC2);

    // 5) BN-apply + log_softmax in place
    logsoftmax_kernel<<<SB_, 256>>>(out);
}

// round 13
// speedup vs baseline: 2.0242x; 1.1502x over previous
#include <cuda_runtime.h>
#include <cuda_bf16.h>
#include <math.h>
#include <stdint.h>

#define S_   1000
#define B_   64
#define D_   440
#define H_   512
#define O_   1000
#define SB_  64000
#define H3_  1536

typedef unsigned long long ull;

// ---------------- f32x2 packed helpers (scan) ----------------
__device__ __forceinline__ ull pk2(float x, float y) {
    ull r; asm("mov.b64 %0, {%1,%2};" : "=l"(r) : "f"(x), "f"(y)); return r;
}
__device__ __forceinline__ ull ffma2(ull a, ull b, ull c) {
    ull d; asm("fma.rn.f32x2 %0, %1, %2, %3;" : "=l"(d) : "l"(a), "l"(b), "l"(c)); return d;
}

// ---------------- scratch ----------------
__device__ __align__(16) float g_YT[(size_t)S_ * H3_ * B_];  // [t][col][b], RAW
__device__ __align__(16) float g_Hst[(size_t)SB_ * H_];
__device__ __align__(16) float g_hT[2][H_ * B_];
__device__ __align__(16) float g_rhT[H_ * B_];
__device__ __align__(16) float g_zT[H_ * B_];
__device__ float g_p1s[H3_ * 50], g_p1q[H3_ * 50];
__device__ float g_A1[H3_], g_C1[H3_];
__device__ float g_p2s[64 * O_], g_p2q[64 * O_];
__device__ float g_A2[O_], g_C2[O_];
__device__ __align__(128) unsigned g_cnt2[64];
// bf16 split arrays
__device__ __align__(16) __nv_bfloat16 g_xh[(size_t)SB_ * 448];
__device__ __align__(16) __nv_bfloat16 g_xl[(size_t)SB_ * 448];
__device__ __align__(16) __nv_bfloat16 g_gwh[H3_ * 448];
__device__ __align__(16) __nv_bfloat16 g_gwl[H3_ * 448];
__device__ __align__(16) __nv_bfloat16 g_hh[(size_t)SB_ * H_];
__device__ __align__(16) __nv_bfloat16 g_hl[(size_t)SB_ * H_];
__device__ __align__(16) __nv_bfloat16 g_fh[1024 * H_];
__device__ __align__(16) __nv_bfloat16 g_fl[1024 * H_];

// ---------------- split kernels ----------------
__global__ void split_pad(const float* __restrict__ src, __nv_bfloat16* __restrict__ dh,
                          __nv_bfloat16* __restrict__ dl, int Rreal, int C, int Cpad) {
    const size_t i = (size_t)blockIdx.x * 256 + threadIdx.x;
    const int r = (int)(i / Cpad), c = (int)(i % Cpad);
    float v = 0.f;
    if (r < Rreal && c < C) v = src[(size_t)r * C + c];
    const __nv_bfloat16 hi = __float2bfloat16(v);
    const __nv_bfloat16 lo = __float2bfloat16(v - __bfloat162float(hi));
    dh[i] = hi; dl[i] = lo;
}

__global__ void split_gw(const float* __restrict__ Wh, const float* __restrict__ Wz,
                         const float* __restrict__ Wr) {
    const size_t i = (size_t)blockIdx.x * 256 + threadIdx.x;   // < 1536*448
    const int r = (int)(i / 448), c = (int)(i % 448);
    float v = 0.f;
    if (c < D_) {
        v = (r < 512) ? Wh[r * D_ + c] : (r < 1024) ? Wz[(r - 512) * D_ + c]
                                                    : Wr[(r - 1024) * D_ + c];
    }
    const __nv_bfloat16 hi = __float2bfloat16(v);
    const __nv_bfloat16 lo = __float2bfloat16(v - __bfloat162float(hi));
    g_gwh[i] = hi; g_gwl[i] = lo;
}

// ---------------- mma.sync bf16 split GEMM: C[M,N] = A[M,Kp]·B[N,Kp]^T ----------------
__device__ __forceinline__ void mma16816(float* d, const uint32_t* a, const uint32_t* b) {
    asm volatile("mma.sync.aligned.m16n8k16.row.col.f32.bf16.bf16.f32 "
                 "{%0,%1,%2,%3}, {%4,%5,%6,%7}, {%8,%9}, {%0,%1,%2,%3};"
                 : "+f"(d[0]), "+f"(d[1]), "+f"(d[2]), "+f"(d[3])
                 : "r"(a[0]), "r"(a[1]), "r"(a[2]), "r"(a[3]), "r"(b[0]), "r"(b[1]));
}

// smem: 2 buffers x {Ah, Al, Bh, Bl}, each 128 rows x 40 bf16 (pad 32->40, conflict-free)
#define MMS_ARR 5120                 // bf16 units per array
#define MMS_TOT (8 * MMS_ARR * 2)    // bytes = 81920

__global__ __launch_bounds__(256, 1) void gemm_mma(
    const __nv_bfloat16* __restrict__ Ah, const __nv_bfloat16* __restrict__ Al,
    const __nv_bfloat16* __restrict__ Bh, const __nv_bfloat16* __restrict__ Bl,
    float* __restrict__ C, int nk, int kstr, int ldc, int nreal, int toYT) {
    extern __shared__ __align__(16) unsigned short smu[];
    const int tid = threadIdx.x, w = tid >> 5, l = tid & 31;
    const int bm = blockIdx.y * 128, bn = blockIdx.x * 128;
    const int wm = (w & 1) * 64, wn = (w >> 1) * 32;

    unsigned short* sAr[2][2];
    unsigned short* sBr[2][2];
#pragma unroll
    for (int bf = 0; bf < 2; bf++)
#pragma unroll
        for (int hl = 0; hl < 2; hl++) {
            sAr[bf][hl] = smu + (bf * 4 + hl) * MMS_ARR;
            sBr[bf][hl] = smu + (bf * 4 + 2 + hl) * MMS_ARR;
        }

    float d[4][4][4];
#pragma unroll
    for (int mt = 0; mt < 4; mt++)
#pragma unroll
        for (int nt = 0; nt < 4; nt++)
#pragma unroll
            for (int q = 0; q < 4; q++) d[mt][nt][q] = 0.f;

    uint4 pf[8];
    const int lrow0 = tid >> 2, lu0 = (tid & 3);           // entry 0
    const int lrow1 = (tid + 256) >> 2, lu1 = lu0;         // entry 1 (same u pattern)

    auto gload = [&](int ch) {
        const int k0 = ch * 32;
        pf[0] = *(const uint4*)(Ah + (size_t)(bm + lrow0) * kstr + k0 + lu0 * 8);
        pf[1] = *(const uint4*)(Ah + (size_t)(bm + lrow1) * kstr + k0 + lu1 * 8);
        pf[2] = *(const uint4*)(Al + (size_t)(bm + lrow0) * kstr + k0 + lu0 * 8);
        pf[3] = *(const uint4*)(Al + (size_t)(bm + lrow1) * kstr + k0 + lu1 * 8);
        pf[4] = *(const uint4*)(Bh + (size_t)(bn + lrow0) * kstr + k0 + lu0 * 8);
        pf[5] = *(const uint4*)(Bh + (size_t)(bn + lrow1) * kstr + k0 + lu1 * 8);
        pf[6] = *(const uint4*)(Bl + (size_t)(bn + lrow0) * kstr + k0 + lu0 * 8);
        pf[7] = *(const uint4*)(Bl + (size_t)(bn + lrow1) * kstr + k0 + lu1 * 8);
    };
    auto sstore = [&](int bf) {
        *(uint4*)(sAr[bf][0] + lrow0 * 40 + lu0 * 8) = pf[0];
        *(uint4*)(sAr[bf][0] + lrow1 * 40 + lu1 * 8) = pf[1];
        *(uint4*)(sAr[bf][1] + lrow0 * 40 + lu0 * 8) = pf[2];
        *(uint4*)(sAr[bf][1] + lrow1 * 40 + lu1 * 8) = pf[3];
        *(uint4*)(sBr[bf][0] + lrow0 * 40 + lu0 * 8) = pf[4];
        *(uint4*)(sBr[bf][0] + lrow1 * 40 + lu1 * 8) = pf[5];
        *(uint4*)(sBr[bf][1] + lrow0 * 40 + lu0 * 8) = pf[6];
        *(uint4*)(sBr[bf][1] + lrow1 * 40 + lu1 * 8) = pf[7];
    };

    gload(0); sstore(0); __syncthreads();

    for (int ch = 0; ch < nk; ch++) {
        const int bf = ch & 1;
        if (ch + 1 < nk) gload(ch + 1);
#pragma unroll
        for (int half = 0; half < 2; half++) {
            const int kb = half * 16;
            const int c0 = kb + (l & 3) * 2;
            uint32_t ah[4][4], al[4][4], bhf[4][2], blf[4][2];
#pragma unroll
            for (int mt = 0; mt < 4; mt++) {
                const int r = wm + mt * 16 + (l >> 2);
                const unsigned short* pH = sAr[bf][0];
                const unsigned short* pL = sAr[bf][1];
                ah[mt][0] = *(const uint32_t*)(pH + r * 40 + c0);
                ah[mt][1] = *(const uint32_t*)(pH + (r + 8) * 40 + c0);
                ah[mt][2] = *(const uint32_t*)(pH + r * 40 + c0 + 8);
                ah[mt][3] = *(const uint32_t*)(pH + (r + 8) * 40 + c0 + 8);
                al[mt][0] = *(const uint32_t*)(pL + r * 40 + c0);
                al[mt][1] = *(const uint32_t*)(pL + (r + 8) * 40 + c0);
                al[mt][2] = *(const uint32_t*)(pL + r * 40 + c0 + 8);
                al[mt][3] = *(const uint32_t*)(pL + (r + 8) * 40 + c0 + 8);
            }
#pragma unroll
            for (int nt = 0; nt < 4; nt++) {
                const int n = wn + nt * 8 + (l >> 2);
                const unsigned short* pH = sBr[bf][0];
                const unsigned short* pL = sBr[bf][1];
                bhf[nt][0] = *(const uint32_t*)(pH + n * 40 + c0);
                bhf[nt][1] = *(const uint32_t*)(pH + n * 40 + c0 + 8);
                blf[nt][0] = *(const uint32_t*)(pL + n * 40 + c0);
                blf[nt][1] = *(const uint32_t*)(pL + n * 40 + c0 + 8);
            }
#pragma unroll
            for (int mt = 0; mt < 4; mt++)
#pragma unroll
                for (int nt = 0; nt < 4; nt++) {
                    mma16816(d[mt][nt], ah[mt], bhf[nt]);
                    mma16816(d[mt][nt], ah[mt], blf[nt]);
                    mma16816(d[mt][nt], al[mt], bhf[nt]);
                }
        }
        if (ch + 1 < nk) sstore((ch + 1) & 1);
        __syncthreads();
    }

    // epilogue
    if (toYT) {
        const int ts = (bm >> 6) + (w & 1);
#pragma unroll
        for (int mt = 0; mt < 4; mt++) {
            const int b0 = mt * 16 + (l >> 2);
#pragma unroll
            for (int nt = 0; nt < 4; nt++) {
                const int col = bn + wn + nt * 8 + (l & 3) * 2;
                float* base = g_YT + ((size_t)ts * H3_ + col) * 64;
                base[b0]           = d[mt][nt][0];
                base[64 + b0]      = d[mt][nt][1];
                base[b0 + 8]       = d[mt][nt][2];
                base[64 + b0 + 8]  = d[mt][nt][3];
            }
        }
    } else {
#pragma unroll
        for (int mt = 0; mt < 4; mt++) {
            const int m = bm + wm + mt * 16 + (l >> 2);
#pragma unroll
            for (int nt = 0; nt < 4; nt++) {
                const int col = bn + wn + nt * 8 + (l & 3) * 2;
                if (col < nreal) {
                    *(float2*)(C + (size_t)m * ldc + col) =
                        make_float2(d[mt][nt][0], d[mt][nt][1]);
                    *(float2*)(C + (size_t)(m + 8) * ldc + col) =
                        make_float2(d[mt][nt][2], d[mt][nt][3]);
                }
            }
        }
    }
}

// ---------------- column stats over YT ----------------
__global__ void colstat_yt() {
    const int col = blockIdx.x * 256 + threadIdx.x;
    const int chunk = blockIdx.y;
    float s = 0.f, q = 0.f;
    for (int t = chunk * 20; t < chunk * 20 + 20; t++) {
        const float4* p4 = (const float4*)&g_YT[((size_t)t * H3_ + col) * B_];
#pragma unroll
        for (int b = 0; b < 16; b++) {
            const float4 v = p4[b];
            s += v.x + v.y + v.z + v.w;
            q = fmaf(v.x, v.x, q); q = fmaf(v.y, v.y, q);
            q = fmaf(v.z, v.z, q); q = fmaf(v.w, v.w, q);
        }
    }
    g_p1s[col * 50 + chunk] = s;
    g_p1q[col * 50 + chunk] = q;
}

__global__ void fold1(const float* __restrict__ gh, const float* __restrict__ bhp,
                      const float* __restrict__ gz, const float* __restrict__ bz,
                      const float* __restrict__ gr, const float* __restrict__ br) {
    const int col = blockIdx.x * 256 + threadIdx.x;
    float s = 0.f, q = 0.f;
    for (int c = 0; c < 50; c++) { s += g_p1s[col * 50 + c]; q += g_p1q[col * 50 + c]; }
    const float m = s * (1.f / 64000.f);
    const float v = q * (1.f / 64000.f) - m * m;
    float gamma, beta;
    if (col < 512)       { gamma = gh[col];        beta = bhp[col]; }
    else if (col < 1024) { gamma = gz[col - 512];  beta = bz[col - 512]; }
    else                 { gamma = gr[col - 1024]; beta = br[col - 1024]; }
    const float a = gamma * rsqrtf(v + 1e-5f);
    g_A1[col] = a;
    g_C1[col] = beta - m * a;
}

// ---------------- column stats (row-major, output BN) ----------------
__global__ void colstat_stage1(const float* __restrict__ X, int ncols,
                               float* __restrict__ ps, float* __restrict__ pq) {
    const int col = blockIdx.x * 256 + threadIdx.x;
    if (col >= ncols) return;
    const int chunk = blockIdx.y;
    const size_t base = (size_t)chunk * 1000 * ncols + col;
    float s = 0.f, q = 0.f;
    for (int r = 0; r < 1000; r++) {
        const float v = X[base + (size_t)r * ncols];
        s += v; q = fmaf(v, v, q);
    }
    ps[col * 64 + chunk] = s;
    pq[col * 64 + chunk] = q;
}

__global__ void colstat_stage2(const float* __restrict__ ps, const float* __restrict__ pq,
                               int ncols, const float* __restrict__ gamma,
                               const float* __restrict__ beta,
                               float* __restrict__ Aout, float* __restrict__ Cout) {
    const int col = blockIdx.x * 256 + threadIdx.x;
    if (col >= ncols) return;
    float s = 0.f, q = 0.f;
    for (int c = 0; c < 64; c++) { s += ps[col * 64 + c]; q += pq[col * 64 + c]; }
    const float m = s * (1.f / 64000.f);
    const float v = q * (1.f / 64000.f) - m * m;
    const float a = gamma[col] * rsqrtf(v + 1e-5f);
    Aout[col] = a;
    Cout[col] = beta[col] - m * a;
}

// ---------------- persistent scan v9b (identical to R12) ----------------
#define SMF_U1 0
#define SMF_U2 8192
#define SMF_P1 12288
#define SMF_P2 21504
#define SMF_T  26624
#define SMF_TOT 26880

__global__ __launch_bounds__(512, 1) void scan9b_kernel(
    const float* __restrict__ Uh, const float* __restrict__ Uz,
    const float* __restrict__ Ur) {
    extern __shared__ float sm[];
    float* sU1 = sm + SMF_U1;
    float* sU2 = sm + SMF_U2;
    float* sP1 = sm + SMF_P1;
    float* sP2 = sm + SMF_P2;
    float* sT  = sm + SMF_T;
    __shared__ unsigned s_base;

    const int cta  = blockIdx.x;
    const int tid  = threadIdx.x;
    const int w    = tid >> 5;
    const int lane = tid & 31;
    const bool isR = cta >= 64;
    const int grp  = isR ? (cta - 64) : cta;
    const int jt1  = grp >> 1;
    const int bh   = cta & 1;
    const int jt2  = cta >> 1;
    const int bglob = bh * 32 + lane;

    unsigned* pc;
    asm("cvta.global.u64 %0, %1;" : "=l"(pc) : "l"(&g_cnt2[0]));
    pc += bh * 32;

    if (tid == 0) {
        unsigned b;
        asm volatile("ld.relaxed.gpu.global.u32 %0, [%1];" : "=r"(b) : "l"(pc));
        s_base = b;
    }

    {
        const float* U1 = isR ? Ur : Uz;
        for (int i = tid; i < 8192; i += 512) {
            const int k = i >> 4, jj = i & 15;
            sU1[i] = U1[(jt1 * 16 + jj) * H_ + k];
        }
        for (int i = tid; i < 4096; i += 512) {
            const int k = i >> 3, jj = i & 7;
            sU2[i] = Uh[(jt2 * 8 + jj) * H_ + k];
        }
    }
    if (tid < 256) g_hT[0][cta * 256 + tid] = 0.f;
    __syncthreads();
    const unsigned base = s_base;

    auto arrive = [&]() {
        __syncthreads();
        if (tid == 0)
            asm volatile("red.release.gpu.global.add.u32 [%0], 1;" :: "l"(pc) : "memory");
    };
    auto wait = [&](unsigned k) {
        if (tid == 0) {
            const unsigned tgt = 64u * k;
            unsigned v;
            do {
                asm volatile("ld.acquire.gpu.global.u32 %0, [%1];"
                             : "=r"(v) : "l"(pc) : "memory");
            } while ((v - base) < tgt);
        }
        __syncthreads();
    };

    const int rj1 = tid >> 5;
    const int jglob1 = jt1 * 16 + rj1;
    const int colg = (isR ? 1024 : 512) + jglob1;
    const size_t yoff1 = (size_t)colg * B_ + bglob;
    const int rj2 = (tid >> 5) & 7;
    const int jglob2 = jt2 * 8 + rj2;
    const size_t yoff2 = (size_t)jglob2 * B_ + bglob;
    const int kw = w * 32;

    const float a1g = g_A1[colg], c1g = g_C1[colg];
    float a1h = 0.f, c1h = 0.f;
    if (tid < 256) { a1h = g_A1[jglob2]; c1h = g_C1[jglob2]; }

    arrive(); wait(1u);

    float yg = __ldcg(g_YT + yoff1);

    for (int t = 0; t < S_; t++) {
        const float* hbuf = g_hT[t & 1];
        float* hnext = g_hT[(t + 1) & 1];
        const float* YTt = g_YT + (size_t)t * (H3_ * B_);

        const float hpre1 = isR ? __ldcg(hbuf + jglob1 * 64 + bglob) : 0.f;

        {
            float hr[32];
#pragma unroll
            for (int kk = 0; kk < 32; kk++)
                hr[kk] = __ldcg(hbuf + (kw + kk) * 64 + bglob);
            ull acc2[8];
#pragma unroll
            for (int p = 0; p < 8; p++) acc2[p] = 0ull;
#pragma unroll
            for (int kk = 0; kk < 32; kk++) {
                const ull hh = pk2(hr[kk], hr[kk]);
                const float* urow = &sU1[(kw + kk) * 16];
                const ulonglong2 u01 = *(const ulonglong2*)(urow);
                const ulonglong2 u23 = *(const ulonglong2*)(urow + 4);
                const ulonglong2 u45 = *(const ulonglong2*)(urow + 8);
                const ulonglong2 u67 = *(const ulonglong2*)(urow + 12);
                acc2[0] = ffma2(hh, u01.x, acc2[0]);
                acc2[1] = ffma2(hh, u01.y, acc2[1]);
                acc2[2] = ffma2(hh, u23.x, acc2[2]);
                acc2[3] = ffma2(hh, u23.y, acc2[3]);
                acc2[4] = ffma2(hh, u45.x, acc2[4]);
                acc2[5] = ffma2(hh, u45.y, acc2[5]);
                acc2[6] = ffma2(hh, u67.x, acc2[6]);
                acc2[7] = ffma2(hh, u67.y, acc2[7]);
            }
            ull* dst = (ull*)&sP1[w * 576 + lane * 18];
#pragma unroll
            for (int p = 0; p < 8; p++) dst[p] = acc2[p];
        }
        __syncthreads();

        {
            float pre = 0.f;
#pragma unroll
            for (int q = 0; q < 16; q++) pre += sP1[q * 576 + (tid & 31) * 18 + rj1];
            const float gate = 1.f / (1.f + __expf(-(fmaf(yg, a1g, c1g) + pre)));
            if (isR) g_rhT[jglob1 * 64 + bglob] = gate * hpre1;
            else     g_zT[jglob1 * 64 + bglob] = gate;
        }
        arrive();

        float yh = 0.f, hp2 = 0.f;
        if (tid < 256) {
            yh  = __ldcg(YTt + yoff2);
            hp2 = __ldcg(hbuf + jglob2 * 64 + bglob);
        }
        wait(2u + 2u * (unsigned)t);

        float zv = 0.f;
        if (tid < 256) zv = __ldcg(g_zT + jglob2 * 64 + bglob);

        {
            float rr[32];
#pragma unroll
            for (int kk = 0; kk < 32; kk++)
                rr[kk] = __ldcg(g_rhT + (kw + kk) * 64 + bglob);
            ull acc2[4];
#pragma unroll
            for (int p = 0; p < 4; p++) acc2[p] = 0ull;
#pragma unroll
            for (int kk = 0; kk < 32; kk++) {
                const ull rv = pk2(rr[kk], rr[kk]);
                const float* urow = &sU2[(kw + kk) * 8];
                const ulonglong2 u01 = *(const ulonglong2*)(urow);
                const ulonglong2 u23 = *(const ulonglong2*)(urow + 4);
                acc2[0] = ffma2(rv, u01.x, acc2[0]);
                acc2[1] = ffma2(rv, u01.y, acc2[1]);
                acc2[2] = ffma2(rv, u23.x, acc2[2]);
                acc2[3] = ffma2(rv, u23.y, acc2[3]);
            }
            ull* dst = (ull*)&sP2[w * 320 + lane * 10];
#pragma unroll
            for (int p = 0; p < 4; p++) dst[p] = acc2[p];
        }
        __syncthreads();

        if (tid < 256) {
            float pre = 0.f;
#pragma unroll
            for (int q = 0; q < 16; q++) pre += sP2[q * 320 + (tid & 31) * 10 + rj2];
            const float hc = tanhf(fmaf(yh, a1h, c1h) + pre);
            const float hn = fmaf(zv, hp2 - hc, hc);
            hnext[jglob2 * 64 + bglob] = hn;
            sT[rj2 * 32 + (tid & 31)] = hn;
        }
        arrive();

        if (tid < 32) {
            const size_t row = (size_t)t * B_ + bh * 32 + tid;
            const float4 v0 = make_float4(sT[0 * 32 + tid], sT[1 * 32 + tid],
                                          sT[2 * 32 + tid], sT[3 * 32 + tid]);
            const float4 v1 = make_float4(sT[4 * 32 + tid], sT[5 * 32 + tid],
                                          sT[6 * 32 + tid], sT[7 * 32 + tid]);
            *(float4*)(g_Hst + row * H_ + jt2 * 8)     = v0;
            *(float4*)(g_Hst + row * H_ + jt2 * 8 + 4) = v1;
        }
        {
            const int tn = (t + 1 < S_) ? (t + 1) : t;
            yg = __ldcg(g_YT + (size_t)tn * (H3_ * B_) + yoff1);
        }
        wait(3u + 2u * (unsigned)t);
    }
}

// ---------------- row log_softmax, single global read, folded BN ----------------
__global__ __launch_bounds__(256) void logsoftmax_kernel(float* __restrict__ C) {
    const int row = blockIdx.x;
    float* p = C + (size_t)row * O_;
    __shared__ float red[256];
    const int t = threadIdx.x;
    float v[4];
    float mx = -3.4e38f;
#pragma unroll
    for (int i = 0; i < 4; i++) {
        const int j = t + i * 256;
        if (j < O_) {
            v[i] = p[j] * g_A2[j] + g_C2[j];
            mx = fmaxf(mx, v[i]);
        } else v[i] = -3.4e38f;
    }
    red[t] = mx; __syncthreads();
    for (int s = 128; s > 0; s >>= 1) { if (t < s) red[t] = fmaxf(red[t], red[t + s]); __syncthreads(); }
    mx = red[0]; __syncthreads();
    float sum = 0.f;
#pragma unroll
    for (int i = 0; i < 4; i++) {
        const int j = t + i * 256;
        if (j < O_) sum += expf(v[i] - mx);
    }
    red[t] = sum; __syncthreads();
    for (int s = 128; s > 0; s >>= 1) { if (t < s) red[t] += red[t + s]; __syncthreads(); }
    const float lse = mx + logf(red[0]);
#pragma unroll
    for (int i = 0; i < 4; i++) {
        const int j = t + i * 256;
        if (j < O_) p[j] = v[i] - lse;
    }
}

// ---------------- launch ----------------
extern "C" void kernel_launch(void* const* d_in, const int* in_sizes, int n_in,
                              void* d_out, int out_size) {
    const float* x  = (const float*)d_in[0];
    const float* Wh = (const float*)d_in[1];
    const float* Wz = (const float*)d_in[2];
    const float* Wr = (const float*)d_in[3];
    const float* Uh = (const float*)d_in[4];
    const float* Uz = (const float*)d_in[5];
    const float* Ur = (const float*)d_in[6];
    const float* gh = (const float*)d_in[7];
    const float* bh = (const float*)d_in[8];
    const float* gz = (const float*)d_in[9];
    const float* bz = (const float*)d_in[10];
    const float* gr = (const float*)d_in[11];
    const float* br = (const float*)d_in[12];
    const float* Wf = (const float*)d_in[13];
    const float* gf = (const float*)d_in[14];
    const float* bf = (const float*)d_in[15];
    float* out = (float*)d_out;

    float *pH, *p2s, *p2q, *pA2, *pC2;
    cudaGetSymbolAddress((void**)&pH,  g_Hst);
    cudaGetSymbolAddress((void**)&p2s, g_p2s);
    cudaGetSymbolAddress((void**)&p2q, g_p2q);
    cudaGetSymbolAddress((void**)&pA2, g_A2);
    cudaGetSymbolAddress((void**)&pC2, g_C2);
    __nv_bfloat16 *pxh, *pxl, *pgwh, *pgwl, *phh, *phl, *pfh, *pfl;
    cudaGetSymbolAddress((void**)&pxh,  g_xh);
    cudaGetSymbolAddress((void**)&pxl,  g_xl);
    cudaGetSymbolAddress((void**)&pgwh, g_gwh);
    cudaGetSymbolAddress((void**)&pgwl, g_gwl);
    cudaGetSymbolAddress((void**)&phh,  g_hh);
    cudaGetSymbolAddress((void**)&phl,  g_hl);
    cudaGetSymbolAddress((void**)&pfh,  g_fh);
    cudaGetSymbolAddress((void**)&pfl,  g_fl);

    cudaFuncSetAttribute(scan9b_kernel, cudaFuncAttributeMaxDynamicSharedMemorySize,
                         SMF_TOT * (int)sizeof(float));
    cudaFuncSetAttribute(gemm_mma, cudaFuncAttributeMaxDynamicSharedMemorySize, MMS_TOT);

    // 0) split inputs
    split_pad<<<(SB_ * 448) / 256, 256>>>(x, pxh, pxl, SB_, D_, 448);
    split_gw<<<(H3_ * 448) / 256, 256>>>(Wh, Wz, Wr);
    split_pad<<<(1024 * H_) / 256, 256>>>(Wf, pfh, pfl, O_, H_, H_);

    // 1) gate projections -> YT[t][col][b] (raw), tensor cores
    gemm_mma<<<dim3(H3_ / 128, SB_ / 128), 256, MMS_TOT>>>(
        pxh, pxl, pgwh, pgwl, (float*)0, 448 / 32, 448, 0, H3_, 1);

    // 2) BN stats over YT + fold coefficients
    colstat_yt<<<dim3(6, 50), 256>>>();
    fold1<<<6, 256>>>(gh, bh, gz, bz, gr, br);

    // 3) persistent recurrent scan
    scan9b_kernel<<<128, 512, SMF_TOT * sizeof(float)>>>(Uh, Uz, Ur);

    // 4) split H, final projection on tensor cores
    split_pad<<<(SB_ * H_) / 256, 256>>>(pH, phh, phl, SB_, H_, H_);
    gemm_mma<<<dim3(1024 / 128, SB_ / 128), 256, MMS_TOT>>>(
        phh, phl, pfh, pfl, out, H_ / 32, H_, O_, O_, 0);

    // 5) output BN stats
    colstat_stage1<<<dim3(4, 64), 256>>>(out, O_, p2s, p2q);
    colstat_stage2<<<4, 256>>>(p2s, p2q, O_, gf, bf, pA2, pC2);

    // 6) BN-apply + log_softmax in place
    logsoftmax_kernel<<<SB_, 256>>>(out);
}

// round 14
// speedup vs baseline: 2.1371x; 1.0558x over previous
#include <cuda_runtime.h>
#include <cuda_bf16.h>
#include <math.h>
#include <stdint.h>

#define S_   1000
#define B_   64
#define D_   440
#define H_   512
#define O_   1000
#define SB_  64000
#define H3_  1536

typedef unsigned long long ull;

// ---------------- f32x2 packed helpers (scan) ----------------
__device__ __forceinline__ ull pk2(float x, float y) {
    ull r; asm("mov.b64 %0, {%1,%2};" : "=l"(r) : "f"(x), "f"(y)); return r;
}
__device__ __forceinline__ ull ffma2(ull a, ull b, ull c) {
    ull d; asm("fma.rn.f32x2 %0, %1, %2, %3;" : "=l"(d) : "l"(a), "l"(b), "l"(c)); return d;
}

// ---------------- scratch ----------------
__device__ __align__(16) float g_YT[(size_t)S_ * H3_ * B_];  // [t][col][b], RAW
__device__ __align__(16) float g_hT[2][H_ * B_];
__device__ __align__(16) float g_rhT[H_ * B_];
__device__ __align__(16) float g_zT[H_ * B_];
__device__ float g_p1s[H3_ * 50], g_p1q[H3_ * 50];
__device__ float g_A1[H3_], g_C1[H3_];
__device__ float g_p2s[64 * O_], g_p2q[64 * O_];
__device__ float g_A2[O_], g_C2[O_];
__device__ __align__(128) unsigned g_cnt2[64];
// bf16 split arrays
__device__ __align__(16) __nv_bfloat16 g_xh[(size_t)SB_ * 448];
__device__ __align__(16) __nv_bfloat16 g_xl[(size_t)SB_ * 448];
__device__ __align__(16) __nv_bfloat16 g_gwh[H3_ * 448];
__device__ __align__(16) __nv_bfloat16 g_gwl[H3_ * 448];
__device__ __align__(16) __nv_bfloat16 g_hh[(size_t)SB_ * H_];   // written by scan
__device__ __align__(16) __nv_bfloat16 g_hl[(size_t)SB_ * H_];
__device__ __align__(16) __nv_bfloat16 g_fh[1024 * H_];
__device__ __align__(16) __nv_bfloat16 g_fl[1024 * H_];

// ---------------- split kernels ----------------
__global__ void split_pad(const float* __restrict__ src, __nv_bfloat16* __restrict__ dh,
                          __nv_bfloat16* __restrict__ dl, int Rreal, int C, int Cpad) {
    const size_t i = (size_t)blockIdx.x * 256 + threadIdx.x;
    const int r = (int)(i / Cpad), c = (int)(i % Cpad);
    float v = 0.f;
    if (r < Rreal && c < C) v = src[(size_t)r * C + c];
    const __nv_bfloat16 hi = __float2bfloat16(v);
    const __nv_bfloat16 lo = __float2bfloat16(v - __bfloat162float(hi));
    dh[i] = hi; dl[i] = lo;
}

__global__ void split_gw(const float* __restrict__ Wh, const float* __restrict__ Wz,
                         const float* __restrict__ Wr) {
    const size_t i = (size_t)blockIdx.x * 256 + threadIdx.x;   // < 1536*448
    const int r = (int)(i / 448), c = (int)(i % 448);
    float v = 0.f;
    if (c < D_) {
        v = (r < 512) ? Wh[r * D_ + c] : (r < 1024) ? Wz[(r - 512) * D_ + c]
                                                    : Wr[(r - 1024) * D_ + c];
    }
    const __nv_bfloat16 hi = __float2bfloat16(v);
    const __nv_bfloat16 lo = __float2bfloat16(v - __bfloat162float(hi));
    g_gwh[i] = hi; g_gwl[i] = lo;
}

// ---------------- mma.sync bf16 split GEMM with cp.async double buffering ----------------
__device__ __forceinline__ void mma16816(float* d, const uint32_t* a, const uint32_t* b) {
    asm volatile("mma.sync.aligned.m16n8k16.row.col.f32.bf16.bf16.f32 "
                 "{%0,%1,%2,%3}, {%4,%5,%6,%7}, {%8,%9}, {%0,%1,%2,%3};"
                 : "+f"(d[0]), "+f"(d[1]), "+f"(d[2]), "+f"(d[3])
                 : "r"(a[0]), "r"(a[1]), "r"(a[2]), "r"(a[3]), "r"(b[0]), "r"(b[1]));
}
__device__ __forceinline__ void cpa16(uint32_t dst, const void* src) {
    asm volatile("cp.async.cg.shared.global [%0], [%1], 16;" :: "r"(dst), "l"(src));
}
__device__ __forceinline__ uint32_t smem_u32g(const void* p) {
    uint32_t a;
    asm("{ .reg .u64 t; cvta.to.shared.u64 t, %1; cvt.u32.u64 %0, t; }" : "=r"(a) : "l"(p));
    return a;
}

// smem: 2 buffers x {Ah, Al, Bh, Bl}, each 128 rows x 40 bf16
#define MMS_ARR 5120                 // bf16 units per array
#define MMS_TOT (8 * MMS_ARR * 2)    // 81920 bytes

__global__ __launch_bounds__(256, 2) void gemm_mma(
    const __nv_bfloat16* __restrict__ Ah, const __nv_bfloat16* __restrict__ Al,
    const __nv_bfloat16* __restrict__ Bh, const __nv_bfloat16* __restrict__ Bl,
    float* __restrict__ C, int nk, int kstr, int ldc, int nreal, int toYT) {
    extern __shared__ __align__(16) unsigned short smu[];
    const int tid = threadIdx.x, w = tid >> 5, l = tid & 31;
    const int bm = blockIdx.y * 128, bn = blockIdx.x * 128;
    const int wm = (w & 1) * 64, wn = (w >> 1) * 32;
    const uint32_t sbase = smem_u32g(smu);

    float d[4][4][4];
#pragma unroll
    for (int mt = 0; mt < 4; mt++)
#pragma unroll
        for (int nt = 0; nt < 4; nt++)
#pragma unroll
            for (int q = 0; q < 4; q++) d[mt][nt][q] = 0.f;

    const int lrow0 = tid >> 2, lu0 = tid & 3;
    const int lrow1 = (tid + 256) >> 2;

    // issue cp.async for chunk ch into buffer bf
    auto issue = [&](int ch, int bf) {
        const int k0 = ch * 32;
        const uint32_t so = sbase + (uint32_t)(bf * 4 * MMS_ARR) * 2;
        // A hi/lo
        cpa16(so + (0 * MMS_ARR + lrow0 * 40 + lu0 * 8) * 2,
              Ah + (size_t)(bm + lrow0) * kstr + k0 + lu0 * 8);
        cpa16(so + (0 * MMS_ARR + lrow1 * 40 + lu0 * 8) * 2,
              Ah + (size_t)(bm + lrow1) * kstr + k0 + lu0 * 8);
        cpa16(so + (1 * MMS_ARR + lrow0 * 40 + lu0 * 8) * 2,
              Al + (size_t)(bm + lrow0) * kstr + k0 + lu0 * 8);
        cpa16(so + (1 * MMS_ARR + lrow1 * 40 + lu0 * 8) * 2,
              Al + (size_t)(bm + lrow1) * kstr + k0 + lu0 * 8);
        // B hi/lo
        cpa16(so + (2 * MMS_ARR + lrow0 * 40 + lu0 * 8) * 2,
              Bh + (size_t)(bn + lrow0) * kstr + k0 + lu0 * 8);
        cpa16(so + (2 * MMS_ARR + lrow1 * 40 + lu0 * 8) * 2,
              Bh + (size_t)(bn + lrow1) * kstr + k0 + lu0 * 8);
        cpa16(so + (3 * MMS_ARR + lrow0 * 40 + lu0 * 8) * 2,
              Bl + (size_t)(bn + lrow0) * kstr + k0 + lu0 * 8);
        cpa16(so + (3 * MMS_ARR + lrow1 * 40 + lu0 * 8) * 2,
              Bl + (size_t)(bn + lrow1) * kstr + k0 + lu0 * 8);
        asm volatile("cp.async.commit_group;" ::: "memory");
    };

    issue(0, 0);

    for (int ch = 0; ch < nk; ch++) {
        const int bf = ch & 1;
        if (ch + 1 < nk) {
            issue(ch + 1, bf ^ 1);
            asm volatile("cp.async.wait_group 1;" ::: "memory");
        } else {
            asm volatile("cp.async.wait_group 0;" ::: "memory");
        }
        __syncthreads();

        const unsigned short* pAH = smu + (bf * 4 + 0) * MMS_ARR;
        const unsigned short* pAL = smu + (bf * 4 + 1) * MMS_ARR;
        const unsigned short* pBH = smu + (bf * 4 + 2) * MMS_ARR;
        const unsigned short* pBL = smu + (bf * 4 + 3) * MMS_ARR;
#pragma unroll
        for (int half = 0; half < 2; half++) {
            const int c0 = half * 16 + (l & 3) * 2;
            uint32_t ah[4][4], al[4][4], bhf[4][2], blf[4][2];
#pragma unroll
            for (int mt = 0; mt < 4; mt++) {
                const int r = wm + mt * 16 + (l >> 2);
                ah[mt][0] = *(const uint32_t*)(pAH + r * 40 + c0);
                ah[mt][1] = *(const uint32_t*)(pAH + (r + 8) * 40 + c0);
                ah[mt][2] = *(const uint32_t*)(pAH + r * 40 + c0 + 8);
                ah[mt][3] = *(const uint32_t*)(pAH + (r + 8) * 40 + c0 + 8);
                al[mt][0] = *(const uint32_t*)(pAL + r * 40 + c0);
                al[mt][1] = *(const uint32_t*)(pAL + (r + 8) * 40 + c0);
                al[mt][2] = *(const uint32_t*)(pAL + r * 40 + c0 + 8);
                al[mt][3] = *(const uint32_t*)(pAL + (r + 8) * 40 + c0 + 8);
            }
#pragma unroll
            for (int nt = 0; nt < 4; nt++) {
                const int n = wn + nt * 8 + (l >> 2);
                bhf[nt][0] = *(const uint32_t*)(pBH + n * 40 + c0);
                bhf[nt][1] = *(const uint32_t*)(pBH + n * 40 + c0 + 8);
                blf[nt][0] = *(const uint32_t*)(pBL + n * 40 + c0);
                blf[nt][1] = *(const uint32_t*)(pBL + n * 40 + c0 + 8);
            }
#pragma unroll
            for (int mt = 0; mt < 4; mt++)
#pragma unroll
                for (int nt = 0; nt < 4; nt++) {
                    mma16816(d[mt][nt], ah[mt], bhf[nt]);
                    mma16816(d[mt][nt], ah[mt], blf[nt]);
                    mma16816(d[mt][nt], al[mt], bhf[nt]);
                }
        }
        __syncthreads();
    }

    // epilogue
    if (toYT) {
        const int ts = (bm >> 6) + (w & 1);
#pragma unroll
        for (int mt = 0; mt < 4; mt++) {
            const int b0 = mt * 16 + (l >> 2);
#pragma unroll
            for (int nt = 0; nt < 4; nt++) {
                const int col = bn + wn + nt * 8 + (l & 3) * 2;
                float* base = g_YT + ((size_t)ts * H3_ + col) * 64;
                base[b0]           = d[mt][nt][0];
                base[64 + b0]      = d[mt][nt][1];
                base[b0 + 8]       = d[mt][nt][2];
                base[64 + b0 + 8]  = d[mt][nt][3];
            }
        }
    } else {
#pragma unroll
        for (int mt = 0; mt < 4; mt++) {
            const int m = bm + wm + mt * 16 + (l >> 2);
#pragma unroll
            for (int nt = 0; nt < 4; nt++) {
                const int col = bn + wn + nt * 8 + (l & 3) * 2;
                if (col < nreal) {
                    *(float2*)(C + (size_t)m * ldc + col) =
                        make_float2(d[mt][nt][0], d[mt][nt][1]);
                    *(float2*)(C + (size_t)(m + 8) * ldc + col) =
                        make_float2(d[mt][nt][2], d[mt][nt][3]);
                }
            }
        }
    }
}

// ---------------- column stats over YT ----------------
__global__ void colstat_yt() {
    const int col = blockIdx.x * 256 + threadIdx.x;
    const int chunk = blockIdx.y;
    float s = 0.f, q = 0.f;
    for (int t = chunk * 20; t < chunk * 20 + 20; t++) {
        const float4* p4 = (const float4*)&g_YT[((size_t)t * H3_ + col) * B_];
#pragma unroll
        for (int b = 0; b < 16; b++) {
            const float4 v = p4[b];
            s += v.x + v.y + v.z + v.w;
            q = fmaf(v.x, v.x, q); q = fmaf(v.y, v.y, q);
            q = fmaf(v.z, v.z, q); q = fmaf(v.w, v.w, q);
        }
    }
    g_p1s[col * 50 + chunk] = s;
    g_p1q[col * 50 + chunk] = q;
}

__global__ void fold1(const float* __restrict__ gh, const float* __restrict__ bhp,
                      const float* __restrict__ gz, const float* __restrict__ bz,
                      const float* __restrict__ gr, const float* __restrict__ br) {
    const int col = blockIdx.x * 256 + threadIdx.x;
    float s = 0.f, q = 0.f;
    for (int c = 0; c < 50; c++) { s += g_p1s[col * 50 + c]; q += g_p1q[col * 50 + c]; }
    const float m = s * (1.f / 64000.f);
    const float v = q * (1.f / 64000.f) - m * m;
    float gamma, beta;
    if (col < 512)       { gamma = gh[col];        beta = bhp[col]; }
    else if (col < 1024) { gamma = gz[col - 512];  beta = bz[col - 512]; }
    else                 { gamma = gr[col - 1024]; beta = br[col - 1024]; }
    const float a = gamma * rsqrtf(v + 1e-5f);
    g_A1[col] = a;
    g_C1[col] = beta - m * a;
}

// ---------------- column stats (row-major, output BN) ----------------
__global__ void colstat_stage1(const float* __restrict__ X, int ncols,
                               float* __restrict__ ps, float* __restrict__ pq) {
    const int col = blockIdx.x * 256 + threadIdx.x;
    if (col >= ncols) return;
    const int chunk = blockIdx.y;
    const size_t base = (size_t)chunk * 1000 * ncols + col;
    float s = 0.f, q = 0.f;
    for (int r = 0; r < 1000; r++) {
        const float v = X[base + (size_t)r * ncols];
        s += v; q = fmaf(v, v, q);
    }
    ps[col * 64 + chunk] = s;
    pq[col * 64 + chunk] = q;
}

__global__ void colstat_stage2(const float* __restrict__ ps, const float* __restrict__ pq,
                               int ncols, const float* __restrict__ gamma,
                               const float* __restrict__ beta,
                               float* __restrict__ Aout, float* __restrict__ Cout) {
    const int col = blockIdx.x * 256 + threadIdx.x;
    if (col >= ncols) return;
    float s = 0.f, q = 0.f;
    for (int c = 0; c < 64; c++) { s += ps[col * 64 + c]; q += pq[col * 64 + c]; }
    const float m = s * (1.f / 64000.f);
    const float v = q * (1.f / 64000.f) - m * m;
    const float a = gamma[col] * rsqrtf(v + 1e-5f);
    Aout[col] = a;
    Cout[col] = beta[col] - m * a;
}

// ---------------- persistent scan v10: bf16 split-h epilogue ----------------
#define SMF_U1 0
#define SMF_U2 8192
#define SMF_P1 12288
#define SMF_P2 21504
#define SMF_T  26624
#define SMF_TOT 26880

__global__ __launch_bounds__(512, 1) void scan10_kernel(
    const float* __restrict__ Uh, const float* __restrict__ Uz,
    const float* __restrict__ Ur) {
    extern __shared__ float sm[];
    float* sU1 = sm + SMF_U1;
    float* sU2 = sm + SMF_U2;
    float* sP1 = sm + SMF_P1;
    float* sP2 = sm + SMF_P2;
    float* sT  = sm + SMF_T;
    __shared__ unsigned s_base;

    const int cta  = blockIdx.x;
    const int tid  = threadIdx.x;
    const int w    = tid >> 5;
    const int lane = tid & 31;
    const bool isR = cta >= 64;
    const int grp  = isR ? (cta - 64) : cta;
    const int jt1  = grp >> 1;
    const int bh   = cta & 1;
    const int jt2  = cta >> 1;
    const int bglob = bh * 32 + lane;

    unsigned* pc;
    asm("cvta.global.u64 %0, %1;" : "=l"(pc) : "l"(&g_cnt2[0]));
    pc += bh * 32;

    if (tid == 0) {
        unsigned b;
        asm volatile("ld.relaxed.gpu.global.u32 %0, [%1];" : "=r"(b) : "l"(pc));
        s_base = b;
    }

    {
        const float* U1 = isR ? Ur : Uz;
        for (int i = tid; i < 8192; i += 512) {
            const int k = i >> 4, jj = i & 15;
            sU1[i] = U1[(jt1 * 16 + jj) * H_ + k];
        }
        for (int i = tid; i < 4096; i += 512) {
            const int k = i >> 3, jj = i & 7;
            sU2[i] = Uh[(jt2 * 8 + jj) * H_ + k];
        }
    }
    if (tid < 256) g_hT[0][cta * 256 + tid] = 0.f;
    __syncthreads();
    const unsigned base = s_base;

    auto arrive = [&]() {
        __syncthreads();
        if (tid == 0)
            asm volatile("red.release.gpu.global.add.u32 [%0], 1;" :: "l"(pc) : "memory");
    };
    auto wait = [&](unsigned k) {
        if (tid == 0) {
            const unsigned tgt = 64u * k;
            unsigned v;
            do {
                asm volatile("ld.acquire.gpu.global.u32 %0, [%1];"
                             : "=r"(v) : "l"(pc) : "memory");
            } while ((v - base) < tgt);
        }
        __syncthreads();
    };

    const int rj1 = tid >> 5;
    const int jglob1 = jt1 * 16 + rj1;
    const int colg = (isR ? 1024 : 512) + jglob1;
    const size_t yoff1 = (size_t)colg * B_ + bglob;
    const int rj2 = (tid >> 5) & 7;
    const int jglob2 = jt2 * 8 + rj2;
    const size_t yoff2 = (size_t)jglob2 * B_ + bglob;
    const int kw = w * 32;

    const float a1g = g_A1[colg], c1g = g_C1[colg];
    float a1h = 0.f, c1h = 0.f;
    if (tid < 256) { a1h = g_A1[jglob2]; c1h = g_C1[jglob2]; }

    arrive(); wait(1u);

    float yg = __ldcg(g_YT + yoff1);

    for (int t = 0; t < S_; t++) {
        const float* hbuf = g_hT[t & 1];
        float* hnext = g_hT[(t + 1) & 1];
        const float* YTt = g_YT + (size_t)t * (H3_ * B_);

        const float hpre1 = isR ? __ldcg(hbuf + jglob1 * 64 + bglob) : 0.f;

        // ---- phase1 gemm ----
        {
            float hr[32];
#pragma unroll
            for (int kk = 0; kk < 32; kk++)
                hr[kk] = __ldcg(hbuf + (kw + kk) * 64 + bglob);
            ull acc2[8];
#pragma unroll
            for (int p = 0; p < 8; p++) acc2[p] = 0ull;
#pragma unroll
            for (int kk = 0; kk < 32; kk++) {
                const ull hh = pk2(hr[kk], hr[kk]);
                const float* urow = &sU1[(kw + kk) * 16];
                const ulonglong2 u01 = *(const ulonglong2*)(urow);
                const ulonglong2 u23 = *(const ulonglong2*)(urow + 4);
                const ulonglong2 u45 = *(const ulonglong2*)(urow + 8);
                const ulonglong2 u67 = *(const ulonglong2*)(urow + 12);
                acc2[0] = ffma2(hh, u01.x, acc2[0]);
                acc2[1] = ffma2(hh, u01.y, acc2[1]);
                acc2[2] = ffma2(hh, u23.x, acc2[2]);
                acc2[3] = ffma2(hh, u23.y, acc2[3]);
                acc2[4] = ffma2(hh, u45.x, acc2[4]);
                acc2[5] = ffma2(hh, u45.y, acc2[5]);
                acc2[6] = ffma2(hh, u67.x, acc2[6]);
                acc2[7] = ffma2(hh, u67.y, acc2[7]);
            }
            ull* dst = (ull*)&sP1[w * 576 + lane * 18];
#pragma unroll
            for (int p = 0; p < 8; p++) dst[p] = acc2[p];
        }
        __syncthreads();

        // ---- phase1 reduce + BN fold + activation ----
        {
            float pre = 0.f;
#pragma unroll
            for (int q = 0; q < 16; q++) pre += sP1[q * 576 + (tid & 31) * 18 + rj1];
            const float gate = 1.f / (1.f + __expf(-(fmaf(yg, a1g, c1g) + pre)));
            if (isR) g_rhT[jglob1 * 64 + bglob] = gate * hpre1;
            else     g_zT[jglob1 * 64 + bglob] = gate;
        }
        arrive();

        float yh = 0.f, hp2 = 0.f;
        if (tid < 256) {
            yh  = __ldcg(YTt + yoff2);
            hp2 = __ldcg(hbuf + jglob2 * 64 + bglob);
        }
        wait(2u + 2u * (unsigned)t);

        float zv = 0.f;
        if (tid < 256) zv = __ldcg(g_zT + jglob2 * 64 + bglob);

        // ---- phase2 gemm ----
        {
            float rr[32];
#pragma unroll
            for (int kk = 0; kk < 32; kk++)
                rr[kk] = __ldcg(g_rhT + (kw + kk) * 64 + bglob);
            ull acc2[4];
#pragma unroll
            for (int p = 0; p < 4; p++) acc2[p] = 0ull;
#pragma unroll
            for (int kk = 0; kk < 32; kk++) {
                const ull rv = pk2(rr[kk], rr[kk]);
                const float* urow = &sU2[(kw + kk) * 8];
                const ulonglong2 u01 = *(const ulonglong2*)(urow);
                const ulonglong2 u23 = *(const ulonglong2*)(urow + 4);
                acc2[0] = ffma2(rv, u01.x, acc2[0]);
                acc2[1] = ffma2(rv, u01.y, acc2[1]);
                acc2[2] = ffma2(rv, u23.x, acc2[2]);
                acc2[3] = ffma2(rv, u23.y, acc2[3]);
            }
            ull* dst = (ull*)&sP2[w * 320 + lane * 10];
#pragma unroll
            for (int p = 0; p < 4; p++) dst[p] = acc2[p];
        }
        __syncthreads();

        // ---- phase2 reduce + BN fold + h update ----
        if (tid < 256) {
            float pre = 0.f;
#pragma unroll
            for (int q = 0; q < 16; q++) pre += sP2[q * 320 + (tid & 31) * 10 + rj2];
            const float hc = tanhf(fmaf(yh, a1h, c1h) + pre);
            const float hn = fmaf(zv, hp2 - hc, hc);
            hnext[jglob2 * 64 + bglob] = hn;
            sT[rj2 * 32 + (tid & 31)] = hn;
        }
        arrive();

        // overlap with B2 wait: write bf16 split of h_t (row-major) + prefetch next yg
        if (tid < 32) {
            const size_t row = (size_t)t * B_ + bh * 32 + tid;
            uint4 hiv, lov;
            unsigned short* ph = (unsigned short*)&hiv;
            unsigned short* pl = (unsigned short*)&lov;
#pragma unroll
            for (int jj = 0; jj < 8; jj++) {
                const float v = sT[jj * 32 + tid];
                const __nv_bfloat16 hb = __float2bfloat16(v);
                const __nv_bfloat16 lb = __float2bfloat16(v - __bfloat162float(hb));
                ph[jj] = *(const unsigned short*)&hb;
                pl[jj] = *(const unsigned short*)&lb;
            }
            *(uint4*)((unsigned short*)g_hh + row * H_ + jt2 * 8) = hiv;
            *(uint4*)((unsigned short*)g_hl + row * H_ + jt2 * 8) = lov;
        }
        {
            const int tn = (t + 1 < S_) ? (t + 1) : t;
            yg = __ldcg(g_YT + (size_t)tn * (H3_ * B_) + yoff1);
        }
        wait(3u + 2u * (unsigned)t);
    }
}

// ---------------- row log_softmax, single global read, folded BN ----------------
__global__ __launch_bounds__(256) void logsoftmax_kernel(float* __restrict__ C) {
    const int row = blockIdx.x;
    float* p = C + (size_t)row * O_;
    __shared__ float red[256];
    const int t = threadIdx.x;
    float v[4];
    float mx = -3.4e38f;
#pragma unroll
    for (int i = 0; i < 4; i++) {
        const int j = t + i * 256;
        if (j < O_) {
            v[i] = p[j] * g_A2[j] + g_C2[j];
            mx = fmaxf(mx, v[i]);
        } else v[i] = -3.4e38f;
    }
    red[t] = mx; __syncthreads();
    for (int s = 128; s > 0; s >>= 1) { if (t < s) red[t] = fmaxf(red[t], red[t + s]); __syncthreads(); }
    mx = red[0]; __syncthreads();
    float sum = 0.f;
#pragma unroll
    for (int i = 0; i < 4; i++) {
        const int j = t + i * 256;
        if (j < O_) sum += expf(v[i] - mx);
    }
    red[t] = sum; __syncthreads();
    for (int s = 128; s > 0; s >>= 1) { if (t < s) red[t] += red[t + s]; __syncthreads(); }
    const float lse = mx + logf(red[0]);
#pragma unroll
    for (int i = 0; i < 4; i++) {
        const int j = t + i * 256;
        if (j < O_) p[j] = v[i] - lse;
    }
}

// ---------------- launch ----------------
extern "C" void kernel_launch(void* const* d_in, const int* in_sizes, int n_in,
                              void* d_out, int out_size) {
    const float* x  = (const float*)d_in[0];
    const float* Wh = (const float*)d_in[1];
    const float* Wz = (const float*)d_in[2];
    const float* Wr = (const float*)d_in[3];
    const float* Uh = (const float*)d_in[4];
    const float* Uz = (const float*)d_in[5];
    const float* Ur = (const float*)d_in[6];
    const float* gh = (const float*)d_in[7];
    const float* bh = (const float*)d_in[8];
    const float* gz = (const float*)d_in[9];
    const float* bz = (const float*)d_in[10];
    const float* gr = (const float*)d_in[11];
    const float* br = (const float*)d_in[12];
    const float* Wf = (const float*)d_in[13];
    const float* gf = (const float*)d_in[14];
    const float* bf = (const float*)d_in[15];
    float* out = (float*)d_out;

    float *p2s, *p2q, *pA2, *pC2;
    cudaGetSymbolAddress((void**)&p2s, g_p2s);
    cudaGetSymbolAddress((void**)&p2q, g_p2q);
    cudaGetSymbolAddress((void**)&pA2, g_A2);
    cudaGetSymbolAddress((void**)&pC2, g_C2);
    __nv_bfloat16 *pxh, *pxl, *pgwh, *pgwl, *phh, *phl, *pfh, *pfl;
    cudaGetSymbolAddress((void**)&pxh,  g_xh);
    cudaGetSymbolAddress((void**)&pxl,  g_xl);
    cudaGetSymbolAddress((void**)&pgwh, g_gwh);
    cudaGetSymbolAddress((void**)&pgwl, g_gwl);
    cudaGetSymbolAddress((void**)&phh,  g_hh);
    cudaGetSymbolAddress((void**)&phl,  g_hl);
    cudaGetSymbolAddress((void**)&pfh,  g_fh);
    cudaGetSymbolAddress((void**)&pfl,  g_fl);

    cudaFuncSetAttribute(scan10_kernel, cudaFuncAttributeMaxDynamicSharedMemorySize,
                         SMF_TOT * (int)sizeof(float));
    cudaFuncSetAttribute(gemm_mma, cudaFuncAttributeMaxDynamicSharedMemorySize, MMS_TOT);

    // 0) split inputs
    split_pad<<<(SB_ * 448) / 256, 256>>>(x, pxh, pxl, SB_, D_, 448);
    split_gw<<<(H3_ * 448) / 256, 256>>>(Wh, Wz, Wr);
    split_pad<<<(1024 * H_) / 256, 256>>>(Wf, pfh, pfl, O_, H_, H_);

    // 1) gate projections -> YT (tensor cores, cp.async pipeline)
    gemm_mma<<<dim3(H3_ / 128, SB_ / 128), 256, MMS_TOT>>>(
        pxh, pxl, pgwh, pgwl, (float*)0, 448 / 32, 448, 0, H3_, 1);

    // 2) BN stats over YT + fold coefficients
    colstat_yt<<<dim3(6, 50), 256>>>();
    fold1<<<6, 256>>>(gh, bh, gz, bz, gr, br);

    // 3) persistent recurrent scan (emits bf16 split h directly)
    scan10_kernel<<<128, 512, SMF_TOT * sizeof(float)>>>(Uh, Uz, Ur);

    // 4) final projection on tensor cores (uses scan-produced hh/hl)
    gemm_mma<<<dim3(1024 / 128, SB_ / 128), 256, MMS_TOT>>>(
        phh, phl, pfh, pfl, out, H_ / 32, H_, O_, O_, 0);

    // 5) output BN stats
    colstat_stage1<<<dim3(4, 64), 256>>>(out, O_, p2s, p2q);
    colstat_stage2<<<4, 256>>>(p2s, p2q, O_, gf, bf, pA2, pC2);

    // 6) BN-apply + log_softmax in place
    logsoftmax_kernel<<<SB_, 256>>>(out);
}

// round 15
// speedup vs baseline: 2.1655x; 1.0133x over previous
#include <cuda_runtime.h>
#include <cuda_bf16.h>
#include <math.h>
#include <stdint.h>

#define S_   1000
#define B_   64
#define D_   440
#define H_   512
#define O_   1000
#define SB_  64000
#define H3_  1536

typedef unsigned long long ull;

// ---------------- f32x2 packed helpers (scan) ----------------
__device__ __forceinline__ ull pk2(float x, float y) {
    ull r; asm("mov.b64 %0, {%1,%2};" : "=l"(r) : "f"(x), "f"(y)); return r;
}
__device__ __forceinline__ ull ffma2(ull a, ull b, ull c) {
    ull d; asm("fma.rn.f32x2 %0, %1, %2, %3;" : "=l"(d) : "l"(a), "l"(b), "l"(c)); return d;
}

// ---------------- scratch ----------------
__device__ __align__(16) float g_YT[(size_t)S_ * H3_ * B_];  // [t][col][b], RAW
__device__ __align__(16) float g_hT[2][H_ * B_];
__device__ __align__(16) float g_rhT[H_ * B_];
__device__ __align__(16) float g_zT[H_ * B_];
__device__ float g_p1s[H3_ * 50], g_p1q[H3_ * 50];
__device__ float g_A1[H3_], g_C1[H3_];
__device__ float g_p2s[64 * O_], g_p2q[64 * O_];
__device__ float g_A2[O_], g_C2[O_];
__device__ __align__(128) unsigned g_cnt2[64];
// bf16 split arrays
__device__ __align__(16) __nv_bfloat16 g_xh[(size_t)SB_ * 448];
__device__ __align__(16) __nv_bfloat16 g_xl[(size_t)SB_ * 448];
__device__ __align__(16) __nv_bfloat16 g_gwh[H3_ * 448];
__device__ __align__(16) __nv_bfloat16 g_gwl[H3_ * 448];
__device__ __align__(16) __nv_bfloat16 g_hh[(size_t)SB_ * H_];   // written by scan
__device__ __align__(16) __nv_bfloat16 g_hl[(size_t)SB_ * H_];
__device__ __align__(16) __nv_bfloat16 g_fh[1024 * H_];
__device__ __align__(16) __nv_bfloat16 g_fl[1024 * H_];

// ---------------- split kernels ----------------
__global__ void split_pad(const float* __restrict__ src, __nv_bfloat16* __restrict__ dh,
                          __nv_bfloat16* __restrict__ dl, int Rreal, int C, int Cpad) {
    const size_t i = (size_t)blockIdx.x * 256 + threadIdx.x;
    const int r = (int)(i / Cpad), c = (int)(i % Cpad);
    float v = 0.f;
    if (r < Rreal && c < C) v = src[(size_t)r * C + c];
    const __nv_bfloat16 hi = __float2bfloat16(v);
    const __nv_bfloat16 lo = __float2bfloat16(v - __bfloat162float(hi));
    dh[i] = hi; dl[i] = lo;
}

__global__ void split_gw(const float* __restrict__ Wh, const float* __restrict__ Wz,
                         const float* __restrict__ Wr) {
    const size_t i = (size_t)blockIdx.x * 256 + threadIdx.x;   // < 1536*448
    const int r = (int)(i / 448), c = (int)(i % 448);
    float v = 0.f;
    if (c < D_) {
        v = (r < 512) ? Wh[r * D_ + c] : (r < 1024) ? Wz[(r - 512) * D_ + c]
                                                    : Wr[(r - 1024) * D_ + c];
    }
    const __nv_bfloat16 hi = __float2bfloat16(v);
    const __nv_bfloat16 lo = __float2bfloat16(v - __bfloat162float(hi));
    g_gwh[i] = hi; g_gwl[i] = lo;
}

// ---------------- mma.sync bf16 split GEMM: cp.async + ldmatrix ----------------
__device__ __forceinline__ void mma16816(float* d, const uint32_t* a, const uint32_t* b) {
    asm volatile("mma.sync.aligned.m16n8k16.row.col.f32.bf16.bf16.f32 "
                 "{%0,%1,%2,%3}, {%4,%5,%6,%7}, {%8,%9}, {%0,%1,%2,%3};"
                 : "+f"(d[0]), "+f"(d[1]), "+f"(d[2]), "+f"(d[3])
                 : "r"(a[0]), "r"(a[1]), "r"(a[2]), "r"(a[3]), "r"(b[0]), "r"(b[1]));
}
__device__ __forceinline__ void cpa16(uint32_t dst, const void* src) {
    asm volatile("cp.async.cg.shared.global [%0], [%1], 16;" :: "r"(dst), "l"(src));
}
__device__ __forceinline__ void ldm4(uint32_t& r0, uint32_t& r1, uint32_t& r2, uint32_t& r3,
                                     uint32_t addr) {
    asm volatile("ldmatrix.sync.aligned.m8n8.x4.shared.b16 {%0,%1,%2,%3}, [%4];"
                 : "=r"(r0), "=r"(r1), "=r"(r2), "=r"(r3) : "r"(addr));
}
__device__ __forceinline__ uint32_t smem_u32g(const void* p) {
    uint32_t a;
    asm("{ .reg .u64 t; cvta.to.shared.u64 t, %1; cvt.u32.u64 %0, t; }" : "=r"(a) : "l"(p));
    return a;
}

// smem: 2 buffers x {Ah, Al, Bh, Bl}, each 128 rows x 40 bf16
#define MMS_ARR 5120                 // bf16 units per array
#define MMS_ARRB (MMS_ARR * 2)       // bytes = 10240
#define MMS_TOT (8 * MMS_ARR * 2)    // 81920 bytes

__global__ __launch_bounds__(256, 2) void gemm_mma(
    const __nv_bfloat16* __restrict__ Ah, const __nv_bfloat16* __restrict__ Al,
    const __nv_bfloat16* __restrict__ Bh, const __nv_bfloat16* __restrict__ Bl,
    float* __restrict__ C, int nk, int kstr, int ldc, int nreal, int toYT) {
    extern __shared__ __align__(16) unsigned short smu[];
    const int tid = threadIdx.x, w = tid >> 5, l = tid & 31;
    const int bm = blockIdx.y * 128, bn = blockIdx.x * 128;
    const int wm = (w & 1) * 64, wn = (w >> 1) * 32;
    const uint32_t sbase = smem_u32g(smu);

    float d[4][4][4];
#pragma unroll
    for (int mt = 0; mt < 4; mt++)
#pragma unroll
        for (int nt = 0; nt < 4; nt++)
#pragma unroll
            for (int q = 0; q < 4; q++) d[mt][nt][q] = 0.f;

    const int lrow0 = tid >> 2, lu0 = tid & 3;
    const int lrow1 = (tid + 256) >> 2;

    // ldmatrix lane-address components (bytes within one array)
    const int g8 = l >> 3, ri = l & 7;
    const uint32_t aoff = (uint32_t)(((wm + (g8 & 1) * 8 + ri) * 40 + (g8 >> 1) * 8) * 2);
    const uint32_t boff = (uint32_t)(((wn + (g8 >> 1) * 8 + ri) * 40 + (g8 & 1) * 8) * 2);

    auto issue = [&](int ch, int bf) {
        const int k0 = ch * 32;
        const uint32_t so = sbase + (uint32_t)(bf * 4) * MMS_ARRB;
        cpa16(so + (uint32_t)(0 * MMS_ARR + lrow0 * 40 + lu0 * 8) * 2,
              Ah + (size_t)(bm + lrow0) * kstr + k0 + lu0 * 8);
        cpa16(so + (uint32_t)(0 * MMS_ARR + lrow1 * 40 + lu0 * 8) * 2,
              Ah + (size_t)(bm + lrow1) * kstr + k0 + lu0 * 8);
        cpa16(so + (uint32_t)(1 * MMS_ARR + lrow0 * 40 + lu0 * 8) * 2,
              Al + (size_t)(bm + lrow0) * kstr + k0 + lu0 * 8);
        cpa16(so + (uint32_t)(1 * MMS_ARR + lrow1 * 40 + lu0 * 8) * 2,
              Al + (size_t)(bm + lrow1) * kstr + k0 + lu0 * 8);
        cpa16(so + (uint32_t)(2 * MMS_ARR + lrow0 * 40 + lu0 * 8) * 2,
              Bh + (size_t)(bn + lrow0) * kstr + k0 + lu0 * 8);
        cpa16(so + (uint32_t)(2 * MMS_ARR + lrow1 * 40 + lu0 * 8) * 2,
              Bh + (size_t)(bn + lrow1) * kstr + k0 + lu0 * 8);
        cpa16(so + (uint32_t)(3 * MMS_ARR + lrow0 * 40 + lu0 * 8) * 2,
              Bl + (size_t)(bn + lrow0) * kstr + k0 + lu0 * 8);
        cpa16(so + (uint32_t)(3 * MMS_ARR + lrow1 * 40 + lu0 * 8) * 2,
              Bl + (size_t)(bn + lrow1) * kstr + k0 + lu0 * 8);
        asm volatile("cp.async.commit_group;" ::: "memory");
    };

    issue(0, 0);

    for (int ch = 0; ch < nk; ch++) {
        const int bf = ch & 1;
        if (ch + 1 < nk) {
            issue(ch + 1, bf ^ 1);
            asm volatile("cp.async.wait_group 1;" ::: "memory");
        } else {
            asm volatile("cp.async.wait_group 0;" ::: "memory");
        }
        __syncthreads();

        const uint32_t bb = sbase + (uint32_t)(bf * 4) * MMS_ARRB;
#pragma unroll
        for (int half = 0; half < 2; half++) {
            const uint32_t kb2 = (uint32_t)(half * 32);      // 16 bf16 = 32 bytes
            uint32_t ah[4][4], al[4][4], bhf[4][2], blf[4][2];
#pragma unroll
            for (int mt = 0; mt < 4; mt++) {
                ldm4(ah[mt][0], ah[mt][1], ah[mt][2], ah[mt][3],
                     bb + 0 * MMS_ARRB + aoff + (uint32_t)(mt * 1280) + kb2);
                ldm4(al[mt][0], al[mt][1], al[mt][2], al[mt][3],
                     bb + 1 * MMS_ARRB + aoff + (uint32_t)(mt * 1280) + kb2);
            }
#pragma unroll
            for (int ntp = 0; ntp < 2; ntp++) {
                uint32_t r0, r1, r2, r3;
                ldm4(r0, r1, r2, r3,
                     bb + 2 * MMS_ARRB + boff + (uint32_t)(ntp * 1280) + kb2);
                bhf[2 * ntp][0] = r0; bhf[2 * ntp][1] = r1;
                bhf[2 * ntp + 1][0] = r2; bhf[2 * ntp + 1][1] = r3;
                ldm4(r0, r1, r2, r3,
                     bb + 3 * MMS_ARRB + boff + (uint32_t)(ntp * 1280) + kb2);
                blf[2 * ntp][0] = r0; blf[2 * ntp][1] = r1;
                blf[2 * ntp + 1][0] = r2; blf[2 * ntp + 1][1] = r3;
            }
#pragma unroll
            for (int mt = 0; mt < 4; mt++)
#pragma unroll
                for (int nt = 0; nt < 4; nt++) {
                    mma16816(d[mt][nt], ah[mt], bhf[nt]);
                    mma16816(d[mt][nt], ah[mt], blf[nt]);
                    mma16816(d[mt][nt], al[mt], bhf[nt]);
                }
        }
        __syncthreads();
    }

    // epilogue
    if (toYT) {
        const int ts = (bm >> 6) + (w & 1);
#pragma unroll
        for (int mt = 0; mt < 4; mt++) {
            const int b0 = mt * 16 + (l >> 2);
#pragma unroll
            for (int nt = 0; nt < 4; nt++) {
                const int col = bn + wn + nt * 8 + (l & 3) * 2;
                float* base = g_YT + ((size_t)ts * H3_ + col) * 64;
                base[b0]           = d[mt][nt][0];
                base[64 + b0]      = d[mt][nt][1];
                base[b0 + 8]       = d[mt][nt][2];
                base[64 + b0 + 8]  = d[mt][nt][3];
            }
        }
    } else {
#pragma unroll
        for (int mt = 0; mt < 4; mt++) {
            const int m = bm + wm + mt * 16 + (l >> 2);
#pragma unroll
            for (int nt = 0; nt < 4; nt++) {
                const int col = bn + wn + nt * 8 + (l & 3) * 2;
                if (col < nreal) {
                    *(float2*)(C + (size_t)m * ldc + col) =
                        make_float2(d[mt][nt][0], d[mt][nt][1]);
                    *(float2*)(C + (size_t)(m + 8) * ldc + col) =
                        make_float2(d[mt][nt][2], d[mt][nt][3]);
                }
            }
        }
    }
}

// ---------------- column stats over YT ----------------
__global__ void colstat_yt() {
    const int col = blockIdx.x * 256 + threadIdx.x;
    const int chunk = blockIdx.y;
    float s = 0.f, q = 0.f;
    for (int t = chunk * 20; t < chunk * 20 + 20; t++) {
        const float4* p4 = (const float4*)&g_YT[((size_t)t * H3_ + col) * B_];
#pragma unroll
        for (int b = 0; b < 16; b++) {
            const float4 v = p4[b];
            s += v.x + v.y + v.z + v.w;
            q = fmaf(v.x, v.x, q); q = fmaf(v.y, v.y, q);
            q = fmaf(v.z, v.z, q); q = fmaf(v.w, v.w, q);
        }
    }
    g_p1s[col * 50 + chunk] = s;
    g_p1q[col * 50 + chunk] = q;
}

__global__ void fold1(const float* __restrict__ gh, const float* __restrict__ bhp,
                      const float* __restrict__ gz, const float* __restrict__ bz,
                      const float* __restrict__ gr, const float* __restrict__ br) {
    const int col = blockIdx.x * 256 + threadIdx.x;
    float s = 0.f, q = 0.f;
    for (int c = 0; c < 50; c++) { s += g_p1s[col * 50 + c]; q += g_p1q[col * 50 + c]; }
    const float m = s * (1.f / 64000.f);
    const float v = q * (1.f / 64000.f) - m * m;
    float gamma, beta;
    if (col < 512)       { gamma = gh[col];        beta = bhp[col]; }
    else if (col < 1024) { gamma = gz[col - 512];  beta = bz[col - 512]; }
    else                 { gamma = gr[col - 1024]; beta = br[col - 1024]; }
    const float a = gamma * rsqrtf(v + 1e-5f);
    g_A1[col] = a;
    g_C1[col] = beta - m * a;
}

// ---------------- column stats (row-major, output BN) ----------------
__global__ void colstat_stage1(const float* __restrict__ X, int ncols,
                               float* __restrict__ ps, float* __restrict__ pq) {
    const int col = blockIdx.x * 256 + threadIdx.x;
    if (col >= ncols) return;
    const int chunk = blockIdx.y;
    const size_t base = (size_t)chunk * 1000 * ncols + col;
    float s = 0.f, q = 0.f;
    for (int r = 0; r < 1000; r++) {
        const float v = X[base + (size_t)r * ncols];
        s += v; q = fmaf(v, v, q);
    }
    ps[col * 64 + chunk] = s;
    pq[col * 64 + chunk] = q;
}

__global__ void colstat_stage2(const float* __restrict__ ps, const float* __restrict__ pq,
                               int ncols, const float* __restrict__ gamma,
                               const float* __restrict__ beta,
                               float* __restrict__ Aout, float* __restrict__ Cout) {
    const int col = blockIdx.x * 256 + threadIdx.x;
    if (col >= ncols) return;
    float s = 0.f, q = 0.f;
    for (int c = 0; c < 64; c++) { s += ps[col * 64 + c]; q += pq[col * 64 + c]; }
    const float m = s * (1.f / 64000.f);
    const float v = q * (1.f / 64000.f) - m * m;
    const float a = gamma[col] * rsqrtf(v + 1e-5f);
    Aout[col] = a;
    Cout[col] = beta[col] - m * a;
}

// ---------------- persistent scan v10 (identical to R14) ----------------
#define SMF_U1 0
#define SMF_U2 8192
#define SMF_P1 12288
#define SMF_P2 21504
#define SMF_T  26624
#define SMF_TOT 26880

__global__ __launch_bounds__(512, 1) void scan10_kernel(
    const float* __restrict__ Uh, const float* __restrict__ Uz,
    const float* __restrict__ Ur) {
    extern __shared__ float sm[];
    float* sU1 = sm + SMF_U1;
    float* sU2 = sm + SMF_U2;
    float* sP1 = sm + SMF_P1;
    float* sP2 = sm + SMF_P2;
    float* sT  = sm + SMF_T;
    __shared__ unsigned s_base;

    const int cta  = blockIdx.x;
    const int tid  = threadIdx.x;
    const int w    = tid >> 5;
    const int lane = tid & 31;
    const bool isR = cta >= 64;
    const int grp  = isR ? (cta - 64) : cta;
    const int jt1  = grp >> 1;
    const int bh   = cta & 1;
    const int jt2  = cta >> 1;
    const int bglob = bh * 32 + lane;

    unsigned* pc;
    asm("cvta.global.u64 %0, %1;" : "=l"(pc) : "l"(&g_cnt2[0]));
    pc += bh * 32;

    if (tid == 0) {
        unsigned b;
        asm volatile("ld.relaxed.gpu.global.u32 %0, [%1];" : "=r"(b) : "l"(pc));
        s_base = b;
    }

    {
        const float* U1 = isR ? Ur : Uz;
        for (int i = tid; i < 8192; i += 512) {
            const int k = i >> 4, jj = i & 15;
            sU1[i] = U1[(jt1 * 16 + jj) * H_ + k];
        }
        for (int i = tid; i < 4096; i += 512) {
            const int k = i >> 3, jj = i & 7;
            sU2[i] = Uh[(jt2 * 8 + jj) * H_ + k];
        }
    }
    if (tid < 256) g_hT[0][cta * 256 + tid] = 0.f;
    __syncthreads();
    const unsigned base = s_base;

    auto arrive = [&]() {
        __syncthreads();
        if (tid == 0)
            asm volatile("red.release.gpu.global.add.u32 [%0], 1;" :: "l"(pc) : "memory");
    };
    auto wait = [&](unsigned k) {
        if (tid == 0) {
            const unsigned tgt = 64u * k;
            unsigned v;
            do {
                asm volatile("ld.acquire.gpu.global.u32 %0, [%1];"
                             : "=r"(v) : "l"(pc) : "memory");
            } while ((v - base) < tgt);
        }
        __syncthreads();
    };

    const int rj1 = tid >> 5;
    const int jglob1 = jt1 * 16 + rj1;
    const int colg = (isR ? 1024 : 512) + jglob1;
    const size_t yoff1 = (size_t)colg * B_ + bglob;
    const int rj2 = (tid >> 5) & 7;
    const int jglob2 = jt2 * 8 + rj2;
    const size_t yoff2 = (size_t)jglob2 * B_ + bglob;
    const int kw = w * 32;

    const float a1g = g_A1[colg], c1g = g_C1[colg];
    float a1h = 0.f, c1h = 0.f;
    if (tid < 256) { a1h = g_A1[jglob2]; c1h = g_C1[jglob2]; }

    arrive(); wait(1u);

    float yg = __ldcg(g_YT + yoff1);

    for (int t = 0; t < S_; t++) {
        const float* hbuf = g_hT[t & 1];
        float* hnext = g_hT[(t + 1) & 1];
        const float* YTt = g_YT + (size_t)t * (H3_ * B_);

        const float hpre1 = isR ? __ldcg(hbuf + jglob1 * 64 + bglob) : 0.f;

        // ---- phase1 gemm ----
        {
            float hr[32];
#pragma unroll
            for (int kk = 0; kk < 32; kk++)
                hr[kk] = __ldcg(hbuf + (kw + kk) * 64 + bglob);
            ull acc2[8];
#pragma unroll
            for (int p = 0; p < 8; p++) acc2[p] = 0ull;
#pragma unroll
            for (int kk = 0; kk < 32; kk++) {
                const ull hh = pk2(hr[kk], hr[kk]);
                const float* urow = &sU1[(kw + kk) * 16];
                const ulonglong2 u01 = *(const ulonglong2*)(urow);
                const ulonglong2 u23 = *(const ulonglong2*)(urow + 4);
                const ulonglong2 u45 = *(const ulonglong2*)(urow + 8);
                const ulonglong2 u67 = *(const ulonglong2*)(urow + 12);
                acc2[0] = ffma2(hh, u01.x, acc2[0]);
                acc2[1] = ffma2(hh, u01.y, acc2[1]);
                acc2[2] = ffma2(hh, u23.x, acc2[2]);
                acc2[3] = ffma2(hh, u23.y, acc2[3]);
                acc2[4] = ffma2(hh, u45.x, acc2[4]);
                acc2[5] = ffma2(hh, u45.y, acc2[5]);
                acc2[6] = ffma2(hh, u67.x, acc2[6]);
                acc2[7] = ffma2(hh, u67.y, acc2[7]);
            }
            ull* dst = (ull*)&sP1[w * 576 + lane * 18];
#pragma unroll
            for (int p = 0; p < 8; p++) dst[p] = acc2[p];
        }
        __syncthreads();

        // ---- phase1 reduce + BN fold + activation ----
        {
            float pre = 0.f;
#pragma unroll
            for (int q = 0; q < 16; q++) pre += sP1[q * 576 + (tid & 31) * 18 + rj1];
            const float gate = 1.f / (1.f + __expf(-(fmaf(yg, a1g, c1g) + pre)));
            if (isR) g_rhT[jglob1 * 64 + bglob] = gate * hpre1;
            else     g_zT[jglob1 * 64 + bglob] = gate;
        }
        arrive();

        float yh = 0.f, hp2 = 0.f;
        if (tid < 256) {
            yh  = __ldcg(YTt + yoff2);
            hp2 = __ldcg(hbuf + jglob2 * 64 + bglob);
        }
        wait(2u + 2u * (unsigned)t);

        float zv = 0.f;
        if (tid < 256) zv = __ldcg(g_zT + jglob2 * 64 + bglob);

        // ---- phase2 gemm ----
        {
            float rr[32];
#pragma unroll
            for (int kk = 0; kk < 32; kk++)
                rr[kk] = __ldcg(g_rhT + (kw + kk) * 64 + bglob);
            ull acc2[4];
#pragma unroll
            for (int p = 0; p < 4; p++) acc2[p] = 0ull;
#pragma unroll
            for (int kk = 0; kk < 32; kk++) {
                const ull rv = pk2(rr[kk], rr[kk]);
                const float* urow = &sU2[(kw + kk) * 8];
                const ulonglong2 u01 = *(const ulonglong2*)(urow);
                const ulonglong2 u23 = *(const ulonglong2*)(urow + 4);
                acc2[0] = ffma2(rv, u01.x, acc2[0]);
                acc2[1] = ffma2(rv, u01.y, acc2[1]);
                acc2[2] = ffma2(rv, u23.x, acc2[2]);
                acc2[3] = ffma2(rv, u23.y, acc2[3]);
            }
            ull* dst = (ull*)&sP2[w * 320 + lane * 10];
#pragma unroll
            for (int p = 0; p < 4; p++) dst[p] = acc2[p];
        }
        __syncthreads();

        // ---- phase2 reduce + BN fold + h update ----
        if (tid < 256) {
            float pre = 0.f;
#pragma unroll
            for (int q = 0; q < 16; q++) pre += sP2[q * 320 + (tid & 31) * 10 + rj2];
            const float hc = tanhf(fmaf(yh, a1h, c1h) + pre);
            const float hn = fmaf(zv, hp2 - hc, hc);
            hnext[jglob2 * 64 + bglob] = hn;
            sT[rj2 * 32 + (tid & 31)] = hn;
        }
        arrive();

        // overlap with B2 wait: write bf16 split of h_t + prefetch next yg
        if (tid < 32) {
            const size_t row = (size_t)t * B_ + bh * 32 + tid;
            uint4 hiv, lov;
            unsigned short* ph = (unsigned short*)&hiv;
            unsigned short* pl = (unsigned short*)&lov;
#pragma unroll
            for (int jj = 0; jj < 8; jj++) {
                const float v = sT[jj * 32 + tid];
                const __nv_bfloat16 hb = __float2bfloat16(v);
                const __nv_bfloat16 lb = __float2bfloat16(v - __bfloat162float(hb));
                ph[jj] = *(const unsigned short*)&hb;
                pl[jj] = *(const unsigned short*)&lb;
            }
            *(uint4*)((unsigned short*)g_hh + row * H_ + jt2 * 8) = hiv;
            *(uint4*)((unsigned short*)g_hl + row * H_ + jt2 * 8) = lov;
        }
        {
            const int tn = (t + 1 < S_) ? (t + 1) : t;
            yg = __ldcg(g_YT + (size_t)tn * (H3_ * B_) + yoff1);
        }
        wait(3u + 2u * (unsigned)t);
    }
}

// ---------------- row log_softmax, single global read, folded BN ----------------
__global__ __launch_bounds__(256) void logsoftmax_kernel(float* __restrict__ C) {
    const int row = blockIdx.x;
    float* p = C + (size_t)row * O_;
    __shared__ float red[256];
    const int t = threadIdx.x;
    float v[4];
    float mx = -3.4e38f;
#pragma unroll
    for (int i = 0; i < 4; i++) {
        const int j = t + i * 256;
        if (j < O_) {
            v[i] = p[j] * g_A2[j] + g_C2[j];
            mx = fmaxf(mx, v[i]);
        } else v[i] = -3.4e38f;
    }
    red[t] = mx; __syncthreads();
    for (int s = 128; s > 0; s >>= 1) { if (t < s) red[t] = fmaxf(red[t], red[t + s]); __syncthreads(); }
    mx = red[0]; __syncthreads();
    float sum = 0.f;
#pragma unroll
    for (int i = 0; i < 4; i++) {
        const int j = t + i * 256;
        if (j < O_) sum += expf(v[i] - mx);
    }
    red[t] = sum; __syncthreads();
    for (int s = 128; s > 0; s >>= 1) { if (t < s) red[t] += red[t + s]; __syncthreads(); }
    const float lse = mx + logf(red[0]);
#pragma unroll
    for (int i = 0; i < 4; i++) {
        const int j = t + i * 256;
        if (j < O_) p[j] = v[i] - lse;
    }
}

// ---------------- launch ----------------
extern "C" void kernel_launch(void* const* d_in, const int* in_sizes, int n_in,
                              void* d_out, int out_size) {
    const float* x  = (const float*)d_in[0];
    const float* Wh = (const float*)d_in[1];
    const float* Wz = (const float*)d_in[2];
    const float* Wr = (const float*)d_in[3];
    const float* Uh = (const float*)d_in[4];
    const float* Uz = (const float*)d_in[5];
    const float* Ur = (const float*)d_in[6];
    const float* gh = (const float*)d_in[7];
    const float* bh = (const float*)d_in[8];
    const float* gz = (const float*)d_in[9];
    const float* bz = (const float*)d_in[10];
    const float* gr = (const float*)d_in[11];
    const float* br = (const float*)d_in[12];
    const float* Wf = (const float*)d_in[13];
    const float* gf = (const float*)d_in[14];
    const float* bf = (const float*)d_in[15];
    float* out = (float*)d_out;

    float *p2s, *p2q, *pA2, *pC2;
    cudaGetSymbolAddress((void**)&p2s, g_p2s);
    cudaGetSymbolAddress((void**)&p2q, g_p2q);
    cudaGetSymbolAddress((void**)&pA2, g_A2);
    cudaGetSymbolAddress((void**)&pC2, g_C2);
    __nv_bfloat16 *pxh, *pxl, *pgwh, *pgwl, *phh, *phl, *pfh, *pfl;
    cudaGetSymbolAddress((void**)&pxh,  g_xh);
    cudaGetSymbolAddress((void**)&pxl,  g_xl);
    cudaGetSymbolAddress((void**)&pgwh, g_gwh);
    cudaGetSymbolAddress((void**)&pgwl, g_gwl);
    cudaGetSymbolAddress((void**)&phh,  g_hh);
    cudaGetSymbolAddress((void**)&phl,  g_hl);
    cudaGetSymbolAddress((void**)&pfh,  g_fh);
    cudaGetSymbolAddress((void**)&pfl,  g_fl);

    cudaFuncSetAttribute(scan10_kernel, cudaFuncAttributeMaxDynamicSharedMemorySize,
                         SMF_TOT * (int)sizeof(float));
    cudaFuncSetAttribute(gemm_mma, cudaFuncAttributeMaxDynamicSharedMemorySize, MMS_TOT);

    // 0) split inputs
    split_pad<<<(SB_ * 448) / 256, 256>>>(x, pxh, pxl, SB_, D_, 448);
    split_gw<<<(H3_ * 448) / 256, 256>>>(Wh, Wz, Wr);
    split_pad<<<(1024 * H_) / 256, 256>>>(Wf, pfh, pfl, O_, H_, H_);

    // 1) gate projections -> YT (tensor cores, cp.async + ldmatrix)
    gemm_mma<<<dim3(H3_ / 128, SB_ / 128), 256, MMS_TOT>>>(
        pxh, pxl, pgwh, pgwl, (float*)0, 448 / 32, 448, 0, H3_, 1);

    // 2) BN stats over YT + fold coefficients
    colstat_yt<<<dim3(6, 50), 256>>>();
    fold1<<<6, 256>>>(gh, bh, gz, bz, gr, br);

    // 3) persistent recurrent scan (emits bf16 split h directly)
    scan10_kernel<<<128, 512, SMF_TOT * sizeof(float)>>>(Uh, Uz, Ur);

    // 4) final projection on tensor cores
    gemm_mma<<<dim3(1024 / 128, SB_ / 128), 256, MMS_TOT>>>(
        phh, phl, pfh, pfl, out, H_ / 32, H_, O_, O_, 0);

    // 5) output BN stats
    colstat_stage1<<<dim3(4, 64), 256>>>(out, O_, p2s, p2q);
    colstat_stage2<<<4, 256>>>(p2s, p2q, O_, gf, bf, pA2, pC2);

    // 6) BN-apply + log_softmax in place
    logsoftmax_kernel<<<SB_, 256>>>(out);
}

// round 16
// speedup vs baseline: 2.3689x; 1.0939x over previous
#include <cuda_runtime.h>
#include <cuda_bf16.h>
#include <math.h>
#include <stdint.h>

#define S_   1000
#define B_   64
#define D_   440
#define H_   512
#define O_   1000
#define SB_  64000
#define H3_  1536

typedef unsigned long long ull;

// ---------------- f32x2 packed helpers (scan) ----------------
__device__ __forceinline__ ull pk2(float x, float y) {
    ull r; asm("mov.b64 %0, {%1,%2};" : "=l"(r) : "f"(x), "f"(y)); return r;
}
__device__ __forceinline__ ull ffma2(ull a, ull b, ull c) {
    ull d; asm("fma.rn.f32x2 %0, %1, %2, %3;" : "=l"(d) : "l"(a), "l"(b), "l"(c)); return d;
}

// ---------------- scratch ----------------
__device__ __align__(16) float g_YT[(size_t)S_ * H3_ * B_];  // [t][col][b], RAW
__device__ __align__(16) float g_hT[2][H_ * B_];
__device__ __align__(16) float g_rhT[H_ * B_];
__device__ float g_p1s[H3_ * 50], g_p1q[H3_ * 50];
__device__ float g_A1[H3_], g_C1[H3_];
__device__ float g_p2s[64 * O_], g_p2q[64 * O_];
__device__ float g_A2[O_], g_C2[O_];
__device__ __align__(128) unsigned g_cnt2[64];
// bf16 split arrays
__device__ __align__(16) __nv_bfloat16 g_xh[(size_t)SB_ * 448];
__device__ __align__(16) __nv_bfloat16 g_xl[(size_t)SB_ * 448];
__device__ __align__(16) __nv_bfloat16 g_gwh[H3_ * 448];
__device__ __align__(16) __nv_bfloat16 g_gwl[H3_ * 448];
__device__ __align__(16) __nv_bfloat16 g_hh[(size_t)SB_ * H_];   // written by scan
__device__ __align__(16) __nv_bfloat16 g_hl[(size_t)SB_ * H_];
__device__ __align__(16) __nv_bfloat16 g_fh[1024 * H_];
__device__ __align__(16) __nv_bfloat16 g_fl[1024 * H_];

// ---------------- split kernels ----------------
__global__ void split_pad(const float* __restrict__ src, __nv_bfloat16* __restrict__ dh,
                          __nv_bfloat16* __restrict__ dl, int Rreal, int C, int Cpad) {
    const size_t i = (size_t)blockIdx.x * 256 + threadIdx.x;
    const int r = (int)(i / Cpad), c = (int)(i % Cpad);
    float v = 0.f;
    if (r < Rreal && c < C) v = src[(size_t)r * C + c];
    const __nv_bfloat16 hi = __float2bfloat16(v);
    const __nv_bfloat16 lo = __float2bfloat16(v - __bfloat162float(hi));
    dh[i] = hi; dl[i] = lo;
}

__global__ void split_gw(const float* __restrict__ Wh, const float* __restrict__ Wz,
                         const float* __restrict__ Wr) {
    const size_t i = (size_t)blockIdx.x * 256 + threadIdx.x;   // < 1536*448
    const int r = (int)(i / 448), c = (int)(i % 448);
    float v = 0.f;
    if (c < D_) {
        v = (r < 512) ? Wh[r * D_ + c] : (r < 1024) ? Wz[(r - 512) * D_ + c]
                                                    : Wr[(r - 1024) * D_ + c];
    }
    const __nv_bfloat16 hi = __float2bfloat16(v);
    const __nv_bfloat16 lo = __float2bfloat16(v - __bfloat162float(hi));
    g_gwh[i] = hi; g_gwl[i] = lo;
}

// ---------------- mma.sync bf16 split GEMM: cp.async + ldmatrix (identical to R15) --------
__device__ __forceinline__ void mma16816(float* d, const uint32_t* a, const uint32_t* b) {
    asm volatile("mma.sync.aligned.m16n8k16.row.col.f32.bf16.bf16.f32 "
                 "{%0,%1,%2,%3}, {%4,%5,%6,%7}, {%8,%9}, {%0,%1,%2,%3};"
                 : "+f"(d[0]), "+f"(d[1]), "+f"(d[2]), "+f"(d[3])
                 : "r"(a[0]), "r"(a[1]), "r"(a[2]), "r"(a[3]), "r"(b[0]), "r"(b[1]));
}
__device__ __forceinline__ void cpa16(uint32_t dst, const void* src) {
    asm volatile("cp.async.cg.shared.global [%0], [%1], 16;" :: "r"(dst), "l"(src));
}
__device__ __forceinline__ void ldm4(uint32_t& r0, uint32_t& r1, uint32_t& r2, uint32_t& r3,
                                     uint32_t addr) {
    asm volatile("ldmatrix.sync.aligned.m8n8.x4.shared.b16 {%0,%1,%2,%3}, [%4];"
                 : "=r"(r0), "=r"(r1), "=r"(r2), "=r"(r3) : "r"(addr));
}
__device__ __forceinline__ uint32_t smem_u32g(const void* p) {
    uint32_t a;
    asm("{ .reg .u64 t; cvta.to.shared.u64 t, %1; cvt.u32.u64 %0, t; }" : "=r"(a) : "l"(p));
    return a;
}

#define MMS_ARR 5120
#define MMS_ARRB (MMS_ARR * 2)
#define MMS_TOT (8 * MMS_ARR * 2)

__global__ __launch_bounds__(256, 2) void gemm_mma(
    const __nv_bfloat16* __restrict__ Ah, const __nv_bfloat16* __restrict__ Al,
    const __nv_bfloat16* __restrict__ Bh, const __nv_bfloat16* __restrict__ Bl,
    float* __restrict__ C, int nk, int kstr, int ldc, int nreal, int toYT) {
    extern __shared__ __align__(16) unsigned short smu[];
    const int tid = threadIdx.x, w = tid >> 5, l = tid & 31;
    const int bm = blockIdx.y * 128, bn = blockIdx.x * 128;
    const int wm = (w & 1) * 64, wn = (w >> 1) * 32;
    const uint32_t sbase = smem_u32g(smu);

    float d[4][4][4];
#pragma unroll
    for (int mt = 0; mt < 4; mt++)
#pragma unroll
        for (int nt = 0; nt < 4; nt++)
#pragma unroll
            for (int q = 0; q < 4; q++) d[mt][nt][q] = 0.f;

    const int lrow0 = tid >> 2, lu0 = tid & 3;
    const int lrow1 = (tid + 256) >> 2;

    const int g8 = l >> 3, ri = l & 7;
    const uint32_t aoff = (uint32_t)(((wm + (g8 & 1) * 8 + ri) * 40 + (g8 >> 1) * 8) * 2);
    const uint32_t boff = (uint32_t)(((wn + (g8 >> 1) * 8 + ri) * 40 + (g8 & 1) * 8) * 2);

    auto issue = [&](int ch, int bf) {
        const int k0 = ch * 32;
        const uint32_t so = sbase + (uint32_t)(bf * 4) * MMS_ARRB;
        cpa16(so + (uint32_t)(0 * MMS_ARR + lrow0 * 40 + lu0 * 8) * 2,
              Ah + (size_t)(bm + lrow0) * kstr + k0 + lu0 * 8);
        cpa16(so + (uint32_t)(0 * MMS_ARR + lrow1 * 40 + lu0 * 8) * 2,
              Ah + (size_t)(bm + lrow1) * kstr + k0 + lu0 * 8);
        cpa16(so + (uint32_t)(1 * MMS_ARR + lrow0 * 40 + lu0 * 8) * 2,
              Al + (size_t)(bm + lrow0) * kstr + k0 + lu0 * 8);
        cpa16(so + (uint32_t)(1 * MMS_ARR + lrow1 * 40 + lu0 * 8) * 2,
              Al + (size_t)(bm + lrow1) * kstr + k0 + lu0 * 8);
        cpa16(so + (uint32_t)(2 * MMS_ARR + lrow0 * 40 + lu0 * 8) * 2,
              Bh + (size_t)(bn + lrow0) * kstr + k0 + lu0 * 8);
        cpa16(so + (uint32_t)(2 * MMS_ARR + lrow1 * 40 + lu0 * 8) * 2,
              Bh + (size_t)(bn + lrow1) * kstr + k0 + lu0 * 8);
        cpa16(so + (uint32_t)(3 * MMS_ARR + lrow0 * 40 + lu0 * 8) * 2,
              Bl + (size_t)(bn + lrow0) * kstr + k0 + lu0 * 8);
        cpa16(so + (uint32_t)(3 * MMS_ARR + lrow1 * 40 + lu0 * 8) * 2,
              Bl + (size_t)(bn + lrow1) * kstr + k0 + lu0 * 8);
        asm volatile("cp.async.commit_group;" ::: "memory");
    };

    issue(0, 0);

    for (int ch = 0; ch < nk; ch++) {
        const int bf = ch & 1;
        if (ch + 1 < nk) {
            issue(ch + 1, bf ^ 1);
            asm volatile("cp.async.wait_group 1;" ::: "memory");
        } else {
            asm volatile("cp.async.wait_group 0;" ::: "memory");
        }
        __syncthreads();

        const uint32_t bb = sbase + (uint32_t)(bf * 4) * MMS_ARRB;
#pragma unroll
        for (int half = 0; half < 2; half++) {
            const uint32_t kb2 = (uint32_t)(half * 32);
            uint32_t ah[4][4], al[4][4], bhf[4][2], blf[4][2];
#pragma unroll
            for (int mt = 0; mt < 4; mt++) {
                ldm4(ah[mt][0], ah[mt][1], ah[mt][2], ah[mt][3],
                     bb + 0 * MMS_ARRB + aoff + (uint32_t)(mt * 1280) + kb2);
                ldm4(al[mt][0], al[mt][1], al[mt][2], al[mt][3],
                     bb + 1 * MMS_ARRB + aoff + (uint32_t)(mt * 1280) + kb2);
            }
#pragma unroll
            for (int ntp = 0; ntp < 2; ntp++) {
                uint32_t r0, r1, r2, r3;
                ldm4(r0, r1, r2, r3,
                     bb + 2 * MMS_ARRB + boff + (uint32_t)(ntp * 1280) + kb2);
                bhf[2 * ntp][0] = r0; bhf[2 * ntp][1] = r1;
                bhf[2 * ntp + 1][0] = r2; bhf[2 * ntp + 1][1] = r3;
                ldm4(r0, r1, r2, r3,
                     bb + 3 * MMS_ARRB + boff + (uint32_t)(ntp * 1280) + kb2);
                blf[2 * ntp][0] = r0; blf[2 * ntp][1] = r1;
                blf[2 * ntp + 1][0] = r2; blf[2 * ntp + 1][1] = r3;
            }
#pragma unroll
            for (int mt = 0; mt < 4; mt++)
#pragma unroll
                for (int nt = 0; nt < 4; nt++) {
                    mma16816(d[mt][nt], ah[mt], bhf[nt]);
                    mma16816(d[mt][nt], ah[mt], blf[nt]);
                    mma16816(d[mt][nt], al[mt], bhf[nt]);
                }
        }
        __syncthreads();
    }

    if (toYT) {
        const int ts = (bm >> 6) + (w & 1);
#pragma unroll
        for (int mt = 0; mt < 4; mt++) {
            const int b0 = mt * 16 + (l >> 2);
#pragma unroll
            for (int nt = 0; nt < 4; nt++) {
                const int col = bn + wn + nt * 8 + (l & 3) * 2;
                float* base = g_YT + ((size_t)ts * H3_ + col) * 64;
                base[b0]           = d[mt][nt][0];
                base[64 + b0]      = d[mt][nt][1];
                base[b0 + 8]       = d[mt][nt][2];
                base[64 + b0 + 8]  = d[mt][nt][3];
            }
        }
    } else {
#pragma unroll
        for (int mt = 0; mt < 4; mt++) {
            const int m = bm + wm + mt * 16 + (l >> 2);
#pragma unroll
            for (int nt = 0; nt < 4; nt++) {
                const int col = bn + wn + nt * 8 + (l & 3) * 2;
                if (col < nreal) {
                    *(float2*)(C + (size_t)m * ldc + col) =
                        make_float2(d[mt][nt][0], d[mt][nt][1]);
                    *(float2*)(C + (size_t)(m + 8) * ldc + col) =
                        make_float2(d[mt][nt][2], d[mt][nt][3]);
                }
            }
        }
    }
}

// ---------------- column stats over YT ----------------
__global__ void colstat_yt() {
    const int col = blockIdx.x * 256 + threadIdx.x;
    const int chunk = blockIdx.y;
    float s = 0.f, q = 0.f;
    for (int t = chunk * 20; t < chunk * 20 + 20; t++) {
        const float4* p4 = (const float4*)&g_YT[((size_t)t * H3_ + col) * B_];
#pragma unroll
        for (int b = 0; b < 16; b++) {
            const float4 v = p4[b];
            s += v.x + v.y + v.z + v.w;
            q = fmaf(v.x, v.x, q); q = fmaf(v.y, v.y, q);
            q = fmaf(v.z, v.z, q); q = fmaf(v.w, v.w, q);
        }
    }
    g_p1s[col * 50 + chunk] = s;
    g_p1q[col * 50 + chunk] = q;
}

__global__ void fold1(const float* __restrict__ gh, const float* __restrict__ bhp,
                      const float* __restrict__ gz, const float* __restrict__ bz,
                      const float* __restrict__ gr, const float* __restrict__ br) {
    const int col = blockIdx.x * 256 + threadIdx.x;
    float s = 0.f, q = 0.f;
    for (int c = 0; c < 50; c++) { s += g_p1s[col * 50 + c]; q += g_p1q[col * 50 + c]; }
    const float m = s * (1.f / 64000.f);
    const float v = q * (1.f / 64000.f) - m * m;
    float gamma, beta;
    if (col < 512)       { gamma = gh[col];        beta = bhp[col]; }
    else if (col < 1024) { gamma = gz[col - 512];  beta = bz[col - 512]; }
    else                 { gamma = gr[col - 1024]; beta = br[col - 1024]; }
    const float a = gamma * rsqrtf(v + 1e-5f);
    g_A1[col] = a;
    g_C1[col] = beta - m * a;
}

// ---------------- column stats (row-major, output BN) ----------------
__global__ void colstat_stage1(const float* __restrict__ X, int ncols,
                               float* __restrict__ ps, float* __restrict__ pq) {
    const int col = blockIdx.x * 256 + threadIdx.x;
    if (col >= ncols) return;
    const int chunk = blockIdx.y;
    const size_t base = (size_t)chunk * 1000 * ncols + col;
    float s = 0.f, q = 0.f;
    for (int r = 0; r < 1000; r++) {
        const float v = X[base + (size_t)r * ncols];
        s += v; q = fmaf(v, v, q);
    }
    ps[col * 64 + chunk] = s;
    pq[col * 64 + chunk] = q;
}

__global__ void colstat_stage2(const float* __restrict__ ps, const float* __restrict__ pq,
                               int ncols, const float* __restrict__ gamma,
                               const float* __restrict__ beta,
                               float* __restrict__ Aout, float* __restrict__ Cout) {
    const int col = blockIdx.x * 256 + threadIdx.x;
    if (col >= ncols) return;
    float s = 0.f, q = 0.f;
    for (int c = 0; c < 64; c++) { s += ps[col * 64 + c]; q += pq[col * 64 + c]; }
    const float m = s * (1.f / 64000.f);
    const float v = q * (1.f / 64000.f) - m * m;
    const float a = gamma[col] * rsqrtf(v + 1e-5f);
    Aout[col] = a;
    Cout[col] = beta[col] - m * a;
}

// ---------------- persistent scan v11: r-only phase1, z-gemm in barrier shadow ----------------
// 128 CTAs x 512 thr. bh = cta&1 (b-half), grp = cta>>1 (j-slice of 8: grp*8..+8).
// Phase1: r gemm (full K, warp k-split) -> rh. B1. z gemm (reuses hr regs) fills the wait.
// Phase2: hcand gemm over rh; reduce hcand + z; h update. B2.
#define SMF_U1 0                      // Ur slice [512k][8j]  = 4096
#define SMF_UZ 4096                   // Uz slice            = 4096
#define SMF_U2 8192                   // Uh slice            = 4096
#define SMF_P1 12288                  // [16w][32b][10] = 5120
#define SMF_PZ 17408                  // 5120
#define SMF_P2 22528                  // 5120
#define SMF_T  27648                  // [8j][32b] = 256
#define SMF_TOT 27904

__global__ __launch_bounds__(512, 1) void scan11_kernel(
    const float* __restrict__ Uh, const float* __restrict__ Uz,
    const float* __restrict__ Ur) {
    extern __shared__ float sm[];
    float* sU1 = sm + SMF_U1;
    float* sUz = sm + SMF_UZ;
    float* sU2 = sm + SMF_U2;
    float* sP1 = sm + SMF_P1;
    float* sPz = sm + SMF_PZ;
    float* sP2 = sm + SMF_P2;
    float* sT  = sm + SMF_T;
    __shared__ unsigned s_base;

    const int cta  = blockIdx.x;
    const int tid  = threadIdx.x;
    const int w    = tid >> 5;
    const int lane = tid & 31;
    const int bh   = cta & 1;
    const int grp  = cta >> 1;          // 0..63
    const int jbase = grp * 8;
    const int bglob = bh * 32 + lane;

    unsigned* pc;
    asm("cvta.global.u64 %0, %1;" : "=l"(pc) : "l"(&g_cnt2[0]));
    pc += bh * 32;

    if (tid == 0) {
        unsigned b;
        asm volatile("ld.relaxed.gpu.global.u32 %0, [%1];" : "=r"(b) : "l"(pc));
        s_base = b;
    }

    // stage U slices (persistent): [512k][8j] each
    for (int i = tid; i < 4096; i += 512) {
        const int k = i >> 3, jj = i & 7;
        sU1[i] = Ur[(jbase + jj) * H_ + k];
        sUz[i] = Uz[(jbase + jj) * H_ + k];
        sU2[i] = Uh[(jbase + jj) * H_ + k];
    }
    if (tid < 256) g_hT[0][cta * 256 + tid] = 0.f;
    __syncthreads();
    const unsigned base = s_base;

    auto arrive = [&]() {
        __syncthreads();
        if (tid == 0)
            asm volatile("red.release.gpu.global.add.u32 [%0], 1;" :: "l"(pc) : "memory");
    };
    auto wait = [&](unsigned k) {
        if (tid == 0) {
            const unsigned tgt = 64u * k;
            unsigned v;
            do {
                asm volatile("ld.acquire.gpu.global.u32 %0, [%1];"
                             : "=r"(v) : "l"(pc) : "memory");
            } while ((v - base) < tgt);
        }
        __syncthreads();
    };

    const int rj = tid >> 5;            // reduce j (tid<256: 0..7)
    const int jglob = jbase + (rj & 7);
    const size_t yoffR = (size_t)(1024 + jglob) * B_ + bglob;
    const size_t yoffH = (size_t)jglob * B_ + bglob;
    const size_t yoffZ = (size_t)(512 + jglob) * B_ + bglob;
    const int kw = w * 32;

    // per-thread BN fold coefficients (fixed columns; tid<256 lanes)
    float a1r = 0.f, c1r = 0.f, a1h = 0.f, c1h = 0.f, a1z = 0.f, c1z = 0.f;
    if (tid < 256) {
        a1r = g_A1[1024 + jglob]; c1r = g_C1[1024 + jglob];
        a1h = g_A1[jglob];        c1h = g_C1[jglob];
        a1z = g_A1[512 + jglob];  c1z = g_C1[512 + jglob];
    }

    arrive(); wait(1u);

    float ygr = (tid < 256) ? __ldcg(g_YT + yoffR) : 0.f;

    for (int t = 0; t < S_; t++) {
        const float* hbuf = g_hT[t & 1];
        float* hnext = g_hT[(t + 1) & 1];
        const float* YTt = g_YT + (size_t)t * (H3_ * B_);

        float hpre = 0.f;
        if (tid < 256) hpre = __ldcg(hbuf + jglob * 64 + bglob);

        // ---- phase1: r gemm (half the old phase1 work) ----
        float hr[32];
#pragma unroll
        for (int kk = 0; kk < 32; kk++)
            hr[kk] = __ldcg(hbuf + (kw + kk) * 64 + bglob);
        {
            ull acc2[4];
#pragma unroll
            for (int p = 0; p < 4; p++) acc2[p] = 0ull;
#pragma unroll
            for (int kk = 0; kk < 32; kk++) {
                const ull hh = pk2(hr[kk], hr[kk]);
                const float* urow = &sU1[(kw + kk) * 8];
                const ulonglong2 u01 = *(const ulonglong2*)(urow);
                const ulonglong2 u23 = *(const ulonglong2*)(urow + 4);
                acc2[0] = ffma2(hh, u01.x, acc2[0]);
                acc2[1] = ffma2(hh, u01.y, acc2[1]);
                acc2[2] = ffma2(hh, u23.x, acc2[2]);
                acc2[3] = ffma2(hh, u23.y, acc2[3]);
            }
            ull* dst = (ull*)&sP1[w * 320 + lane * 10];
#pragma unroll
            for (int p = 0; p < 4; p++) dst[p] = acc2[p];
        }
        __syncthreads();

        // ---- phase1 reduce: r -> rh ----
        if (tid < 256) {
            float pre = 0.f;
#pragma unroll
            for (int q = 0; q < 16; q++) pre += sP1[q * 320 + lane * 10 + rj];
            const float r = 1.f / (1.f + __expf(-(fmaf(ygr, a1r, c1r) + pre)));
            g_rhT[jglob * 64 + bglob] = r * hpre;
        }
        arrive();                                   // B1: rh published

        // ---- z gemm in the barrier shadow (reuses hr registers) ----
        {
            ull acc2[4];
#pragma unroll
            for (int p = 0; p < 4; p++) acc2[p] = 0ull;
#pragma unroll
            for (int kk = 0; kk < 32; kk++) {
                const ull hh = pk2(hr[kk], hr[kk]);
                const float* urow = &sUz[(kw + kk) * 8];
                const ulonglong2 u01 = *(const ulonglong2*)(urow);
                const ulonglong2 u23 = *(const ulonglong2*)(urow + 4);
                acc2[0] = ffma2(hh, u01.x, acc2[0]);
                acc2[1] = ffma2(hh, u01.y, acc2[1]);
                acc2[2] = ffma2(hh, u23.x, acc2[2]);
                acc2[3] = ffma2(hh, u23.y, acc2[3]);
            }
            ull* dst = (ull*)&sPz[w * 320 + lane * 10];
#pragma unroll
            for (int p = 0; p < 4; p++) dst[p] = acc2[p];
        }
        // prefetch phase2 YT operands (read-only)
        float yh = 0.f, yz = 0.f;
        if (tid < 256) {
            yh = __ldcg(YTt + yoffH);
            yz = __ldcg(YTt + yoffZ);
        }
        wait(2u + 2u * (unsigned)t);                // also orders sPz stores

        // ---- phase2: hcand gemm over rh ----
        {
            float rr[32];
#pragma unroll
            for (int kk = 0; kk < 32; kk++)
                rr[kk] = __ldcg(g_rhT + (kw + kk) * 64 + bglob);
            ull acc2[4];
#pragma unroll
            for (int p = 0; p < 4; p++) acc2[p] = 0ull;
#pragma unroll
            for (int kk = 0; kk < 32; kk++) {
                const ull rv = pk2(rr[kk], rr[kk]);
                const float* urow = &sU2[(kw + kk) * 8];
                const ulonglong2 u01 = *(const ulonglong2*)(urow);
                const ulonglong2 u23 = *(const ulonglong2*)(urow + 4);
                acc2[0] = ffma2(rv, u01.x, acc2[0]);
                acc2[1] = ffma2(rv, u01.y, acc2[1]);
                acc2[2] = ffma2(rv, u23.x, acc2[2]);
                acc2[3] = ffma2(rv, u23.y, acc2[3]);
            }
            ull* dst = (ull*)&sP2[w * 320 + lane * 10];
#pragma unroll
            for (int p = 0; p < 4; p++) dst[p] = acc2[p];
        }
        __syncthreads();

        // ---- phase2 reduce: hcand + z + h update ----
        if (tid < 256) {
            float hcpre = 0.f, zpre = 0.f;
#pragma unroll
            for (int q = 0; q < 16; q++) {
                hcpre += sP2[q * 320 + lane * 10 + rj];
                zpre  += sPz[q * 320 + lane * 10 + rj];
            }
            const float hc = tanhf(fmaf(yh, a1h, c1h) + hcpre);
            const float z  = 1.f / (1.f + __expf(-(fmaf(yz, a1z, c1z) + zpre)));
            const float hn = fmaf(z, hpre - hc, hc);
            hnext[jglob * 64 + bglob] = hn;
            sT[(rj & 7) * 32 + lane] = hn;
        }
        arrive();                                   // B2: hnext published

        // overlap with B2 wait: bf16 split store + next ygr prefetch
        if (tid < 32) {
            const size_t row = (size_t)t * B_ + bh * 32 + tid;
            uint4 hiv, lov;
            unsigned short* ph = (unsigned short*)&hiv;
            unsigned short* pl = (unsigned short*)&lov;
#pragma unroll
            for (int jj = 0; jj < 8; jj++) {
                const float v = sT[jj * 32 + tid];
                const __nv_bfloat16 hb = __float2bfloat16(v);
                const __nv_bfloat16 lb = __float2bfloat16(v - __bfloat162float(hb));
                ph[jj] = *(const unsigned short*)&hb;
                pl[jj] = *(const unsigned short*)&lb;
            }
            *(uint4*)((unsigned short*)g_hh + row * H_ + jbase) = hiv;
            *(uint4*)((unsigned short*)g_hl + row * H_ + jbase) = lov;
        }
        if (tid < 256) {
            const int tn = (t + 1 < S_) ? (t + 1) : t;
            ygr = __ldcg(g_YT + (size_t)tn * (H3_ * B_) + yoffR);
        }
        wait(3u + 2u * (unsigned)t);
    }
}

// ---------------- row log_softmax, single global read, folded BN ----------------
__global__ __launch_bounds__(256) void logsoftmax_kernel(float* __restrict__ C) {
    const int row = blockIdx.x;
    float* p = C + (size_t)row * O_;
    __shared__ float red[256];
    const int t = threadIdx.x;
    float v[4];
    float mx = -3.4e38f;
#pragma unroll
    for (int i = 0; i < 4; i++) {
        const int j = t + i * 256;
        if (j < O_) {
            v[i] = p[j] * g_A2[j] + g_C2[j];
            mx = fmaxf(mx, v[i]);
        } else v[i] = -3.4e38f;
    }
    red[t] = mx; __syncthreads();
    for (int s = 128; s > 0; s >>= 1) { if (t < s) red[t] = fmaxf(red[t], red[t + s]); __syncthreads(); }
    mx = red[0]; __syncthreads();
    float sum = 0.f;
#pragma unroll
    for (int i = 0; i < 4; i++) {
        const int j = t + i * 256;
        if (j < O_) sum += expf(v[i] - mx);
    }
    red[t] = sum; __syncthreads();
    for (int s = 128; s > 0; s >>= 1) { if (t < s) red[t] += red[t + s]; __syncthreads(); }
    const float lse = mx + logf(red[0]);
#pragma unroll
    for (int i = 0; i < 4; i++) {
        const int j = t + i * 256;
        if (j < O_) p[j] = v[i] - lse;
    }
}

// ---------------- launch ----------------
extern "C" void kernel_launch(void* const* d_in, const int* in_sizes, int n_in,
                              void* d_out, int out_size) {
    const float* x  = (const float*)d_in[0];
    const float* Wh = (const float*)d_in[1];
    const float* Wz = (const float*)d_in[2];
    const float* Wr = (const float*)d_in[3];
    const float* Uh = (const float*)d_in[4];
    const float* Uz = (const float*)d_in[5];
    const float* Ur = (const float*)d_in[6];
    const float* gh = (const float*)d_in[7];
    const float* bh = (const float*)d_in[8];
    const float* gz = (const float*)d_in[9];
    const float* bz = (const float*)d_in[10];
    const float* gr = (const float*)d_in[11];
    const float* br = (const float*)d_in[12];
    const float* Wf = (const float*)d_in[13];
    const float* gf = (const float*)d_in[14];
    const float* bf = (const float*)d_in[15];
    float* out = (float*)d_out;

    float *p2s, *p2q, *pA2, *pC2;
    cudaGetSymbolAddress((void**)&p2s, g_p2s);
    cudaGetSymbolAddress((void**)&p2q, g_p2q);
    cudaGetSymbolAddress((void**)&pA2, g_A2);
    cudaGetSymbolAddress((void**)&pC2, g_C2);
    __nv_bfloat16 *pxh, *pxl, *pgwh, *pgwl, *phh, *phl, *pfh, *pfl;
    cudaGetSymbolAddress((void**)&pxh,  g_xh);
    cudaGetSymbolAddress((void**)&pxl,  g_xl);
    cudaGetSymbolAddress((void**)&pgwh, g_gwh);
    cudaGetSymbolAddress((void**)&pgwl, g_gwl);
    cudaGetSymbolAddress((void**)&phh,  g_hh);
    cudaGetSymbolAddress((void**)&phl,  g_hl);
    cudaGetSymbolAddress((void**)&pfh,  g_fh);
    cudaGetSymbolAddress((void**)&pfl,  g_fl);

    cudaFuncSetAttribute(scan11_kernel, cudaFuncAttributeMaxDynamicSharedMemorySize,
                         SMF_TOT * (int)sizeof(float));
    cudaFuncSetAttribute(gemm_mma, cudaFuncAttributeMaxDynamicSharedMemorySize, MMS_TOT);

    // 0) split inputs
    split_pad<<<(SB_ * 448) / 256, 256>>>(x, pxh, pxl, SB_, D_, 448);
    split_gw<<<(H3_ * 448) / 256, 256>>>(Wh, Wz, Wr);
    split_pad<<<(1024 * H_) / 256, 256>>>(Wf, pfh, pfl, O_, H_, H_);

    // 1) gate projections -> YT
    gemm_mma<<<dim3(H3_ / 128, SB_ / 128), 256, MMS_TOT>>>(
        pxh, pxl, pgwh, pgwl, (float*)0, 448 / 32, 448, 0, H3_, 1);

    // 2) BN stats over YT + fold coefficients
    colstat_yt<<<dim3(6, 50), 256>>>();
    fold1<<<6, 256>>>(gh, bh, gz, bz, gr, br);

    // 3) persistent recurrent scan (r-only phase1, z in barrier shadow)
    scan11_kernel<<<128, 512, SMF_TOT * sizeof(float)>>>(Uh, Uz, Ur);

    // 4) final projection on tensor cores
    gemm_mma<<<dim3(1024 / 128, SB_ / 128), 256, MMS_TOT>>>(
        phh, phl, pfh, pfl, out, H_ / 32, H_, O_, O_, 0);

    // 5) output BN stats
    colstat_stage1<<<dim3(4, 64), 256>>>(out, O_, p2s, p2q);
    colstat_stage2<<<4, 256>>>(p2s, p2q, O_, gf, bf, pA2, pC2);

    // 6) BN-apply + log_softmax in place
    logsoftmax_kernel<<<SB_, 256>>>(out);
}

// round 17
// speedup vs baseline: 2.4573x; 1.0373x over previous
#include <cuda_runtime.h>
#include <cuda_bf16.h>
#include <math.h>
#include <stdint.h>

#define S_   1000
#define B_   64
#define D_   440
#define H_   512
#define O_   1000
#define SB_  64000
#define H3_  1536

typedef unsigned long long ull;

// ---------------- f32x2 packed helpers (scan) ----------------
__device__ __forceinline__ ull pk2(float x, float y) {
    ull r; asm("mov.b64 %0, {%1,%2};" : "=l"(r) : "f"(x), "f"(y)); return r;
}
__device__ __forceinline__ ull ffma2(ull a, ull b, ull c) {
    ull d; asm("fma.rn.f32x2 %0, %1, %2, %3;" : "=l"(d) : "l"(a), "l"(b), "l"(c)); return d;
}

// ---------------- scratch ----------------
__device__ __align__(16) float g_YT[(size_t)S_ * H3_ * B_];  // [t][col][b], RAW
__device__ __align__(16) float g_hT[2][H_ * B_];
__device__ __align__(16) float g_rhT[H_ * B_];
__device__ float g_p1s[H3_ * 50], g_p1q[H3_ * 50];
__device__ float g_A1[H3_], g_C1[H3_];
__device__ float g_p2s[64 * O_], g_p2q[64 * O_];
__device__ float g_A2[O_], g_C2[O_];
__device__ __align__(128) unsigned g_cnt2[64];
// bf16 split arrays
__device__ __align__(16) __nv_bfloat16 g_xh[(size_t)SB_ * 448];
__device__ __align__(16) __nv_bfloat16 g_xl[(size_t)SB_ * 448];
__device__ __align__(16) __nv_bfloat16 g_gwh[H3_ * 448];
__device__ __align__(16) __nv_bfloat16 g_gwl[H3_ * 448];
__device__ __align__(16) __nv_bfloat16 g_hh[(size_t)SB_ * H_];   // written by scan
__device__ __align__(16) __nv_bfloat16 g_hl[(size_t)SB_ * H_];
__device__ __align__(16) __nv_bfloat16 g_fh[1024 * H_];
__device__ __align__(16) __nv_bfloat16 g_fl[1024 * H_];

// ---------------- split kernels ----------------
__global__ void split_pad(const float* __restrict__ src, __nv_bfloat16* __restrict__ dh,
                          __nv_bfloat16* __restrict__ dl, int Rreal, int C, int Cpad) {
    const size_t i = (size_t)blockIdx.x * 256 + threadIdx.x;
    const int r = (int)(i / Cpad), c = (int)(i % Cpad);
    float v = 0.f;
    if (r < Rreal && c < C) v = src[(size_t)r * C + c];
    const __nv_bfloat16 hi = __float2bfloat16(v);
    const __nv_bfloat16 lo = __float2bfloat16(v - __bfloat162float(hi));
    dh[i] = hi; dl[i] = lo;
}

__global__ void split_gw(const float* __restrict__ Wh, const float* __restrict__ Wz,
                         const float* __restrict__ Wr) {
    const size_t i = (size_t)blockIdx.x * 256 + threadIdx.x;   // < 1536*448
    const int r = (int)(i / 448), c = (int)(i % 448);
    float v = 0.f;
    if (c < D_) {
        v = (r < 512) ? Wh[r * D_ + c] : (r < 1024) ? Wz[(r - 512) * D_ + c]
                                                    : Wr[(r - 1024) * D_ + c];
    }
    const __nv_bfloat16 hi = __float2bfloat16(v);
    const __nv_bfloat16 lo = __float2bfloat16(v - __bfloat162float(hi));
    g_gwh[i] = hi; g_gwl[i] = lo;
}

// ---------------- mma.sync bf16 split GEMM: cp.async + ldmatrix ----------------
__device__ __forceinline__ void mma16816(float* d, const uint32_t* a, const uint32_t* b) {
    asm volatile("mma.sync.aligned.m16n8k16.row.col.f32.bf16.bf16.f32 "
                 "{%0,%1,%2,%3}, {%4,%5,%6,%7}, {%8,%9}, {%0,%1,%2,%3};"
                 : "+f"(d[0]), "+f"(d[1]), "+f"(d[2]), "+f"(d[3])
                 : "r"(a[0]), "r"(a[1]), "r"(a[2]), "r"(a[3]), "r"(b[0]), "r"(b[1]));
}
__device__ __forceinline__ void cpa16(uint32_t dst, const void* src) {
    asm volatile("cp.async.cg.shared.global [%0], [%1], 16;" :: "r"(dst), "l"(src));
}
__device__ __forceinline__ void ldm4(uint32_t& r0, uint32_t& r1, uint32_t& r2, uint32_t& r3,
                                     uint32_t addr) {
    asm volatile("ldmatrix.sync.aligned.m8n8.x4.shared.b16 {%0,%1,%2,%3}, [%4];"
                 : "=r"(r0), "=r"(r1), "=r"(r2), "=r"(r3) : "r"(addr));
}
__device__ __forceinline__ uint32_t smem_u32g(const void* p) {
    uint32_t a;
    asm("{ .reg .u64 t; cvta.to.shared.u64 t, %1; cvt.u32.u64 %0, t; }" : "=r"(a) : "l"(p));
    return a;
}

#define MMS_ARR 5120
#define MMS_ARRB (MMS_ARR * 2)
#define MMS_TOT (8 * MMS_ARR * 2)

__global__ __launch_bounds__(256, 2) void gemm_mma(
    const __nv_bfloat16* __restrict__ Ah, const __nv_bfloat16* __restrict__ Al,
    const __nv_bfloat16* __restrict__ Bh, const __nv_bfloat16* __restrict__ Bl,
    float* __restrict__ C, int nk, int kstr, int ldc, int nreal, int toYT) {
    extern __shared__ __align__(16) unsigned short smu[];
    const int tid = threadIdx.x, w = tid >> 5, l = tid & 31;
    const int bm = blockIdx.y * 128, bn = blockIdx.x * 128;
    const int wm = (w & 1) * 64, wn = (w >> 1) * 32;
    const uint32_t sbase = smem_u32g(smu);

    float d[4][4][4];
#pragma unroll
    for (int mt = 0; mt < 4; mt++)
#pragma unroll
        for (int nt = 0; nt < 4; nt++)
#pragma unroll
            for (int q = 0; q < 4; q++) d[mt][nt][q] = 0.f;

    const int lrow0 = tid >> 2, lu0 = tid & 3;
    const int lrow1 = (tid + 256) >> 2;

    const int g8 = l >> 3, ri = l & 7;
    const uint32_t aoff = (uint32_t)(((wm + (g8 & 1) * 8 + ri) * 40 + (g8 >> 1) * 8) * 2);
    const uint32_t boff = (uint32_t)(((wn + (g8 >> 1) * 8 + ri) * 40 + (g8 & 1) * 8) * 2);

    auto issue = [&](int ch, int bf) {
        const int k0 = ch * 32;
        const uint32_t so = sbase + (uint32_t)(bf * 4) * MMS_ARRB;
        cpa16(so + (uint32_t)(0 * MMS_ARR + lrow0 * 40 + lu0 * 8) * 2,
              Ah + (size_t)(bm + lrow0) * kstr + k0 + lu0 * 8);
        cpa16(so + (uint32_t)(0 * MMS_ARR + lrow1 * 40 + lu0 * 8) * 2,
              Ah + (size_t)(bm + lrow1) * kstr + k0 + lu0 * 8);
        cpa16(so + (uint32_t)(1 * MMS_ARR + lrow0 * 40 + lu0 * 8) * 2,
              Al + (size_t)(bm + lrow0) * kstr + k0 + lu0 * 8);
        cpa16(so + (uint32_t)(1 * MMS_ARR + lrow1 * 40 + lu0 * 8) * 2,
              Al + (size_t)(bm + lrow1) * kstr + k0 + lu0 * 8);
        cpa16(so + (uint32_t)(2 * MMS_ARR + lrow0 * 40 + lu0 * 8) * 2,
              Bh + (size_t)(bn + lrow0) * kstr + k0 + lu0 * 8);
        cpa16(so + (uint32_t)(2 * MMS_ARR + lrow1 * 40 + lu0 * 8) * 2,
              Bh + (size_t)(bn + lrow1) * kstr + k0 + lu0 * 8);
        cpa16(so + (uint32_t)(3 * MMS_ARR + lrow0 * 40 + lu0 * 8) * 2,
              Bl + (size_t)(bn + lrow0) * kstr + k0 + lu0 * 8);
        cpa16(so + (uint32_t)(3 * MMS_ARR + lrow1 * 40 + lu0 * 8) * 2,
              Bl + (size_t)(bn + lrow1) * kstr + k0 + lu0 * 8);
        asm volatile("cp.async.commit_group;" ::: "memory");
    };

    issue(0, 0);

    for (int ch = 0; ch < nk; ch++) {
        const int bf = ch & 1;
        if (ch + 1 < nk) {
            issue(ch + 1, bf ^ 1);
            asm volatile("cp.async.wait_group 1;" ::: "memory");
        } else {
            asm volatile("cp.async.wait_group 0;" ::: "memory");
        }
        __syncthreads();

        const uint32_t bb = sbase + (uint32_t)(bf * 4) * MMS_ARRB;
#pragma unroll
        for (int half = 0; half < 2; half++) {
            const uint32_t kb2 = (uint32_t)(half * 32);
            uint32_t ah[4][4], al[4][4], bhf[4][2], blf[4][2];
#pragma unroll
            for (int mt = 0; mt < 4; mt++) {
                ldm4(ah[mt][0], ah[mt][1], ah[mt][2], ah[mt][3],
                     bb + 0 * MMS_ARRB + aoff + (uint32_t)(mt * 1280) + kb2);
                ldm4(al[mt][0], al[mt][1], al[mt][2], al[mt][3],
                     bb + 1 * MMS_ARRB + aoff + (uint32_t)(mt * 1280) + kb2);
            }
#pragma unroll
            for (int ntp = 0; ntp < 2; ntp++) {
                uint32_t r0, r1, r2, r3;
                ldm4(r0, r1, r2, r3,
                     bb + 2 * MMS_ARRB + boff + (uint32_t)(ntp * 1280) + kb2);
                bhf[2 * ntp][0] = r0; bhf[2 * ntp][1] = r1;
                bhf[2 * ntp + 1][0] = r2; bhf[2 * ntp + 1][1] = r3;
                ldm4(r0, r1, r2, r3,
                     bb + 3 * MMS_ARRB + boff + (uint32_t)(ntp * 1280) + kb2);
                blf[2 * ntp][0] = r0; blf[2 * ntp][1] = r1;
                blf[2 * ntp + 1][0] = r2; blf[2 * ntp + 1][1] = r3;
            }
#pragma unroll
            for (int mt = 0; mt < 4; mt++)
#pragma unroll
                for (int nt = 0; nt < 4; nt++) {
                    mma16816(d[mt][nt], ah[mt], bhf[nt]);
                    mma16816(d[mt][nt], ah[mt], blf[nt]);
                    mma16816(d[mt][nt], al[mt], bhf[nt]);
                }
        }
        __syncthreads();
    }

    if (toYT) {
        const int ts = (bm >> 6) + (w & 1);
#pragma unroll
        for (int mt = 0; mt < 4; mt++) {
            const int b0 = mt * 16 + (l >> 2);
#pragma unroll
            for (int nt = 0; nt < 4; nt++) {
                const int col = bn + wn + nt * 8 + (l & 3) * 2;
                float* base = g_YT + ((size_t)ts * H3_ + col) * 64;
                base[b0]           = d[mt][nt][0];
                base[64 + b0]      = d[mt][nt][1];
                base[b0 + 8]       = d[mt][nt][2];
                base[64 + b0 + 8]  = d[mt][nt][3];
            }
        }
    } else {
#pragma unroll
        for (int mt = 0; mt < 4; mt++) {
            const int m = bm + wm + mt * 16 + (l >> 2);
#pragma unroll
            for (int nt = 0; nt < 4; nt++) {
                const int col = bn + wn + nt * 8 + (l & 3) * 2;
                if (col < nreal) {
                    *(float2*)(C + (size_t)m * ldc + col) =
                        make_float2(d[mt][nt][0], d[mt][nt][1]);
                    *(float2*)(C + (size_t)(m + 8) * ldc + col) =
                        make_float2(d[mt][nt][2], d[mt][nt][3]);
                }
            }
        }
    }
}

// ---------------- column stats over YT ----------------
__global__ void colstat_yt() {
    const int col = blockIdx.x * 256 + threadIdx.x;
    const int chunk = blockIdx.y;
    float s = 0.f, q = 0.f;
    for (int t = chunk * 20; t < chunk * 20 + 20; t++) {
        const float4* p4 = (const float4*)&g_YT[((size_t)t * H3_ + col) * B_];
#pragma unroll
        for (int b = 0; b < 16; b++) {
            const float4 v = p4[b];
            s += v.x + v.y + v.z + v.w;
            q = fmaf(v.x, v.x, q); q = fmaf(v.y, v.y, q);
            q = fmaf(v.z, v.z, q); q = fmaf(v.w, v.w, q);
        }
    }
    g_p1s[col * 50 + chunk] = s;
    g_p1q[col * 50 + chunk] = q;
}

__global__ void fold1(const float* __restrict__ gh, const float* __restrict__ bhp,
                      const float* __restrict__ gz, const float* __restrict__ bz,
                      const float* __restrict__ gr, const float* __restrict__ br) {
    const int col = blockIdx.x * 256 + threadIdx.x;
    float s = 0.f, q = 0.f;
    for (int c = 0; c < 50; c++) { s += g_p1s[col * 50 + c]; q += g_p1q[col * 50 + c]; }
    const float m = s * (1.f / 64000.f);
    const float v = q * (1.f / 64000.f) - m * m;
    float gamma, beta;
    if (col < 512)       { gamma = gh[col];        beta = bhp[col]; }
    else if (col < 1024) { gamma = gz[col - 512];  beta = bz[col - 512]; }
    else                 { gamma = gr[col - 1024]; beta = br[col - 1024]; }
    const float a = gamma * rsqrtf(v + 1e-5f);
    g_A1[col] = a;
    g_C1[col] = beta - m * a;
}

// ---------------- column stats (row-major, output BN) ----------------
__global__ void colstat_stage1(const float* __restrict__ X, int ncols,
                               float* __restrict__ ps, float* __restrict__ pq) {
    const int col = blockIdx.x * 256 + threadIdx.x;
    if (col >= ncols) return;
    const int chunk = blockIdx.y;
    const size_t base = (size_t)chunk * 1000 * ncols + col;
    float s = 0.f, q = 0.f;
    for (int r = 0; r < 1000; r++) {
        const float v = X[base + (size_t)r * ncols];
        s += v; q = fmaf(v, v, q);
    }
    ps[col * 64 + chunk] = s;
    pq[col * 64 + chunk] = q;
}

__global__ void colstat_stage2(const float* __restrict__ ps, const float* __restrict__ pq,
                               int ncols, const float* __restrict__ gamma,
                               const float* __restrict__ beta,
                               float* __restrict__ Aout, float* __restrict__ Cout) {
    const int col = blockIdx.x * 256 + threadIdx.x;
    if (col >= ncols) return;
    float s = 0.f, q = 0.f;
    for (int c = 0; c < 64; c++) { s += ps[col * 64 + c]; q += pq[col * 64 + c]; }
    const float m = s * (1.f / 64000.f);
    const float v = q * (1.f / 64000.f) - m * m;
    const float a = gamma[col] * rsqrtf(v + 1e-5f);
    Aout[col] = a;
    Cout[col] = beta[col] - m * a;
}

// ---------------- persistent scan v12: dual-poll barrier + z reduce in shadow ----------------
#define SMF_U1 0                      // Ur slice [512k][8j]  = 4096
#define SMF_UZ 4096                   // Uz slice            = 4096
#define SMF_U2 8192                   // Uh slice            = 4096
#define SMF_P1 12288                  // [16w][32b][10] = 5120
#define SMF_PZ 17408                  // 5120
#define SMF_P2 22528                  // 5120
#define SMF_T  27648                  // [8j][32b] = 256
#define SMF_TOT 27904

__global__ __launch_bounds__(512, 1) void scan12_kernel(
    const float* __restrict__ Uh, const float* __restrict__ Uz,
    const float* __restrict__ Ur) {
    extern __shared__ float sm[];
    float* sU1 = sm + SMF_U1;
    float* sUz = sm + SMF_UZ;
    float* sU2 = sm + SMF_U2;
    float* sP1 = sm + SMF_P1;
    float* sPz = sm + SMF_PZ;
    float* sP2 = sm + SMF_P2;
    float* sT  = sm + SMF_T;
    __shared__ unsigned s_base;

    const int cta  = blockIdx.x;
    const int tid  = threadIdx.x;
    const int w    = tid >> 5;
    const int lane = tid & 31;
    const int bh   = cta & 1;
    const int grp  = cta >> 1;          // 0..63
    const int jbase = grp * 8;
    const int bglob = bh * 32 + lane;

    unsigned* pc;
    asm("cvta.global.u64 %0, %1;" : "=l"(pc) : "l"(&g_cnt2[0]));
    pc += bh * 32;

    if (tid == 0) {
        unsigned b;
        asm volatile("ld.relaxed.gpu.global.u32 %0, [%1];" : "=r"(b) : "l"(pc));
        s_base = b;
    }

    for (int i = tid; i < 4096; i += 512) {
        const int k = i >> 3, jj = i & 7;
        sU1[i] = Ur[(jbase + jj) * H_ + k];
        sUz[i] = Uz[(jbase + jj) * H_ + k];
        sU2[i] = Uh[(jbase + jj) * H_ + k];
    }
    if (tid < 256) g_hT[0][cta * 256 + tid] = 0.f;
    __syncthreads();
    const unsigned base = s_base;

    auto arrive = [&]() {
        __syncthreads();
        if (tid == 0)
            asm volatile("red.release.gpu.global.add.u32 [%0], 1;" :: "l"(pc) : "memory");
    };
    // dual-poller wait: two independent L2 streams halve detection latency
    auto wait = [&](unsigned k) {
        if (tid == 0 || tid == 256) {
            const unsigned tgt = 64u * k;
            unsigned v;
            do {
                asm volatile("ld.acquire.gpu.global.u32 %0, [%1];"
                             : "=r"(v) : "l"(pc) : "memory");
            } while ((v - base) < tgt);
        }
        __syncthreads();
    };

    const int rj = tid >> 5;
    const int jglob = jbase + (rj & 7);
    const size_t yoffR = (size_t)(1024 + jglob) * B_ + bglob;
    const size_t yoffH = (size_t)jglob * B_ + bglob;
    const size_t yoffZ = (size_t)(512 + jglob) * B_ + bglob;
    const int kw = w * 32;

    float a1r = 0.f, c1r = 0.f, a1h = 0.f, c1h = 0.f, a1z = 0.f, c1z = 0.f;
    if (tid < 256) {
        a1r = g_A1[1024 + jglob]; c1r = g_C1[1024 + jglob];
        a1h = g_A1[jglob];        c1h = g_C1[jglob];
        a1z = g_A1[512 + jglob];  c1z = g_C1[512 + jglob];
    }

    arrive(); wait(1u);

    float ygr = (tid < 256) ? __ldcg(g_YT + yoffR) : 0.f;

    for (int t = 0; t < S_; t++) {
        const float* hbuf = g_hT[t & 1];
        float* hnext = g_hT[(t + 1) & 1];
        const float* YTt = g_YT + (size_t)t * (H3_ * B_);

        float hpre = 0.f;
        if (tid < 256) hpre = __ldcg(hbuf + jglob * 64 + bglob);

        // ---- phase1: r gemm ----
        float hr[32];
#pragma unroll
        for (int kk = 0; kk < 32; kk++)
            hr[kk] = __ldcg(hbuf + (kw + kk) * 64 + bglob);
        {
            ull acc2[4];
#pragma unroll
            for (int p = 0; p < 4; p++) acc2[p] = 0ull;
#pragma unroll
            for (int kk = 0; kk < 32; kk++) {
                const ull hh = pk2(hr[kk], hr[kk]);
                const float* urow = &sU1[(kw + kk) * 8];
                const ulonglong2 u01 = *(const ulonglong2*)(urow);
                const ulonglong2 u23 = *(const ulonglong2*)(urow + 4);
                acc2[0] = ffma2(hh, u01.x, acc2[0]);
                acc2[1] = ffma2(hh, u01.y, acc2[1]);
                acc2[2] = ffma2(hh, u23.x, acc2[2]);
                acc2[3] = ffma2(hh, u23.y, acc2[3]);
            }
            ull* dst = (ull*)&sP1[w * 320 + lane * 10];
#pragma unroll
            for (int p = 0; p < 4; p++) dst[p] = acc2[p];
        }
        __syncthreads();

        // ---- phase1 reduce: r -> rh ----
        if (tid < 256) {
            float pre = 0.f;
#pragma unroll
            for (int q = 0; q < 16; q++) pre += sP1[q * 320 + lane * 10 + rj];
            const float r = 1.f / (1.f + __expf(-(fmaf(ygr, a1r, c1r) + pre)));
            g_rhT[jglob * 64 + bglob] = r * hpre;
        }
        arrive();                                   // B1: rh published

        // ---- B1 shadow: yh/yz prefetch, z gemm, z reduce ----
        float yh = 0.f, yz = 0.f;
        if (tid < 256) {
            yh = __ldcg(YTt + yoffH);
            yz = __ldcg(YTt + yoffZ);
        }
        {
            ull acc2[4];
#pragma unroll
            for (int p = 0; p < 4; p++) acc2[p] = 0ull;
#pragma unroll
            for (int kk = 0; kk < 32; kk++) {
                const ull hh = pk2(hr[kk], hr[kk]);
                const float* urow = &sUz[(kw + kk) * 8];
                const ulonglong2 u01 = *(const ulonglong2*)(urow);
                const ulonglong2 u23 = *(const ulonglong2*)(urow + 4);
                acc2[0] = ffma2(hh, u01.x, acc2[0]);
                acc2[1] = ffma2(hh, u01.y, acc2[1]);
                acc2[2] = ffma2(hh, u23.x, acc2[2]);
                acc2[3] = ffma2(hh, u23.y, acc2[3]);
            }
            ull* dst = (ull*)&sPz[w * 320 + lane * 10];
#pragma unroll
            for (int p = 0; p < 4; p++) dst[p] = acc2[p];
        }
        __syncthreads();
        float zpre = 0.f;
        if (tid < 256) {
#pragma unroll
            for (int q = 0; q < 16; q++) zpre += sPz[q * 320 + lane * 10 + rj];
        }
        wait(2u + 2u * (unsigned)t);

        // ---- phase2: hcand gemm over rh ----
        {
            float rr[32];
#pragma unroll
            for (int kk = 0; kk < 32; kk++)
                rr[kk] = __ldcg(g_rhT + (kw + kk) * 64 + bglob);
            ull acc2[4];
#pragma unroll
            for (int p = 0; p < 4; p++) acc2[p] = 0ull;
#pragma unroll
            for (int kk = 0; kk < 32; kk++) {
                const ull rv = pk2(rr[kk], rr[kk]);
                const float* urow = &sU2[(kw + kk) * 8];
                const ulonglong2 u01 = *(const ulonglong2*)(urow);
                const ulonglong2 u23 = *(const ulonglong2*)(urow + 4);
                acc2[0] = ffma2(rv, u01.x, acc2[0]);
                acc2[1] = ffma2(rv, u01.y, acc2[1]);
                acc2[2] = ffma2(rv, u23.x, acc2[2]);
                acc2[3] = ffma2(rv, u23.y, acc2[3]);
            }
            ull* dst = (ull*)&sP2[w * 320 + lane * 10];
#pragma unroll
            for (int p = 0; p < 4; p++) dst[p] = acc2[p];
        }
        __syncthreads();

        // ---- phase2 reduce: hcand + (pre-reduced) z + h update ----
        if (tid < 256) {
            float hcpre = 0.f;
#pragma unroll
            for (int q = 0; q < 16; q++) hcpre += sP2[q * 320 + lane * 10 + rj];
            const float hc = tanhf(fmaf(yh, a1h, c1h) + hcpre);
            const float z  = 1.f / (1.f + __expf(-(fmaf(yz, a1z, c1z) + zpre)));
            const float hn = fmaf(z, hpre - hc, hc);
            hnext[jglob * 64 + bglob] = hn;
            sT[(rj & 7) * 32 + lane] = hn;
        }
        arrive();                                   // B2: hnext published

        // B2 shadow: bf16 split store + next ygr prefetch
        if (tid < 32) {
            const size_t row = (size_t)t * B_ + bh * 32 + tid;
            uint4 hiv, lov;
            unsigned short* ph = (unsigned short*)&hiv;
            unsigned short* pl = (unsigned short*)&lov;
#pragma unroll
            for (int jj = 0; jj < 8; jj++) {
                const float v = sT[jj * 32 + tid];
                const __nv_bfloat16 hb = __float2bfloat16(v);
                const __nv_bfloat16 lb = __float2bfloat16(v - __bfloat162float(hb));
                ph[jj] = *(const unsigned short*)&hb;
                pl[jj] = *(const unsigned short*)&lb;
            }
            *(uint4*)((unsigned short*)g_hh + row * H_ + jbase) = hiv;
            *(uint4*)((unsigned short*)g_hl + row * H_ + jbase) = lov;
        }
        if (tid < 256) {
            const int tn = (t + 1 < S_) ? (t + 1) : t;
            ygr = __ldcg(g_YT + (size_t)tn * (H3_ * B_) + yoffR);
        }
        wait(3u + 2u * (unsigned)t);
    }
}

// ---------------- row log_softmax, single global read, folded BN ----------------
__global__ __launch_bounds__(256) void logsoftmax_kernel(float* __restrict__ C) {
    const int row = blockIdx.x;
    float* p = C + (size_t)row * O_;
    __shared__ float red[256];
    const int t = threadIdx.x;
    float v[4];
    float mx = -3.4e38f;
#pragma unroll
    for (int i = 0; i < 4; i++) {
        const int j = t + i * 256;
        if (j < O_) {
            v[i] = p[j] * g_A2[j] + g_C2[j];
            mx = fmaxf(mx, v[i]);
        } else v[i] = -3.4e38f;
    }
    red[t] = mx; __syncthreads();
    for (int s = 128; s > 0; s >>= 1) { if (t < s) red[t] = fmaxf(red[t], red[t + s]); __syncthreads(); }
    mx = red[0]; __syncthreads();
    float sum = 0.f;
#pragma unroll
    for (int i = 0; i < 4; i++) {
        const int j = t + i * 256;
        if (j < O_) sum += expf(v[i] - mx);
    }
    red[t] = sum; __syncthreads();
    for (int s = 128; s > 0; s >>= 1) { if (t < s) red[t] += red[t + s]; __syncthreads(); }
    const float lse = mx + logf(red[0]);
#pragma unroll
    for (int i = 0; i < 4; i++) {
        const int j = t + i * 256;
        if (j < O_) p[j] = v[i] - lse;
    }
}

// ---------------- launch ----------------
extern "C" void kernel_launch(void* const* d_in, const int* in_sizes, int n_in,
                              void* d_out, int out_size) {
    const float* x  = (const float*)d_in[0];
    const float* Wh = (const float*)d_in[1];
    const float* Wz = (const float*)d_in[2];
    const float* Wr = (const float*)d_in[3];
    const float* Uh = (const float*)d_in[4];
    const float* Uz = (const float*)d_in[5];
    const float* Ur = (const float*)d_in[6];
    const float* gh = (const float*)d_in[7];
    const float* bh = (const float*)d_in[8];
    const float* gz = (const float*)d_in[9];
    const float* bz = (const float*)d_in[10];
    const float* gr = (const float*)d_in[11];
    const float* br = (const float*)d_in[12];
    const float* Wf = (const float*)d_in[13];
    const float* gf = (const float*)d_in[14];
    const float* bf = (const float*)d_in[15];
    float* out = (float*)d_out;

    float *p2s, *p2q, *pA2, *pC2;
    cudaGetSymbolAddress((void**)&p2s, g_p2s);
    cudaGetSymbolAddress((void**)&p2q, g_p2q);
    cudaGetSymbolAddress((void**)&pA2, g_A2);
    cudaGetSymbolAddress((void**)&pC2, g_C2);
    __nv_bfloat16 *pxh, *pxl, *pgwh, *pgwl, *phh, *phl, *pfh, *pfl;
    cudaGetSymbolAddress((void**)&pxh,  g_xh);
    cudaGetSymbolAddress((void**)&pxl,  g_xl);
    cudaGetSymbolAddress((void**)&pgwh, g_gwh);
    cudaGetSymbolAddress((void**)&pgwl, g_gwl);
    cudaGetSymbolAddress((void**)&phh,  g_hh);
    cudaGetSymbolAddress((void**)&phl,  g_hl);
    cudaGetSymbolAddress((void**)&pfh,  g_fh);
    cudaGetSymbolAddress((void**)&pfl,  g_fl);

    cudaFuncSetAttribute(scan12_kernel, cudaFuncAttributeMaxDynamicSharedMemorySize,
                         SMF_TOT * (int)sizeof(float));
    cudaFuncSetAttribute(gemm_mma, cudaFuncAttributeMaxDynamicSharedMemorySize, MMS_TOT);

    // 0) split inputs
    split_pad<<<(SB_ * 448) / 256, 256>>>(x, pxh, pxl, SB_, D_, 448);
    split_gw<<<(H3_ * 448) / 256, 256>>>(Wh, Wz, Wr);
    split_pad<<<(1024 * H_) / 256, 256>>>(Wf, pfh, pfl, O_, H_, H_);

    // 1) gate projections -> YT
    gemm_mma<<<dim3(H3_ / 128, SB_ / 128), 256, MMS_TOT>>>(
        pxh, pxl, pgwh, pgwl, (float*)0, 448 / 32, 448, 0, H3_, 1);

    // 2) BN stats over YT + fold coefficients
    colstat_yt<<<dim3(6, 50), 256>>>();
    fold1<<<6, 256>>>(gh, bh, gz, bz, gr, br);

    // 3) persistent recurrent scan
    scan12_kernel<<<128, 512, SMF_TOT * sizeof(float)>>>(Uh, Uz, Ur);

    // 4) final projection on tensor cores
    gemm_mma<<<dim3(1024 / 128, SB_ / 128), 256, MMS_TOT>>>(
        phh, phl, pfh, pfl, out, H_ / 32, H_, O_, O_, 0);

    // 5) output BN stats
    colstat_stage1<<<dim3(4, 64), 256>>>(out, O_, p2s, p2q);
    colstat_stage2<<<4, 256>>>(p2s, p2q, O_, gf, bf, pA2, pC2);

    // 6) BN-apply + log_softmax in place
    logsoftmax_kernel<<<SB_, 256>>>(out);
}